// round 4
// baseline (speedup 1.0000x reference)
#include <cuda_runtime.h>
#include <math.h>
#include <stdint.h>

#define NT   4096      // trees
#define KC   16        // children
#define DM   256       // DOUT
#define GD   1024      // 4*DOUT
#define NCMB 5         // recurrent combos: (j0,f),(j0,b),(j1,f),(j2,f),(j3,f)

// ---------------- scratch (device globals; no allocations allowed) ----------
__device__ float s_xseq [(long)NT*KC*DM];
__device__ float s_cseq [(long)NT*KC*DM];
__device__ int   s_len  [NT];
__device__ float s_Wih5 [(long)NCMB*GD*DM];      // gate-interleaved packing
__device__ float s_Whh5 [(long)NCMB*GD*DM];      // gate-interleaved packing
__device__ float s_b5   [NCMB*GD];               // gate-interleaved packing
__device__ float s_WihB [3L*GD*DM];              // original order
__device__ float s_hb   [3*GD];
__device__ float s_Gx   [(long)NCMB*NT*KC*GD];   // gate-interleaved columns
__device__ float s_h    [2L*NCMB*NT*DM];         // double-buffered h state
__device__ float s_c    [(long)NCMB*NT*DM];
__device__ float s_gB   [3L*NT*GD];
__device__ float s_Wx   [(long)NT*GD];
__device__ float s_ycat0[(long)NT*KC*2*DM];
__device__ float s_ylcat[3L*NT*2*DM];
__device__ float s_xlast[(long)NT*DM];
__device__ float s_ys0  [(long)NT*KC*DM];
__device__ float s_ysl  [3L*NT*DM];

__device__ __forceinline__ float sigf(float x){ return 1.f/(1.f+expf(-x)); }

__device__ __forceinline__ uint32_t f2tf32(float f){
    uint32_t r; asm("cvt.rna.tf32.f32 %0, %1;" : "=r"(r) : "f"(f)); return r;
}

__device__ __forceinline__ void mma_tf32(float4& c,
        uint32_t a0, uint32_t a1, uint32_t a2, uint32_t a3,
        uint32_t b0, uint32_t b1){
    asm volatile(
        "mma.sync.aligned.m16n8k8.row.col.f32.tf32.tf32.f32 "
        "{%0,%1,%2,%3}, {%4,%5,%6,%7}, {%8,%9}, {%0,%1,%2,%3};"
        : "+f"(c.x), "+f"(c.y), "+f"(c.z), "+f"(c.w)
        : "r"(a0), "r"(a1), "r"(a2), "r"(a3), "r"(b0), "r"(b1));
}

// ---------------- prep: pack weights (gate-interleaved rows) ----------------
// packed row r' -> gate q=(r'>>5)&3, unit d=((r'>>7)<<5)|(r'&31); src r=q*256+d
__global__ void prep_weights(const float* __restrict__ Wih, const float* __restrict__ Whh,
                             const float* __restrict__ bih, const float* __restrict__ bhh){
    const int map5[5]={0,1,2,4,6};
    const int mapB[3]={3,5,7};
    long idx = (long)blockIdx.x*blockDim.x + threadIdx.x;
    long stride = (long)gridDim.x*blockDim.x;
    for (long i=idx; i<(long)NCMB*GD*DM; i+=stride){
        int cmb = (int)(i/((long)GD*DM)); long rem = i%((long)GD*DM);
        int rp = (int)(rem/DM); int kcol = (int)(rem%DM);
        int q = (rp>>5)&3; int d = ((rp>>7)<<5)|(rp&31);
        long src = (long)map5[cmb]*GD*DM + (long)(q*256+d)*DM + kcol;
        s_Wih5[i]=Wih[src];
        s_Whh5[i]=Whh[src];
    }
    for (long i=idx; i<3L*GD*DM; i+=stride){
        int jb = (int)(i/((long)GD*DM)); long r = i%((long)GD*DM);
        s_WihB[i]=Wih[(long)mapB[jb]*GD*DM + r];
    }
    for (long i=idx; i<(long)NCMB*GD; i+=stride){
        int cmb=(int)(i/GD); int rp=(int)(i%GD);
        int q=(rp>>5)&3; int d=((rp>>7)<<5)|(rp&31);
        int r = q*256+d;
        s_b5[i]=bih[map5[cmb]*GD+r]+bhh[map5[cmb]*GD+r];
    }
}

// ---------------- gather child states ---------------------------------------
__global__ void gather_k(const float* __restrict__ h_tensor,
                         const float* __restrict__ c_tensor,
                         const int*   __restrict__ indice){
    long i = (long)blockIdx.x*blockDim.x + threadIdx.x;
    if (i >= (long)NT*KC*(DM/4)) return;
    long nk = i / (DM/4);
    int  d4 = (int)(i % (DM/4));
    int id = indice[nk]; if (id < 0) id = 0;
    ((float4*)s_xseq)[i] = ((const float4*)h_tensor)[(long)id*(DM/4)+d4];
    ((float4*)s_cseq)[i] = ((const float4*)c_tensor)[(long)id*(DM/4)+d4];
}

// ---------------- lengths + initial states (h buffer 0) ----------------------
__global__ void meta_k(const int* __restrict__ indice,
                       const float* __restrict__ h0, const float* __restrict__ c0){
    long idx = (long)blockIdx.x*blockDim.x + threadIdx.x;
    long stride = (long)gridDim.x*blockDim.x;
    for (long n=idx; n<NT; n+=stride){
        int l=0;
        #pragma unroll
        for (int k=0;k<KC;k++) if (indice[n*KC+k] != -1) l++;
        s_len[n]=l;
    }
    const int jmap[5]={0,0,1,2,3};
    for (long i=idx; i<(long)NCMB*NT*DM; i+=stride){
        int cmb = (int)(i/((long)NT*DM)); int d = (int)(i%DM);
        s_h[i] = h0[jmap[cmb]*DM+d];
        s_c[i] = c0[jmap[cmb]*DM+d];
    }
}

__global__ void xlast_k(){
    long i = (long)blockIdx.x*blockDim.x + threadIdx.x;
    if (i >= (long)NT*(DM/4)) return;
    int n = (int)(i/(DM/4)); int d4 = (int)(i%(DM/4));
    int last = s_len[n]-1;
    ((float4*)s_xlast)[i] = ((const float4*)s_xseq)[((long)n*KC+last)*(DM/4)+d4];
}

__global__ void hb_k(const float* __restrict__ h0, const float* __restrict__ Whh,
                     const float* __restrict__ bih, const float* __restrict__ bhh){
    int idx = blockIdx.x*blockDim.x + threadIdx.x;
    if (idx >= 3*GD) return;
    int jb = idx/GD, o = idx%GD;
    int jd2 = 2*(jb+1)+1;
    const float* w = Whh + (long)jd2*GD*DM + (long)o*DM;
    const float* h = h0 + (jb+1)*DM;
    float acc=0.f;
    #pragma unroll 8
    for (int d=0; d<DM; d++) acc += h[d]*w[d];
    s_hb[idx] = acc + bih[jd2*GD+o] + bhh[jd2*GD+o];
}

// ---------------- tf32 mma.sync batched GEMM: C = A @ B^T (+bias)(+Cadd) ----
// A:[M,K] rm, B:[N,K] rm, M%128==0, N%128==0, K%32==0.
// 256 thr = 8 warps in 2x4; warp tile 64x32 via m16n8k8 (4 mtiles x 4 ntiles).
// K chunks of 32; fp32->tf32 on smem store; double buffer + reg prefetch +
// 2-deep fragment pipeline across k-substeps.
// fuseStep >= 0: LSTM-gate fused epilogue (weights gate-interleaved); writes
// state to hOut / s_c and scatters ycat0/ylcat. No C write.
#define STR 36      // smem row stride in u32 (conflict-free frags, 16B-aligned)
#define ABUF(b) ((b)*128*STR)
#define BBUF(b) (2*128*STR + (b)*128*STR)

__global__ void __launch_bounds__(256) gemm_mma(
    const float* __restrict__ A, long aBatch,
    const float* __restrict__ B, long bBatch,
    const float* __restrict__ bias, long biasBatch,
    const float* __restrict__ Cadd, long caddBatch, int caddRow,
    float* __restrict__ C, long cBatch, int cRow,
    int M, int N, int K, int xorZ, int xorVal,
    int fuseStep, float* __restrict__ hOut)
{
    extern __shared__ uint32_t sm[];
    int tid = threadIdx.x;
    int wid = tid >> 5;
    int lane = tid & 31;
    int g = lane >> 2;          // group id 0..7
    int t = lane & 3;           // thread-in-group 0..3
    int wr = wid >> 2;          // warp row 0..1 (64 rows)
    int wc = wid & 3;           // warp col 0..3 (32 cols)

    int z = blockIdx.z;
    const float* Ab = A + (long)z*aBatch;
    const float* Bb = B + (long)z*bBatch;
    int rxor = (z==xorZ) ? xorVal : 0;
    long brow = (long)blockIdx.y * 128;
    long bcol = (long)blockIdx.x * 128;

    int ldr = tid >> 3;         // 0..31 : row group (x4 per 128 rows)
    int ldc = tid & 7;          // float4 column within 32-float chunk

    float4 pa[4], pb[4];
    #define GLOAD(ch) do {                                                        \
        long kb = (long)(ch)*32;                                                  \
        _Pragma("unroll")                                                         \
        for (int l=0;l<4;l++){                                                    \
            long gr = (brow + ldr + l*32) ^ rxor;                                 \
            pa[l] = *reinterpret_cast<const float4*>(&Ab[gr*K + kb + ldc*4]);     \
            pb[l] = *reinterpret_cast<const float4*>(&Bb[(bcol + ldr + l*32)*K + kb + ldc*4]); \
        }                                                                         \
    } while(0)

    #define SSTORE(buf) do {                                                      \
        _Pragma("unroll")                                                         \
        for (int l=0;l<4;l++){                                                    \
            int r = ldr + l*32;                                                   \
            uint32_t* da = &sm[ABUF(buf) + r*STR + ldc*4];                        \
            da[0]=f2tf32(pa[l].x); da[1]=f2tf32(pa[l].y);                         \
            da[2]=f2tf32(pa[l].z); da[3]=f2tf32(pa[l].w);                         \
            uint32_t* db = &sm[BBUF(buf) + r*STR + ldc*4];                        \
            db[0]=f2tf32(pb[l].x); db[1]=f2tf32(pb[l].y);                         \
            db[2]=f2tf32(pb[l].z); db[3]=f2tf32(pb[l].w);                         \
        }                                                                         \
    } while(0)

    #define LOADFRAG(sA, sB, ks, dst) do {                                        \
        int _k0 = (ks)*8;                                                         \
        _Pragma("unroll")                                                         \
        for (int mt=0; mt<4; mt++){                                               \
            int ar = wr*64 + mt*16 + g;                                           \
            af[dst][mt][0] = (sA)[ar*STR + _k0 + t];                              \
            af[dst][mt][1] = (sA)[(ar+8)*STR + _k0 + t];                          \
            af[dst][mt][2] = (sA)[ar*STR + _k0 + t + 4];                          \
            af[dst][mt][3] = (sA)[(ar+8)*STR + _k0 + t + 4];                      \
        }                                                                         \
        _Pragma("unroll")                                                         \
        for (int nt=0; nt<4; nt++){                                               \
            int bn = wc*32 + nt*8 + g;                                            \
            bf[dst][nt][0] = (sB)[bn*STR + _k0 + t];                              \
            bf[dst][nt][1] = (sB)[bn*STR + _k0 + t + 4];                          \
        }                                                                         \
    } while(0)

    float4 acc[4][4];
    #pragma unroll
    for (int i=0;i<4;i++)
        #pragma unroll
        for (int j=0;j<4;j++) acc[i][j] = make_float4(0.f,0.f,0.f,0.f);

    uint32_t af[2][4][4], bf[2][4][2];

    int nCh = K >> 5;
    GLOAD(0); SSTORE(0);
    __syncthreads();

    for (int i = 0; i < nCh; i++){
        int b = i & 1;
        if (i + 1 < nCh) GLOAD(i + 1);
        const uint32_t* sA = &sm[ABUF(b)];
        const uint32_t* sB = &sm[BBUF(b)];
        LOADFRAG(sA, sB, 0, 0);
        #pragma unroll
        for (int ks = 0; ks < 4; ks++){
            int cur = ks & 1;
            if (ks < 3) LOADFRAG(sA, sB, ks+1, cur^1);
            #pragma unroll
            for (int mt=0; mt<4; mt++)
                #pragma unroll
                for (int nt=0; nt<4; nt++)
                    mma_tf32(acc[mt][nt],
                             af[cur][mt][0],af[cur][mt][1],af[cur][mt][2],af[cur][mt][3],
                             bf[cur][nt][0], bf[cur][nt][1]);
        }
        if (i + 1 < nCh){
            __syncthreads();
            SSTORE(b ^ 1);
            __syncthreads();
        }
    }

    const float* caddb = Cadd ? Cadd + (long)z*caddBatch : (const float*)0;

    if (fuseStep >= 0){
        // ---- fused LSTM-gate epilogue (recurrence steps) --------------------
        float* gs = (float*)sm;            // 128 x 132 staging tile
        __syncthreads();                   // all warps done reading A/B bufs
        #pragma unroll
        for (int mt=0; mt<4; mt++){
            long row0 = brow + wr*64 + mt*16 + g;
            int lr0 = wr*64 + mt*16 + g;
            #pragma unroll
            for (int nt=0; nt<4; nt++){
                int lcol = wc*32 + nt*8 + 2*t;
                long col = bcol + lcol;
                float2 v0 = make_float2(acc[mt][nt].x, acc[mt][nt].y);
                float2 v1 = make_float2(acc[mt][nt].z, acc[mt][nt].w);
                float2 a0 = *reinterpret_cast<const float2*>(&caddb[row0*caddRow + col]);
                float2 a1 = *reinterpret_cast<const float2*>(&caddb[(row0+8)*caddRow + col]);
                v0.x += a0.x; v0.y += a0.y;
                v1.x += a1.x; v1.y += a1.y;
                *reinterpret_cast<float2*>(&gs[lr0*132 + lcol])     = v0;
                *reinterpret_cast<float2*>(&gs[(lr0+8)*132 + lcol]) = v1;
            }
        }
        __syncthreads();
        int s = fuseStep;
        #pragma unroll
        for (int it=0; it<16; it++){
            int idx = tid + it*256;            // 0..4095
            int lr = idx >> 5, ld = idx & 31;
            int n = (int)brow + lr;
            int d = (int)(bcol>>2) + ld;       // bcol = 128*bx, units = 32*bx + ld
            float gi = gs[lr*132 + ld];
            float gf = gs[lr*132 + 32 + ld];
            float gu = gs[lr*132 + 64 + ld];
            float go = gs[lr*132 + 96 + ld];
            long ist = ((long)z*NT + n)*DM + d;
            float cp = s_c[ist];
            float ig=sigf(gi), fg=sigf(gf), ug=tanhf(gu), og=sigf(go);
            float cn = fg*cp + ig*ug;
            float hn = og*tanhf(cn);
            if (z == 1){                        // j0 backward: prefix-masked
                int kk = 15 - s;
                bool m = kk < s_len[n];
                float hp = Ab[(long)n*DM + d];  // old h (A operand, L2-hot)
                if (m) s_c[ist] = cn;
                hOut[ist] = m ? hn : hp;
                s_ycat0[((long)n*KC+kk)*(2*DM) + DM + d] = m ? hn : 0.f;
            } else {
                s_c[ist] = cn;
                hOut[ist] = hn;
                if (z == 0) s_ycat0[((long)n*KC+s)*(2*DM) + d] = hn;
                else if (s == s_len[n]-1)
                    s_ylcat[((long)(z-2)*NT+n)*(2*DM) + d] = hn;
            }
        }
        return;
    }

    // ---- plain epilogue ----
    const float* biasb = bias ? bias + (long)z*biasBatch : (const float*)0;
    float* Cb = C + (long)z*cBatch;
    #pragma unroll
    for (int mt=0; mt<4; mt++){
        long row0 = brow + wr*64 + mt*16 + g;
        #pragma unroll
        for (int nt=0; nt<4; nt++){
            long col = bcol + wc*32 + nt*8 + 2*t;
            float2 v0 = make_float2(acc[mt][nt].x, acc[mt][nt].y);
            float2 v1 = make_float2(acc[mt][nt].z, acc[mt][nt].w);
            if (biasb){
                v0.x += biasb[col];   v0.y += biasb[col+1];
                v1.x += biasb[col];   v1.y += biasb[col+1];
            }
            if (caddb){
                float2 a0 = *reinterpret_cast<const float2*>(&caddb[row0*caddRow + col]);
                float2 a1 = *reinterpret_cast<const float2*>(&caddb[(row0+8)*caddRow + col]);
                v0.x += a0.x; v0.y += a0.y;
                v1.x += a1.x; v1.y += a1.y;
            }
            *reinterpret_cast<float2*>(&Cb[row0*cRow + col])     = v0;
            *reinterpret_cast<float2*>(&Cb[(row0+8)*cRow + col]) = v1;
        }
    }
    #undef GLOAD
    #undef SSTORE
    #undef LOADFRAG
}

// ---------------- one-step backward gates (j=1..3, original layout) ----------
__global__ void gates_last(const float* __restrict__ c0){
    long i = (long)blockIdx.x*blockDim.x + threadIdx.x;
    if (i >= 3L*NT*DM) return;
    int jb = (int)(i/((long)NT*DM));
    long nd = i%((long)NT*DM);
    int n = (int)(nd/DM), d = (int)(nd%DM);
    const float* g = s_gB + (long)jb*NT*GD + (long)n*GD;
    float ig=sigf(g[d]), fg=sigf(g[DM+d]), ug=tanhf(g[2*DM+d]), og=sigf(g[3*DM+d]);
    float cp = c0[(jb+1)*DM+d];
    float cn = fg*cp + ig*ug;
    float hn = og*tanhf(cn);
    s_ylcat[((long)jb*NT+n)*(2*DM) + DM + d] = hn;
}

__global__ void final_k(float* __restrict__ out){
    int n = blockIdx.x, d = threadIdx.x;
    float wf = s_Wx[(long)n*GD + d];
    float wi = s_Wx[(long)n*GD + DM + d];
    float wu = s_Wx[(long)n*GD + 2*DM + d];
    float wo = s_Wx[(long)n*GD + 3*DM + d];
    int len = s_len[n];
    float bf = 0.f;
    for (int k=0;k<len;k++){
        float y  = s_ys0 [((long)n*KC+k)*DM + d];
        float cc = s_cseq[((long)n*KC+k)*DM + d];
        bf += sigf(wf + y) * cc;
    }
    float bi = sigf (s_ysl[0L*NT*DM + (long)n*DM + d] + wi);
    float bu = tanhf(s_ysl[1L*NT*DM + (long)n*DM + d] + wu);
    float bo = sigf (s_ysl[2L*NT*DM + (long)n*DM + d] + wo);
    float ncv = bi*bu + bf;
    float nhv = bo*tanhf(ncv);
    out[(long)n*DM + d] = nhv;
    out[(long)NT*DM + (long)n*DM + d] = ncv;
}

// =============================================================================
extern "C" void kernel_launch(void* const* d_in, const int* in_sizes, int n_in,
                              void* d_out, int out_size) {
    const float* x        = (const float*)d_in[0];
    const float* h_tensor = (const float*)d_in[1];
    const float* c_tensor = (const float*)d_in[2];
    const int*   indice   = (const int*)  d_in[3];
    const float* W_w      = (const float*)d_in[4];
    const float* W_b      = (const float*)d_in[5];
    const float* h0       = (const float*)d_in[6];
    const float* c0       = (const float*)d_in[7];
    const float* Wih      = (const float*)d_in[8];
    const float* Whh      = (const float*)d_in[9];
    const float* bih      = (const float*)d_in[10];
    const float* bhh      = (const float*)d_in[11];
    const float* fc       = (const float*)d_in[12];
    float* out = (float*)d_out;

    float *p_xseq,*p_Wih5,*p_Whh5,*p_b5,*p_Gx,*p_h,*p_g,*p_Wx,
          *p_xlast,*p_WihB,*p_hb,*p_gB,*p_ycat0,*p_ys0,*p_ylcat,*p_ysl;
    cudaGetSymbolAddress((void**)&p_xseq,  s_xseq);
    cudaGetSymbolAddress((void**)&p_Wih5,  s_Wih5);
    cudaGetSymbolAddress((void**)&p_Whh5,  s_Whh5);
    cudaGetSymbolAddress((void**)&p_b5,    s_b5);
    cudaGetSymbolAddress((void**)&p_Gx,    s_Gx);
    cudaGetSymbolAddress((void**)&p_h,     s_h);
    cudaGetSymbolAddress((void**)&p_g,     s_gB);   // dummy C for fused launches
    cudaGetSymbolAddress((void**)&p_Wx,    s_Wx);
    cudaGetSymbolAddress((void**)&p_xlast, s_xlast);
    cudaGetSymbolAddress((void**)&p_WihB,  s_WihB);
    cudaGetSymbolAddress((void**)&p_hb,    s_hb);
    cudaGetSymbolAddress((void**)&p_gB,    s_gB);
    cudaGetSymbolAddress((void**)&p_ycat0, s_ycat0);
    cudaGetSymbolAddress((void**)&p_ys0,   s_ys0);
    cudaGetSymbolAddress((void**)&p_ylcat, s_ylcat);
    cudaGetSymbolAddress((void**)&p_ysl,   s_ysl);
    (void)in_sizes; (void)n_in; (void)out_size;

    const int SMEM_SZ = 4*128*STR*4;      // 73728 bytes (>= 128*132*4 staging)
    cudaFuncSetAttribute(gemm_mma, cudaFuncAttributeMaxDynamicSharedMemorySize, SMEM_SZ);

    // 1) pack weights / gather / meta
    prep_weights<<<1024,256>>>(Wih,Whh,bih,bhh);
    gather_k<<<(int)(((long)NT*KC*(DM/4))/256),256>>>(h_tensor,c_tensor,indice);
    meta_k<<<512,256>>>(indice,h0,c0);

    // 2) Wx = x @ W_w^T + W_b        [4096,1024]  (original layout)
    gemm_mma<<<dim3(GD/128, NT/128, 1),256,SMEM_SZ>>>(
        x,0, W_w,0, W_b,0, (const float*)0,0,0,
        p_Wx,0,GD, NT,GD,DM, -1,0, -1,(float*)0);

    // 3) Gx = xseq @ Wih5^T + b5 (gate-interleaved), reversed rows for z==1
    gemm_mma<<<dim3(GD/128, (NT*KC)/128, NCMB),256,SMEM_SZ>>>(
        p_xseq,0, p_Wih5,(long)GD*DM, p_b5,(long)GD, (const float*)0,0,0,
        p_Gx,(long)NT*KC*GD,GD, NT*KC,GD,DM, 1,15, -1,(float*)0);

    // 4) one-step backward prep
    hb_k<<<12,256>>>(h0,Whh,bih,bhh);
    xlast_k<<<(int)(((long)NT*(DM/4)+255)/256),256>>>();

    // 5) 16 recurrence steps, gates fused into GEMM epilogue; h double-buffered
    const long HBUF = (long)NCMB*NT*DM;
    for (int s = 0; s < KC; s++){
        const float* hIn = p_h + (long)(s&1)*HBUF;
        float*      hOut = p_h + (long)((s+1)&1)*HBUF;
        gemm_mma<<<dim3(GD/128, NT/128, NCMB),256,SMEM_SZ>>>(
            hIn,(long)NT*DM, p_Whh5,(long)GD*DM, (const float*)0,0,
            p_Gx + (long)s*GD, (long)NT*KC*GD, KC*GD,
            p_g,(long)NT*GD,GD, NT,GD,DM, -1,0, s,hOut);
    }

    // 6) backward one-step for j=1..3 (original layout)
    gemm_mma<<<dim3(GD/128, NT/128, 3),256,SMEM_SZ>>>(
        p_xlast,0, p_WihB,(long)GD*DM, p_hb,(long)GD, (const float*)0,0,0,
        p_gB,(long)NT*GD,GD, NT,GD,DM, -1,0, -1,(float*)0);
    gates_last<<<(int)((3L*NT*DM+255)/256),256>>>(c0);

    // 7) fc projections
    gemm_mma<<<dim3(DM/128, (NT*KC)/128, 1),256,SMEM_SZ>>>(
        p_ycat0,0, fc,0, (const float*)0,0, (const float*)0,0,0,
        p_ys0,0,DM, NT*KC,DM,2*DM, -1,0, -1,(float*)0);
    gemm_mma<<<dim3(DM/128, NT/128, 3),256,SMEM_SZ>>>(
        p_ylcat,(long)NT*2*DM, fc + (long)DM*2*DM,(long)DM*2*DM,
        (const float*)0,0, (const float*)0,0,0,
        p_ysl,(long)NT*DM,DM, NT,DM,2*DM, -1,0, -1,(float*)0);

    // 8) final combine -> (new_h, new_c)
    final_k<<<NT,DM>>>(out);
}

// round 6
// speedup vs baseline: 1.9567x; 1.9567x over previous
#include <cuda_runtime.h>
#include <cuda_fp16.h>
#include <math.h>
#include <stdint.h>

#define NT   4096      // trees
#define KC   16        // children
#define DM   256       // DOUT
#define GD   1024      // 4*DOUT
#define NCMB 5         // recurrent combos: (j0,f),(j0,b),(j1,f),(j2,f),(j3,f)

// ---------------- scratch (device globals; no allocations allowed) ----------
// fp16 GEMM operands
__device__ __align__(16) __half s_x16   [(long)NT*DM];
__device__ __align__(16) __half s_xseq16[(long)NT*KC*DM];
__device__ __align__(16) __half s_xlast16[(long)NT*DM];
__device__ __align__(16) __half s_Wih5h [(long)NCMB*GD*DM];
__device__ __align__(16) __half s_Whh5h [(long)NCMB*GD*DM];
__device__ __align__(16) __half s_WihBh [3L*GD*DM];
__device__ __align__(16) __half s_Wwh   [(long)GD*DM];
__device__ __align__(16) __half s_fch   [4L*DM*2*DM];
__device__ __align__(16) __half s_h16   [(long)NCMB*NT*DM];
__device__ __align__(16) __half s_ycat016[(long)NT*KC*2*DM];
__device__ __align__(16) __half s_ylcat16[3L*NT*2*DM];
// fp32 state / accumulators
__device__ float s_cseq [(long)NT*KC*DM];
__device__ int   s_len  [NT];
__device__ float s_b5   [NCMB*GD];
__device__ float s_hb   [3*GD];
__device__ float s_Gx   [(long)NCMB*NT*KC*GD];
__device__ float s_c    [(long)NCMB*NT*DM];
__device__ float s_g    [(long)NCMB*NT*GD];
__device__ float s_gB   [3L*NT*GD];
__device__ float s_Wx   [(long)NT*GD];
__device__ float s_ys0  [(long)NT*KC*DM];
__device__ float s_ysl  [3L*NT*DM];

__device__ __forceinline__ float sigf(float x){ return 1.f/(1.f+expf(-x)); }

__device__ __forceinline__ void mma_f16(float4& c,
        uint32_t a0, uint32_t a1, uint32_t a2, uint32_t a3,
        uint32_t b0, uint32_t b1){
    asm volatile(
        "mma.sync.aligned.m16n8k16.row.col.f32.f16.f16.f32 "
        "{%0,%1,%2,%3}, {%4,%5,%6,%7}, {%8,%9}, {%0,%1,%2,%3};"
        : "+f"(c.x), "+f"(c.y), "+f"(c.z), "+f"(c.w)
        : "r"(a0), "r"(a1), "r"(a2), "r"(a3), "r"(b0), "r"(b1));
}

// ---------------- prep: pack + convert weights to fp16 ----------------------
__global__ void prep_weights(const float* __restrict__ Wih, const float* __restrict__ Whh,
                             const float* __restrict__ bih, const float* __restrict__ bhh,
                             const float* __restrict__ W_w, const float* __restrict__ fc){
    const int map5[5]={0,1,2,4,6};
    const int mapB[3]={3,5,7};
    long idx = (long)blockIdx.x*blockDim.x + threadIdx.x;
    long stride = (long)gridDim.x*blockDim.x;
    for (long i=idx; i<(long)NCMB*GD*DM; i+=stride){
        int cmb = (int)(i/((long)GD*DM)); long r = i%((long)GD*DM);
        s_Wih5h[i]=__float2half(Wih[(long)map5[cmb]*GD*DM + r]);
        s_Whh5h[i]=__float2half(Whh[(long)map5[cmb]*GD*DM + r]);
    }
    for (long i=idx; i<3L*GD*DM; i+=stride){
        int jb = (int)(i/((long)GD*DM)); long r = i%((long)GD*DM);
        s_WihBh[i]=__float2half(Wih[(long)mapB[jb]*GD*DM + r]);
    }
    for (long i=idx; i<(long)GD*DM; i+=stride)
        s_Wwh[i]=__float2half(W_w[i]);
    for (long i=idx; i<4L*DM*2*DM; i+=stride)
        s_fch[i]=__float2half(fc[i]);
    for (long i=idx; i<(long)NCMB*GD; i+=stride){
        int cmb=(int)(i/GD); int o=(int)(i%GD);
        s_b5[i]=bih[map5[cmb]*GD+o]+bhh[map5[cmb]*GD+o];
    }
}

// ---------------- convert x to fp16 ------------------------------------------
__global__ void conv_x(const float* __restrict__ x){
    long i = (long)blockIdx.x*blockDim.x + threadIdx.x;
    if (i < (long)NT*DM) s_x16[i] = __float2half(x[i]);
}

// ---------------- gather child states ---------------------------------------
__global__ void gather_k(const float* __restrict__ h_tensor,
                         const float* __restrict__ c_tensor,
                         const int*   __restrict__ indice){
    long i = (long)blockIdx.x*blockDim.x + threadIdx.x;
    if (i >= (long)NT*KC*(DM/4)) return;
    long nk = i / (DM/4);
    int  d4 = (int)(i % (DM/4));
    int id = indice[nk]; if (id < 0) id = 0;
    float4 h = ((const float4*)h_tensor)[(long)id*(DM/4)+d4];
    ((float4*)s_cseq)[i] = ((const float4*)c_tensor)[(long)id*(DM/4)+d4];
    __half2 h01 = __floats2half2_rn(h.x, h.y);
    __half2 h23 = __floats2half2_rn(h.z, h.w);
    ((__half2*)s_xseq16)[i*2]   = h01;
    ((__half2*)s_xseq16)[i*2+1] = h23;
}

// ---------------- lengths + initial states ----------------------------------
__global__ void meta_k(const int* __restrict__ indice,
                       const float* __restrict__ h0, const float* __restrict__ c0){
    long idx = (long)blockIdx.x*blockDim.x + threadIdx.x;
    long stride = (long)gridDim.x*blockDim.x;
    for (long n=idx; n<NT; n+=stride){
        int l=0;
        #pragma unroll
        for (int k=0;k<KC;k++) if (indice[n*KC+k] != -1) l++;
        s_len[n]=l;
    }
    const int jmap[5]={0,0,1,2,3};
    for (long i=idx; i<(long)NCMB*NT*DM; i+=stride){
        int cmb = (int)(i/((long)NT*DM)); int d = (int)(i%DM);
        s_h16[i] = __float2half(h0[jmap[cmb]*DM+d]);
        s_c[i]   = c0[jmap[cmb]*DM+d];
    }
}

__global__ void xlast_k(){
    long i = (long)blockIdx.x*blockDim.x + threadIdx.x;   // uint4 index (8 fp16)
    if (i >= (long)NT*(DM/8)) return;
    int n = (int)(i/(DM/8)); int j = (int)(i%(DM/8));
    int last = s_len[n]-1;
    ((uint4*)s_xlast16)[i] = ((const uint4*)s_xseq16)[((long)n*KC+last)*(DM/8)+j];
}

__global__ void hb_k(const float* __restrict__ h0, const float* __restrict__ Whh,
                     const float* __restrict__ bih, const float* __restrict__ bhh){
    int idx = blockIdx.x*blockDim.x + threadIdx.x;
    if (idx >= 3*GD) return;
    int jb = idx/GD, o = idx%GD;
    int jd2 = 2*(jb+1)+1;
    const float* w = Whh + (long)jd2*GD*DM + (long)o*DM;
    const float* h = h0 + (jb+1)*DM;
    float acc=0.f;
    #pragma unroll 8
    for (int d=0; d<DM; d++) acc += h[d]*w[d];
    s_hb[idx] = acc + bih[jd2*GD+o] + bhh[jd2*GD+o];
}

// ---------------- fp16 mma.sync batched GEMM: C = A @ B^T (+bias)(+Cadd) ----
// A:[M,K] rm fp16, B:[N,K] rm fp16, M%128==0, N%128==0, K%32==0, fp32 accum.
// 256 thr = 8 warps in 2x4; warp tile 64x32 via m16n8k16 (4 mtiles x 4 ntiles).
// K chunks of 32 fp16 (64B/row); cp.async 3-stage ring, one sync per chunk.
#define STR2 20                       // u32 per smem row (16 data + 4 pad)
#define AB_U32 (128*STR2)             // 2560 u32 per tile buffer
#define ABUF(b) ((b)*AB_U32)
#define BBUF(b) (3*AB_U32 + (b)*AB_U32)

__global__ void __launch_bounds__(256,2) gemm_h(
    const __half* __restrict__ A, long aBatch,
    const __half* __restrict__ B, long bBatch,
    const float* __restrict__ bias, long biasBatch,
    const float* __restrict__ Cadd, long caddBatch, int caddRow,
    float* __restrict__ C, long cBatch, int cRow,
    int M, int N, int K, int xorZ, int xorVal)
{
    extern __shared__ uint32_t sm[];
    uint32_t sbase;
    asm("{ .reg .u64 t; cvta.to.shared.u64 t, %1; cvt.u32.u64 %0, t; }"
        : "=r"(sbase) : "l"(sm));
    int tid = threadIdx.x;
    int wid = tid >> 5;
    int lane = tid & 31;
    int g = lane >> 2, t = lane & 3;
    int wr = wid >> 2, wc = wid & 3;

    int z = blockIdx.z;
    const __half* Ab = A + (long)z*aBatch;
    const __half* Bb = B + (long)z*bBatch;
    int rxor = (z==xorZ) ? xorVal : 0;
    long brow = (long)blockIdx.y * 128;
    long bcol = (long)blockIdx.x * 128;

    int lrow4 = tid >> 2;         // 0..63 (row within half-tile pass)
    int lq    = tid & 3;          // 16B quarter of a 64B row

    // full coverage: 128 rows x 64B per tile = 512 x 16B chunks = 256 thr x 2
    #define PREFETCH(ch, buf) do {                                                \
        long kb = (long)(ch)*32;                                                  \
        _Pragma("unroll")                                                         \
        for (int l=0;l<2;l++){                                                    \
            int r = lrow4 + l*64;                                                 \
            long gr = (brow + r) ^ rxor;                                          \
            uint32_t da = sbase + (ABUF(buf) + r*STR2)*4 + lq*16;                 \
            asm volatile("cp.async.cg.shared.global [%0],[%1],16;"                \
                         :: "r"(da), "l"(Ab + gr*K + kb + lq*8));                 \
            uint32_t db = sbase + (BBUF(buf) + r*STR2)*4 + lq*16;                 \
            asm volatile("cp.async.cg.shared.global [%0],[%1],16;"                \
                         :: "r"(db), "l"(Bb + (bcol + r)*K + kb + lq*8));         \
        }                                                                         \
        asm volatile("cp.async.commit_group;");                                   \
    } while(0)

    float4 acc[4][4];
    #pragma unroll
    for (int i=0;i<4;i++)
        #pragma unroll
        for (int j=0;j<4;j++) acc[i][j] = make_float4(0.f,0.f,0.f,0.f);

    int nCh = K >> 5;
    PREFETCH(0, 0);
    if (nCh > 1) PREFETCH(1, 1);

    for (int i = 0; i < nCh; i++){
        if (i + 1 < nCh) asm volatile("cp.async.wait_group 1;" ::: "memory");
        else             asm volatile("cp.async.wait_group 0;" ::: "memory");
        __syncthreads();
        int cb = i % 3;
        const uint32_t* sA = &sm[ABUF(cb)];
        const uint32_t* sB = &sm[BBUF(cb)];
        #pragma unroll
        for (int ks = 0; ks < 2; ks++){
            int k0 = ks*8;
            uint32_t af[4][4], bf[4][2];
            #pragma unroll
            for (int mt=0; mt<4; mt++){
                int ar = wr*64 + mt*16 + g;
                af[mt][0] = sA[ar*STR2 + k0 + t];
                af[mt][1] = sA[(ar+8)*STR2 + k0 + t];
                af[mt][2] = sA[ar*STR2 + k0 + t + 4];
                af[mt][3] = sA[(ar+8)*STR2 + k0 + t + 4];
            }
            #pragma unroll
            for (int nt=0; nt<4; nt++){
                int bn = wc*32 + nt*8 + g;
                bf[nt][0] = sB[bn*STR2 + k0 + t];
                bf[nt][1] = sB[bn*STR2 + k0 + t + 4];
            }
            #pragma unroll
            for (int mt=0; mt<4; mt++)
                #pragma unroll
                for (int nt=0; nt<4; nt++)
                    mma_f16(acc[mt][nt], af[mt][0],af[mt][1],af[mt][2],af[mt][3],
                            bf[nt][0], bf[nt][1]);
        }
        if (i + 2 < nCh) PREFETCH(i + 2, (i + 2) % 3);
    }

    // ---- epilogue ----
    const float* biasb = bias ? bias + (long)z*biasBatch : (const float*)0;
    const float* caddb = Cadd ? Cadd + (long)z*caddBatch : (const float*)0;
    float* Cb = C + (long)z*cBatch;
    #pragma unroll
    for (int mt=0; mt<4; mt++){
        long row0 = brow + wr*64 + mt*16 + g;
        #pragma unroll
        for (int nt=0; nt<4; nt++){
            long col = bcol + wc*32 + nt*8 + 2*t;
            float2 v0 = make_float2(acc[mt][nt].x, acc[mt][nt].y);
            float2 v1 = make_float2(acc[mt][nt].z, acc[mt][nt].w);
            if (biasb){
                v0.x += biasb[col];   v0.y += biasb[col+1];
                v1.x += biasb[col];   v1.y += biasb[col+1];
            }
            if (caddb){
                float2 a0 = *reinterpret_cast<const float2*>(&caddb[row0*caddRow + col]);
                float2 a1 = *reinterpret_cast<const float2*>(&caddb[(row0+8)*caddRow + col]);
                v0.x += a0.x; v0.y += a0.y;
                v1.x += a1.x; v1.y += a1.y;
            }
            *reinterpret_cast<float2*>(&Cb[row0*cRow + col])     = v0;
            *reinterpret_cast<float2*>(&Cb[(row0+8)*cRow + col]) = v1;
        }
    }
    #undef PREFETCH
}

// ---------------- gates + state update per recurrence step -------------------
__global__ void gates_step(int s){
    long i = (long)blockIdx.x*blockDim.x + threadIdx.x;
    if (i >= (long)NCMB*NT*DM) return;
    int cmb = (int)(i/((long)NT*DM));
    long nd = i%((long)NT*DM);
    int n = (int)(nd/DM), d = (int)(nd%DM);
    const float* g = s_g + (long)cmb*NT*GD + (long)n*GD;
    float ig = sigf(g[d]);
    float fg = sigf(g[DM+d]);
    float ug = tanhf(g[2*DM+d]);
    float og = sigf(g[3*DM+d]);
    float cp = s_c[i];
    float cn = fg*cp + ig*ug;
    float hn = og*tanhf(cn);
    if (cmb == 1){
        int kk = 15 - s;
        bool m = kk < s_len[n];
        if (m){ s_c[i]=cn; s_h16[i]=__float2half(hn); }
        s_ycat016[((long)n*KC+kk)*(2*DM) + DM + d] = __float2half(m ? hn : 0.f);
    } else {
        s_c[i]=cn;
        s_h16[i]=__float2half(hn);
        if (cmb==0) s_ycat016[((long)n*KC+s)*(2*DM) + d] = __float2half(hn);
        else if (s == s_len[n]-1)
            s_ylcat16[((long)(cmb-2)*NT+n)*(2*DM) + d] = __float2half(hn);
    }
}

__global__ void gates_last(const float* __restrict__ c0){
    long i = (long)blockIdx.x*blockDim.x + threadIdx.x;
    if (i >= 3L*NT*DM) return;
    int jb = (int)(i/((long)NT*DM));
    long nd = i%((long)NT*DM);
    int n = (int)(nd/DM), d = (int)(nd%DM);
    const float* g = s_gB + (long)jb*NT*GD + (long)n*GD;
    float ig=sigf(g[d]), fg=sigf(g[DM+d]), ug=tanhf(g[2*DM+d]), og=sigf(g[3*DM+d]);
    float cp = c0[(jb+1)*DM+d];
    float cn = fg*cp + ig*ug;
    float hn = og*tanhf(cn);
    s_ylcat16[((long)jb*NT+n)*(2*DM) + DM + d] = __float2half(hn);
}

__global__ void final_k(float* __restrict__ out){
    int n = blockIdx.x, d = threadIdx.x;
    float wf = s_Wx[(long)n*GD + d];
    float wi = s_Wx[(long)n*GD + DM + d];
    float wu = s_Wx[(long)n*GD + 2*DM + d];
    float wo = s_Wx[(long)n*GD + 3*DM + d];
    int len = s_len[n];
    float bf = 0.f;
    for (int k=0;k<len;k++){
        float y  = s_ys0 [((long)n*KC+k)*DM + d];
        float cc = s_cseq[((long)n*KC+k)*DM + d];
        bf += sigf(wf + y) * cc;
    }
    float bi = sigf (s_ysl[0L*NT*DM + (long)n*DM + d] + wi);
    float bu = tanhf(s_ysl[1L*NT*DM + (long)n*DM + d] + wu);
    float bo = sigf (s_ysl[2L*NT*DM + (long)n*DM + d] + wo);
    float ncv = bi*bu + bf;
    float nhv = bo*tanhf(ncv);
    out[(long)n*DM + d] = nhv;
    out[(long)NT*DM + (long)n*DM + d] = ncv;
}

// =============================================================================
extern "C" void kernel_launch(void* const* d_in, const int* in_sizes, int n_in,
                              void* d_out, int out_size) {
    const float* x        = (const float*)d_in[0];
    const float* h_tensor = (const float*)d_in[1];
    const float* c_tensor = (const float*)d_in[2];
    const int*   indice   = (const int*)  d_in[3];
    const float* W_w      = (const float*)d_in[4];
    const float* W_b      = (const float*)d_in[5];
    const float* h0       = (const float*)d_in[6];
    const float* c0       = (const float*)d_in[7];
    const float* Wih      = (const float*)d_in[8];
    const float* Whh      = (const float*)d_in[9];
    const float* bih      = (const float*)d_in[10];
    const float* bhh      = (const float*)d_in[11];
    const float* fc       = (const float*)d_in[12];
    float* out = (float*)d_out;

    __half *p_x16,*p_xseq16,*p_xlast16,*p_Wih5h,*p_Whh5h,*p_WihBh,*p_Wwh,*p_fch,
           *p_h16,*p_ycat016,*p_ylcat16;
    float *p_b5,*p_hb,*p_Gx,*p_g,*p_gB,*p_Wx,*p_ys0,*p_ysl;
    cudaGetSymbolAddress((void**)&p_x16,     s_x16);
    cudaGetSymbolAddress((void**)&p_xseq16,  s_xseq16);
    cudaGetSymbolAddress((void**)&p_xlast16, s_xlast16);
    cudaGetSymbolAddress((void**)&p_Wih5h,   s_Wih5h);
    cudaGetSymbolAddress((void**)&p_Whh5h,   s_Whh5h);
    cudaGetSymbolAddress((void**)&p_WihBh,   s_WihBh);
    cudaGetSymbolAddress((void**)&p_Wwh,     s_Wwh);
    cudaGetSymbolAddress((void**)&p_fch,     s_fch);
    cudaGetSymbolAddress((void**)&p_h16,     s_h16);
    cudaGetSymbolAddress((void**)&p_ycat016, s_ycat016);
    cudaGetSymbolAddress((void**)&p_ylcat16, s_ylcat16);
    cudaGetSymbolAddress((void**)&p_b5,      s_b5);
    cudaGetSymbolAddress((void**)&p_hb,      s_hb);
    cudaGetSymbolAddress((void**)&p_Gx,      s_Gx);
    cudaGetSymbolAddress((void**)&p_g,       s_g);
    cudaGetSymbolAddress((void**)&p_gB,      s_gB);
    cudaGetSymbolAddress((void**)&p_Wx,      s_Wx);
    cudaGetSymbolAddress((void**)&p_ys0,     s_ys0);
    cudaGetSymbolAddress((void**)&p_ysl,     s_ysl);
    (void)in_sizes; (void)n_in; (void)out_size;

    const int SMEM_SZ = 6*AB_U32*4;       // 61440 bytes (3-stage A+B ring)
    cudaFuncSetAttribute(gemm_h, cudaFuncAttributeMaxDynamicSharedMemorySize, SMEM_SZ);

    // 1) pack/convert weights, convert x, gather, meta
    prep_weights<<<1024,256>>>(Wih,Whh,bih,bhh,W_w,fc);
    conv_x<<<(int)(((long)NT*DM+255)/256),256>>>(x);
    gather_k<<<(int)(((long)NT*KC*(DM/4))/256),256>>>(h_tensor,c_tensor,indice);
    meta_k<<<512,256>>>(indice,h0,c0);

    // 2) Wx = x @ W_w^T + W_b        [4096,1024]
    gemm_h<<<dim3(GD/128, NT/128, 1),256,SMEM_SZ>>>(
        p_x16,0, p_Wwh,0, W_b,0, (const float*)0,0,0,
        p_Wx,0,GD, NT,GD,DM, -1,0);

    // 3) Gx = xseq @ Wih5^T + b5, time-reversed rows for combo 1 (z==1)
    gemm_h<<<dim3(GD/128, (NT*KC)/128, NCMB),256,SMEM_SZ>>>(
        p_xseq16,0, p_Wih5h,(long)GD*DM, p_b5,(long)GD, (const float*)0,0,0,
        p_Gx,(long)NT*KC*GD,GD, NT*KC,GD,DM, 1,15);

    // 4) one-step backward prep
    hb_k<<<12,256>>>(h0,Whh,bih,bhh);
    xlast_k<<<(int)(((long)NT*(DM/8)+255)/256),256>>>();

    // 5) the 16 recurrence steps (5 combos batched per step)
    long gatesN = (long)NCMB*NT*DM;
    for (int s = 0; s < KC; s++){
        gemm_h<<<dim3(GD/128, NT/128, NCMB),256,SMEM_SZ>>>(
            p_h16,(long)NT*DM, p_Whh5h,(long)GD*DM, (const float*)0,0,
            p_Gx + (long)s*GD, (long)NT*KC*GD, KC*GD,
            p_g,(long)NT*GD,GD, NT,GD,DM, -1,0);
        gates_step<<<(int)((gatesN+255)/256),256>>>(s);
    }

    // 6) backward one-step for j=1..3
    gemm_h<<<dim3(GD/128, NT/128, 3),256,SMEM_SZ>>>(
        p_xlast16,0, p_WihBh,(long)GD*DM, p_hb,(long)GD, (const float*)0,0,0,
        p_gB,(long)NT*GD,GD, NT,GD,DM, -1,0);
    gates_last<<<(int)((3L*NT*DM+255)/256),256>>>(c0);

    // 7) fc projections
    gemm_h<<<dim3(DM/128, (NT*KC)/128, 1),256,SMEM_SZ>>>(
        p_ycat016,0, p_fch,0, (const float*)0,0, (const float*)0,0,0,
        p_ys0,0,DM, NT*KC,DM,2*DM, -1,0);
    gemm_h<<<dim3(DM/128, NT/128, 3),256,SMEM_SZ>>>(
        p_ylcat16,(long)NT*2*DM, p_fch + (long)DM*2*DM,(long)DM*2*DM,
        (const float*)0,0, (const float*)0,0,0,
        p_ysl,(long)NT*DM,DM, NT,DM,2*DM, -1,0);

    // 8) final combine -> (new_h, new_c)
    final_k<<<NT,DM>>>(out);
}

// round 7
// speedup vs baseline: 2.4118x; 1.2326x over previous
#include <cuda_runtime.h>
#include <cuda_fp16.h>
#include <math.h>
#include <stdint.h>

#define NT   4096      // trees
#define KC   16        // children
#define DM   256       // DOUT
#define GD   1024      // 4*DOUT
#define NCMB 5         // recurrent combos: (j0,f),(j0,b),(j1,f),(j2,f),(j3,f)

// ---------------- scratch (device globals; no allocations allowed) ----------
// fp16 GEMM operands
__device__ __align__(16) __half s_x16   [(long)NT*DM];
__device__ __align__(16) __half s_xseq16[(long)NT*KC*DM];
__device__ __align__(16) __half s_xlast16[(long)NT*DM];
__device__ __align__(16) __half s_Wih5h [(long)NCMB*GD*DM];
__device__ __align__(16) __half s_Whh5h [(long)NCMB*GD*DM];
__device__ __align__(16) __half s_WihBh [3L*GD*DM];
__device__ __align__(16) __half s_Wwh   [(long)GD*DM];
__device__ __align__(16) __half s_fch   [4L*DM*2*DM];
__device__ __align__(16) __half s_h16   [(long)NCMB*NT*DM];
__device__ __align__(16) __half s_ycat016[(long)NT*KC*2*DM];
__device__ __align__(16) __half s_ylcat16[3L*NT*2*DM];
// fp16 intermediates (halved DRAM traffic)
__device__ __align__(16) __half s_Gx16  [(long)NCMB*NT*KC*GD];
__device__ __align__(16) __half s_g16   [(long)NCMB*NT*GD];
__device__ __align__(16) __half s_gB16  [3L*NT*GD];
__device__ __align__(16) __half s_ys016 [(long)NT*KC*DM];
__device__ __align__(16) __half s_ysl16 [3L*NT*DM];
// fp32 state
__device__ float s_cseq [(long)NT*KC*DM];
__device__ int   s_len  [NT];
__device__ float s_b5   [NCMB*GD];
__device__ float s_hb   [3*GD];
__device__ float s_c    [(long)NCMB*NT*DM];
__device__ float s_Wx   [(long)NT*GD];

__device__ __forceinline__ float sigf(float x){ return 1.f/(1.f+expf(-x)); }

__device__ __forceinline__ void mma_f16(float4& c,
        uint32_t a0, uint32_t a1, uint32_t a2, uint32_t a3,
        uint32_t b0, uint32_t b1){
    asm volatile(
        "mma.sync.aligned.m16n8k16.row.col.f32.f16.f16.f32 "
        "{%0,%1,%2,%3}, {%4,%5,%6,%7}, {%8,%9}, {%0,%1,%2,%3};"
        : "+f"(c.x), "+f"(c.y), "+f"(c.z), "+f"(c.w)
        : "r"(a0), "r"(a1), "r"(a2), "r"(a3), "r"(b0), "r"(b1));
}

// ---------------- prep: pack + convert weights to fp16 ----------------------
__global__ void prep_weights(const float* __restrict__ Wih, const float* __restrict__ Whh,
                             const float* __restrict__ bih, const float* __restrict__ bhh,
                             const float* __restrict__ W_w, const float* __restrict__ fc){
    const int map5[5]={0,1,2,4,6};
    const int mapB[3]={3,5,7};
    long idx = (long)blockIdx.x*blockDim.x + threadIdx.x;
    long stride = (long)gridDim.x*blockDim.x;
    for (long i=idx; i<(long)NCMB*GD*DM; i+=stride){
        int cmb = (int)(i/((long)GD*DM)); long r = i%((long)GD*DM);
        s_Wih5h[i]=__float2half(Wih[(long)map5[cmb]*GD*DM + r]);
        s_Whh5h[i]=__float2half(Whh[(long)map5[cmb]*GD*DM + r]);
    }
    for (long i=idx; i<3L*GD*DM; i+=stride){
        int jb = (int)(i/((long)GD*DM)); long r = i%((long)GD*DM);
        s_WihBh[i]=__float2half(Wih[(long)mapB[jb]*GD*DM + r]);
    }
    for (long i=idx; i<(long)GD*DM; i+=stride)
        s_Wwh[i]=__float2half(W_w[i]);
    for (long i=idx; i<4L*DM*2*DM; i+=stride)
        s_fch[i]=__float2half(fc[i]);
    for (long i=idx; i<(long)NCMB*GD; i+=stride){
        int cmb=(int)(i/GD); int o=(int)(i%GD);
        s_b5[i]=bih[map5[cmb]*GD+o]+bhh[map5[cmb]*GD+o];
    }
}

// ---------------- convert x to fp16 ------------------------------------------
__global__ void conv_x(const float* __restrict__ x){
    long i = (long)blockIdx.x*blockDim.x + threadIdx.x;
    if (i < (long)NT*DM) s_x16[i] = __float2half(x[i]);
}

// ---------------- gather child states ---------------------------------------
__global__ void gather_k(const float* __restrict__ h_tensor,
                         const float* __restrict__ c_tensor,
                         const int*   __restrict__ indice){
    long i = (long)blockIdx.x*blockDim.x + threadIdx.x;
    if (i >= (long)NT*KC*(DM/4)) return;
    long nk = i / (DM/4);
    int  d4 = (int)(i % (DM/4));
    int id = indice[nk]; if (id < 0) id = 0;
    float4 h = ((const float4*)h_tensor)[(long)id*(DM/4)+d4];
    ((float4*)s_cseq)[i] = ((const float4*)c_tensor)[(long)id*(DM/4)+d4];
    ((__half2*)s_xseq16)[i*2]   = __floats2half2_rn(h.x, h.y);
    ((__half2*)s_xseq16)[i*2+1] = __floats2half2_rn(h.z, h.w);
}

// ---------------- lengths + initial states ----------------------------------
__global__ void meta_k(const int* __restrict__ indice,
                       const float* __restrict__ h0, const float* __restrict__ c0){
    long idx = (long)blockIdx.x*blockDim.x + threadIdx.x;
    long stride = (long)gridDim.x*blockDim.x;
    for (long n=idx; n<NT; n+=stride){
        int l=0;
        #pragma unroll
        for (int k=0;k<KC;k++) if (indice[n*KC+k] != -1) l++;
        s_len[n]=l;
    }
    const int jmap[5]={0,0,1,2,3};
    for (long i=idx; i<(long)NCMB*NT*DM; i+=stride){
        int cmb = (int)(i/((long)NT*DM)); int d = (int)(i%DM);
        s_h16[i] = __float2half(h0[jmap[cmb]*DM+d]);
        s_c[i]   = c0[jmap[cmb]*DM+d];
    }
}

__global__ void xlast_k(){
    long i = (long)blockIdx.x*blockDim.x + threadIdx.x;   // uint4 index (8 fp16)
    if (i >= (long)NT*(DM/8)) return;
    int n = (int)(i/(DM/8)); int j = (int)(i%(DM/8));
    int last = s_len[n]-1;
    ((uint4*)s_xlast16)[i] = ((const uint4*)s_xseq16)[((long)n*KC+last)*(DM/8)+j];
}

__global__ void hb_k(const float* __restrict__ h0, const float* __restrict__ Whh,
                     const float* __restrict__ bih, const float* __restrict__ bhh){
    int idx = blockIdx.x*blockDim.x + threadIdx.x;
    if (idx >= 3*GD) return;
    int jb = idx/GD, o = idx%GD;
    int jd2 = 2*(jb+1)+1;
    const float* w = Whh + (long)jd2*GD*DM + (long)o*DM;
    const float* h = h0 + (jb+1)*DM;
    float acc=0.f;
    #pragma unroll 8
    for (int d=0; d<DM; d++) acc += h[d]*w[d];
    s_hb[idx] = acc + bih[jd2*GD+o] + bhh[jd2*GD+o];
}

// ---------------- fp16 mma.sync batched GEMM -----------------------------
// C = A @ B^T (+bias fp32)(+Cadd fp16); C is fp32 (CF) or fp16 (CH).
// A:[M,K] rm fp16, B:[N,K] rm fp16, M%128==0, N%128==0, K%32==0, fp32 accum.
// 256 thr = 8 warps in 2x4; warp tile 64x32 via m16n8k16.
// K chunks of 32 fp16 (64B/row); cp.async 3-stage ring, one sync per chunk.
#define STR2 20                       // u32 per smem row (16 data + 4 pad)
#define AB_U32 (128*STR2)             // 2560 u32 per tile buffer
#define ABUF(b) ((b)*AB_U32)
#define BBUF(b) (3*AB_U32 + (b)*AB_U32)

__global__ void __launch_bounds__(256,2) gemm_h(
    const __half* __restrict__ A, long aBatch,
    const __half* __restrict__ B, long bBatch,
    const float* __restrict__ bias, long biasBatch,
    const __half* __restrict__ CaddH, long caddBatch, int caddRow,
    float* __restrict__ CF, __half* __restrict__ CH, long cBatch, int cRow,
    int M, int N, int K, int xorZ, int xorVal)
{
    extern __shared__ uint32_t sm[];
    uint32_t sbase;
    asm("{ .reg .u64 t; cvta.to.shared.u64 t, %1; cvt.u32.u64 %0, t; }"
        : "=r"(sbase) : "l"(sm));
    int tid = threadIdx.x;
    int wid = tid >> 5;
    int lane = tid & 31;
    int g = lane >> 2, t = lane & 3;
    int wr = wid >> 2, wc = wid & 3;

    int z = blockIdx.z;
    const __half* Ab = A + (long)z*aBatch;
    const __half* Bb = B + (long)z*bBatch;
    int rxor = (z==xorZ) ? xorVal : 0;
    long brow = (long)blockIdx.y * 128;
    long bcol = (long)blockIdx.x * 128;

    int lrow4 = tid >> 2;         // 0..63
    int lq    = tid & 3;          // 16B quarter of a 64B row

    #define PREFETCH(ch, buf) do {                                                \
        long kb = (long)(ch)*32;                                                  \
        _Pragma("unroll")                                                         \
        for (int l=0;l<2;l++){                                                    \
            int r = lrow4 + l*64;                                                 \
            long gr = (brow + r) ^ rxor;                                          \
            uint32_t da = sbase + (ABUF(buf) + r*STR2)*4 + lq*16;                 \
            asm volatile("cp.async.cg.shared.global [%0],[%1],16;"                \
                         :: "r"(da), "l"(Ab + gr*K + kb + lq*8));                 \
            uint32_t db = sbase + (BBUF(buf) + r*STR2)*4 + lq*16;                 \
            asm volatile("cp.async.cg.shared.global [%0],[%1],16;"                \
                         :: "r"(db), "l"(Bb + (bcol + r)*K + kb + lq*8));         \
        }                                                                         \
        asm volatile("cp.async.commit_group;");                                   \
    } while(0)

    float4 acc[4][4];
    #pragma unroll
    for (int i=0;i<4;i++)
        #pragma unroll
        for (int j=0;j<4;j++) acc[i][j] = make_float4(0.f,0.f,0.f,0.f);

    int nCh = K >> 5;
    PREFETCH(0, 0);
    if (nCh > 1) PREFETCH(1, 1);

    for (int i = 0; i < nCh; i++){
        if (i + 1 < nCh) asm volatile("cp.async.wait_group 1;" ::: "memory");
        else             asm volatile("cp.async.wait_group 0;" ::: "memory");
        __syncthreads();
        int cb = i % 3;
        const uint32_t* sA = &sm[ABUF(cb)];
        const uint32_t* sB = &sm[BBUF(cb)];
        #pragma unroll
        for (int ks = 0; ks < 2; ks++){
            int k0 = ks*8;
            uint32_t af[4][4], bf[4][2];
            #pragma unroll
            for (int mt=0; mt<4; mt++){
                int ar = wr*64 + mt*16 + g;
                af[mt][0] = sA[ar*STR2 + k0 + t];
                af[mt][1] = sA[(ar+8)*STR2 + k0 + t];
                af[mt][2] = sA[ar*STR2 + k0 + t + 4];
                af[mt][3] = sA[(ar+8)*STR2 + k0 + t + 4];
            }
            #pragma unroll
            for (int nt=0; nt<4; nt++){
                int bn = wc*32 + nt*8 + g;
                bf[nt][0] = sB[bn*STR2 + k0 + t];
                bf[nt][1] = sB[bn*STR2 + k0 + t + 4];
            }
            #pragma unroll
            for (int mt=0; mt<4; mt++)
                #pragma unroll
                for (int nt=0; nt<4; nt++)
                    mma_f16(acc[mt][nt], af[mt][0],af[mt][1],af[mt][2],af[mt][3],
                            bf[nt][0], bf[nt][1]);
        }
        if (i + 2 < nCh) PREFETCH(i + 2, (i + 2) % 3);
    }

    // ---- epilogue ----
    const float*  biasb = bias  ? bias  + (long)z*biasBatch : (const float*)0;
    const __half* caddb = CaddH ? CaddH + (long)z*caddBatch : (const __half*)0;
    #pragma unroll
    for (int mt=0; mt<4; mt++){
        long row0 = brow + wr*64 + mt*16 + g;
        #pragma unroll
        for (int nt=0; nt<4; nt++){
            long col = bcol + wc*32 + nt*8 + 2*t;
            float2 v0 = make_float2(acc[mt][nt].x, acc[mt][nt].y);
            float2 v1 = make_float2(acc[mt][nt].z, acc[mt][nt].w);
            if (biasb){
                v0.x += biasb[col];   v0.y += biasb[col+1];
                v1.x += biasb[col];   v1.y += biasb[col+1];
            }
            if (caddb){
                float2 a0 = __half22float2(*reinterpret_cast<const __half2*>(&caddb[row0*caddRow + col]));
                float2 a1 = __half22float2(*reinterpret_cast<const __half2*>(&caddb[(row0+8)*caddRow + col]));
                v0.x += a0.x; v0.y += a0.y;
                v1.x += a1.x; v1.y += a1.y;
            }
            if (CH){
                __half* Cb = CH + (long)z*cBatch;
                *reinterpret_cast<__half2*>(&Cb[row0*cRow + col])     = __floats2half2_rn(v0.x, v0.y);
                *reinterpret_cast<__half2*>(&Cb[(row0+8)*cRow + col]) = __floats2half2_rn(v1.x, v1.y);
            } else {
                float* Cb = CF + (long)z*cBatch;
                *reinterpret_cast<float2*>(&Cb[row0*cRow + col])     = v0;
                *reinterpret_cast<float2*>(&Cb[(row0+8)*cRow + col]) = v1;
            }
        }
    }
    #undef PREFETCH
}

// ---------------- gates + state update per recurrence step (half2) ----------
__global__ void gates_step(int s){
    long i = (long)blockIdx.x*blockDim.x + threadIdx.x;
    if (i >= (long)NCMB*NT*(DM/2)) return;
    int cmb = (int)(i/((long)NT*(DM/2)));
    long nd = i%((long)NT*(DM/2));
    int n = (int)(nd/(DM/2)), d2 = (int)(nd%(DM/2));
    int d = d2*2;
    const __half2* g = (const __half2*)(s_g16 + (long)cmb*NT*GD + (long)n*GD);
    float2 gi = __half22float2(g[d2]);
    float2 gf = __half22float2(g[(DM>>1)+d2]);
    float2 gu = __half22float2(g[DM+d2]);
    float2 go = __half22float2(g[((3*DM)>>1)+d2]);
    long ist = ((long)cmb*NT + n)*DM + d;
    float2 cp = *reinterpret_cast<const float2*>(&s_c[ist]);
    float2 cn, hn;
    cn.x = sigf(gf.x)*cp.x + sigf(gi.x)*tanhf(gu.x);
    cn.y = sigf(gf.y)*cp.y + sigf(gi.y)*tanhf(gu.y);
    hn.x = sigf(go.x)*tanhf(cn.x);
    hn.y = sigf(go.y)*tanhf(cn.y);
    if (cmb == 1){
        int kk = 15 - s;
        bool m = kk < s_len[n];
        if (m){
            *reinterpret_cast<float2*>(&s_c[ist]) = cn;
            *reinterpret_cast<__half2*>(&s_h16[ist]) = __floats2half2_rn(hn.x, hn.y);
        }
        __half2 yv = m ? __floats2half2_rn(hn.x, hn.y) : __floats2half2_rn(0.f, 0.f);
        *reinterpret_cast<__half2*>(&s_ycat016[((long)n*KC+kk)*(2*DM) + DM + d]) = yv;
    } else {
        *reinterpret_cast<float2*>(&s_c[ist]) = cn;
        *reinterpret_cast<__half2*>(&s_h16[ist]) = __floats2half2_rn(hn.x, hn.y);
        if (cmb==0)
            *reinterpret_cast<__half2*>(&s_ycat016[((long)n*KC+s)*(2*DM) + d]) = __floats2half2_rn(hn.x, hn.y);
        else if (s == s_len[n]-1)
            *reinterpret_cast<__half2*>(&s_ylcat16[((long)(cmb-2)*NT+n)*(2*DM) + d]) = __floats2half2_rn(hn.x, hn.y);
    }
}

__global__ void gates_last(const float* __restrict__ c0){
    long i = (long)blockIdx.x*blockDim.x + threadIdx.x;
    if (i >= 3L*NT*(DM/2)) return;
    int jb = (int)(i/((long)NT*(DM/2)));
    long nd = i%((long)NT*(DM/2));
    int n = (int)(nd/(DM/2)), d2 = (int)(nd%(DM/2));
    int d = d2*2;
    const __half2* g = (const __half2*)(s_gB16 + (long)jb*NT*GD + (long)n*GD);
    float2 gi = __half22float2(g[d2]);
    float2 gf = __half22float2(g[(DM>>1)+d2]);
    float2 gu = __half22float2(g[DM+d2]);
    float2 go = __half22float2(g[((3*DM)>>1)+d2]);
    float2 cp = *reinterpret_cast<const float2*>(&c0[(jb+1)*DM+d]);
    float2 hn;
    float cnx = sigf(gf.x)*cp.x + sigf(gi.x)*tanhf(gu.x);
    float cny = sigf(gf.y)*cp.y + sigf(gi.y)*tanhf(gu.y);
    hn.x = sigf(go.x)*tanhf(cnx);
    hn.y = sigf(go.y)*tanhf(cny);
    *reinterpret_cast<__half2*>(&s_ylcat16[((long)jb*NT+n)*(2*DM) + DM + d]) = __floats2half2_rn(hn.x, hn.y);
}

__global__ void final_k(float* __restrict__ out){
    int n = blockIdx.x, d = threadIdx.x;
    float wf = s_Wx[(long)n*GD + d];
    float wi = s_Wx[(long)n*GD + DM + d];
    float wu = s_Wx[(long)n*GD + 2*DM + d];
    float wo = s_Wx[(long)n*GD + 3*DM + d];
    int len = s_len[n];
    float bf = 0.f;
    for (int k=0;k<len;k++){
        float y  = __half2float(s_ys016[((long)n*KC+k)*DM + d]);
        float cc = s_cseq[((long)n*KC+k)*DM + d];
        bf += sigf(wf + y) * cc;
    }
    float bi = sigf (__half2float(s_ysl16[0L*NT*DM + (long)n*DM + d]) + wi);
    float bu = tanhf(__half2float(s_ysl16[1L*NT*DM + (long)n*DM + d]) + wu);
    float bo = sigf (__half2float(s_ysl16[2L*NT*DM + (long)n*DM + d]) + wo);
    float ncv = bi*bu + bf;
    float nhv = bo*tanhf(ncv);
    out[(long)n*DM + d] = nhv;
    out[(long)NT*DM + (long)n*DM + d] = ncv;
}

// =============================================================================
extern "C" void kernel_launch(void* const* d_in, const int* in_sizes, int n_in,
                              void* d_out, int out_size) {
    const float* x        = (const float*)d_in[0];
    const float* h_tensor = (const float*)d_in[1];
    const float* c_tensor = (const float*)d_in[2];
    const int*   indice   = (const int*)  d_in[3];
    const float* W_w      = (const float*)d_in[4];
    const float* W_b      = (const float*)d_in[5];
    const float* h0       = (const float*)d_in[6];
    const float* c0       = (const float*)d_in[7];
    const float* Wih      = (const float*)d_in[8];
    const float* Whh      = (const float*)d_in[9];
    const float* bih      = (const float*)d_in[10];
    const float* bhh      = (const float*)d_in[11];
    const float* fc       = (const float*)d_in[12];
    float* out = (float*)d_out;

    __half *p_x16,*p_xseq16,*p_xlast16,*p_Wih5h,*p_Whh5h,*p_WihBh,*p_Wwh,*p_fch,
           *p_h16,*p_ycat016,*p_ylcat16,*p_Gx16,*p_g16,*p_gB16,*p_ys016,*p_ysl16;
    float *p_b5,*p_hb,*p_Wx;
    cudaGetSymbolAddress((void**)&p_x16,     s_x16);
    cudaGetSymbolAddress((void**)&p_xseq16,  s_xseq16);
    cudaGetSymbolAddress((void**)&p_xlast16, s_xlast16);
    cudaGetSymbolAddress((void**)&p_Wih5h,   s_Wih5h);
    cudaGetSymbolAddress((void**)&p_Whh5h,   s_Whh5h);
    cudaGetSymbolAddress((void**)&p_WihBh,   s_WihBh);
    cudaGetSymbolAddress((void**)&p_Wwh,     s_Wwh);
    cudaGetSymbolAddress((void**)&p_fch,     s_fch);
    cudaGetSymbolAddress((void**)&p_h16,     s_h16);
    cudaGetSymbolAddress((void**)&p_ycat016, s_ycat016);
    cudaGetSymbolAddress((void**)&p_ylcat16, s_ylcat16);
    cudaGetSymbolAddress((void**)&p_Gx16,    s_Gx16);
    cudaGetSymbolAddress((void**)&p_g16,     s_g16);
    cudaGetSymbolAddress((void**)&p_gB16,    s_gB16);
    cudaGetSymbolAddress((void**)&p_ys016,   s_ys016);
    cudaGetSymbolAddress((void**)&p_ysl16,   s_ysl16);
    cudaGetSymbolAddress((void**)&p_b5,      s_b5);
    cudaGetSymbolAddress((void**)&p_hb,      s_hb);
    cudaGetSymbolAddress((void**)&p_Wx,      s_Wx);
    (void)in_sizes; (void)n_in; (void)out_size;

    const int SMEM_SZ = 6*AB_U32*4;       // 61440 bytes (3-stage A+B ring)
    cudaFuncSetAttribute(gemm_h, cudaFuncAttributeMaxDynamicSharedMemorySize, SMEM_SZ);

    // 1) pack/convert weights, convert x, gather, meta
    prep_weights<<<1024,256>>>(Wih,Whh,bih,bhh,W_w,fc);
    conv_x<<<(int)(((long)NT*DM+255)/256),256>>>(x);
    gather_k<<<(int)(((long)NT*KC*(DM/4))/256),256>>>(h_tensor,c_tensor,indice);
    meta_k<<<512,256>>>(indice,h0,c0);

    // 2) Wx = x @ W_w^T + W_b        [4096,1024] -> fp32 (read by final_k)
    gemm_h<<<dim3(GD/128, NT/128, 1),256,SMEM_SZ>>>(
        p_x16,0, p_Wwh,0, W_b,0, (const __half*)0,0,0,
        p_Wx,(__half*)0,0,GD, NT,GD,DM, -1,0);

    // 3) Gx = xseq @ Wih5^T + b5 -> fp16, time-reversed rows for combo 1 (z==1)
    gemm_h<<<dim3(GD/128, (NT*KC)/128, NCMB),256,SMEM_SZ>>>(
        p_xseq16,0, p_Wih5h,(long)GD*DM, p_b5,(long)GD, (const __half*)0,0,0,
        (float*)0,p_Gx16,(long)NT*KC*GD,GD, NT*KC,GD,DM, 1,15);

    // 4) one-step backward prep
    hb_k<<<12,256>>>(h0,Whh,bih,bhh);
    xlast_k<<<(int)(((long)NT*(DM/8)+255)/256),256>>>();

    // 5) the 16 recurrence steps (5 combos batched per step)
    long gatesN = (long)NCMB*NT*(DM/2);
    for (int s = 0; s < KC; s++){
        gemm_h<<<dim3(GD/128, NT/128, NCMB),256,SMEM_SZ>>>(
            p_h16,(long)NT*DM, p_Whh5h,(long)GD*DM, (const float*)0,0,
            p_Gx16 + (long)s*GD, (long)NT*KC*GD, KC*GD,
            (float*)0,p_g16,(long)NT*GD,GD, NT,GD,DM, -1,0);
        gates_step<<<(int)((gatesN+255)/256),256>>>(s);
    }

    // 6) backward one-step for j=1..3 -> fp16
    gemm_h<<<dim3(GD/128, NT/128, 3),256,SMEM_SZ>>>(
        p_xlast16,0, p_WihBh,(long)GD*DM, p_hb,(long)GD, (const __half*)0,0,0,
        (float*)0,p_gB16,(long)NT*GD,GD, NT,GD,DM, -1,0);
    gates_last<<<(int)((3L*NT*(DM/2)+255)/256),256>>>(c0);

    // 7) fc projections -> fp16
    gemm_h<<<dim3(DM/128, (NT*KC)/128, 1),256,SMEM_SZ>>>(
        p_ycat016,0, p_fch,0, (const float*)0,0, (const __half*)0,0,0,
        (float*)0,p_ys016,0,DM, NT*KC,DM,2*DM, -1,0);
    gemm_h<<<dim3(DM/128, NT/128, 3),256,SMEM_SZ>>>(
        p_ylcat16,(long)NT*2*DM, p_fch + (long)DM*2*DM,(long)DM*2*DM,
        (const float*)0,0, (const __half*)0,0,0,
        (float*)0,p_ysl16,(long)NT*DM,DM, NT,DM,2*DM, -1,0);

    // 8) final combine -> (new_h, new_c)
    final_k<<<NT,DM>>>(out);
}

// round 8
// speedup vs baseline: 2.4547x; 1.0178x over previous
#include <cuda_runtime.h>
#include <cuda_fp16.h>
#include <math.h>
#include <stdint.h>

#define NT   4096      // trees
#define KC   16        // children
#define DM   256       // DOUT
#define GD   1024      // 4*DOUT
#define NCMB 5         // recurrent combos: (j0,f),(j0,b),(j1,f),(j2,f),(j3,f)

// ---------------- scratch (device globals; no allocations allowed) ----------
// fp16 GEMM operands (all tree-indexed arrays live in SORTED order)
__device__ __align__(16) __half s_x16   [(long)NT*DM];
__device__ __align__(16) __half s_xseq16[(long)NT*KC*DM];   // k-major: [k*NT+n][DM]
__device__ __align__(16) __half s_xlast16[(long)NT*DM];
__device__ __align__(16) __half s_Wih5h [(long)NCMB*GD*DM];
__device__ __align__(16) __half s_Whh5h [(long)NCMB*GD*DM];
__device__ __align__(16) __half s_WihBh [3L*GD*DM];
__device__ __align__(16) __half s_Wwh   [(long)GD*DM];
__device__ __align__(16) __half s_fch   [4L*DM*2*DM];
__device__ __align__(16) __half s_h16   [(long)NCMB*NT*DM];
__device__ __align__(16) __half s_ycat016[(long)NT*KC*2*DM]; // k-major rows
__device__ __align__(16) __half s_ylcat16[3L*NT*2*DM];
// fp16 intermediates
__device__ __align__(16) __half s_Gx16  [(long)NCMB*NT*KC*GD]; // k-major rows
__device__ __align__(16) __half s_g16   [(long)NCMB*NT*GD];
__device__ __align__(16) __half s_gB16  [3L*NT*GD];
__device__ __align__(16) __half s_ys016 [(long)NT*KC*DM];      // k-major rows
__device__ __align__(16) __half s_ysl16 [3L*NT*DM];
// fp32 state + sort metadata
__device__ float s_cseq [(long)NT*KC*DM];
__device__ int   s_len  [NT];        // sorted (descending)
__device__ int   s_ord  [NT];        // sorted slot -> original tree id
__device__ int   s_lenOrig[NT];
__device__ int   s_cntF [17];        // cntF[s] = #trees with len > s
__device__ float s_b5   [NCMB*GD];
__device__ float s_hb   [3*GD];
__device__ float s_c    [(long)NCMB*NT*DM];
__device__ float s_Wx   [(long)NT*GD];

__device__ __forceinline__ float sigf(float x){ return 1.f/(1.f+expf(-x)); }

__device__ __forceinline__ void mma_f16(float4& c,
        uint32_t a0, uint32_t a1, uint32_t a2, uint32_t a3,
        uint32_t b0, uint32_t b1){
    asm volatile(
        "mma.sync.aligned.m16n8k16.row.col.f32.f16.f16.f32 "
        "{%0,%1,%2,%3}, {%4,%5,%6,%7}, {%8,%9}, {%0,%1,%2,%3};"
        : "+f"(c.x), "+f"(c.y), "+f"(c.z), "+f"(c.w)
        : "r"(a0), "r"(a1), "r"(a2), "r"(a3), "r"(b0), "r"(b1));
}

// ---------------- sort trees by length (descending, counting sort) ----------
__global__ void sort_k(const int* __restrict__ indice){
    __shared__ int hist[17];
    __shared__ int binCur[17];
    int tid = threadIdx.x;
    if (tid < 17) hist[tid]=0;
    __syncthreads();
    for (int n=tid; n<NT; n+=blockDim.x){
        int l=0;
        #pragma unroll
        for (int k=0;k<KC;k++) if (indice[n*KC+k]!=-1) l++;
        s_lenOrig[n]=l;
        atomicAdd(&hist[l],1);
    }
    __syncthreads();
    if (tid==0){
        int run=0;
        for (int l=16;l>=1;l--){ binCur[l]=run; run+=hist[l]; }
        int c=0;
        s_cntF[16]=0;
        for (int s=15;s>=0;s--){ c += hist[s+1]; s_cntF[s]=c; }
    }
    __syncthreads();
    for (int n=tid; n<NT; n+=blockDim.x){
        int l=s_lenOrig[n];
        int pos=atomicAdd(&binCur[l],1);
        s_ord[pos]=n;
        s_len[pos]=l;
    }
}

// ---------------- prep: pack + convert weights to fp16 ----------------------
__global__ void prep_weights(const float* __restrict__ Wih, const float* __restrict__ Whh,
                             const float* __restrict__ bih, const float* __restrict__ bhh,
                             const float* __restrict__ W_w, const float* __restrict__ fc){
    const int map5[5]={0,1,2,4,6};
    const int mapB[3]={3,5,7};
    long idx = (long)blockIdx.x*blockDim.x + threadIdx.x;
    long stride = (long)gridDim.x*blockDim.x;
    for (long i=idx; i<(long)NCMB*GD*DM; i+=stride){
        int cmb = (int)(i/((long)GD*DM)); long r = i%((long)GD*DM);
        s_Wih5h[i]=__float2half(Wih[(long)map5[cmb]*GD*DM + r]);
        s_Whh5h[i]=__float2half(Whh[(long)map5[cmb]*GD*DM + r]);
    }
    for (long i=idx; i<3L*GD*DM; i+=stride){
        int jb = (int)(i/((long)GD*DM)); long r = i%((long)GD*DM);
        s_WihBh[i]=__float2half(Wih[(long)mapB[jb]*GD*DM + r]);
    }
    for (long i=idx; i<(long)GD*DM; i+=stride)
        s_Wwh[i]=__float2half(W_w[i]);
    for (long i=idx; i<4L*DM*2*DM; i+=stride)
        s_fch[i]=__float2half(fc[i]);
    for (long i=idx; i<(long)NCMB*GD; i+=stride){
        int cmb=(int)(i/GD); int o=(int)(i%GD);
        s_b5[i]=bih[map5[cmb]*GD+o]+bhh[map5[cmb]*GD+o];
    }
}

// ---------------- convert x to fp16 (sorted rows) ----------------------------
__global__ void conv_x(const float* __restrict__ x){
    long i = (long)blockIdx.x*blockDim.x + threadIdx.x;   // float4 index
    if (i >= (long)NT*(DM/4)) return;
    int sn = (int)(i/(DM/4)); int d4 = (int)(i%(DM/4));
    int orig = s_ord[sn];
    float4 v = ((const float4*)x)[(long)orig*(DM/4)+d4];
    ((__half2*)s_x16)[((long)sn*DM + d4*4)>>1]     = __floats2half2_rn(v.x, v.y);
    ((__half2*)s_x16)[(((long)sn*DM + d4*4)>>1)+1] = __floats2half2_rn(v.z, v.w);
}

// ---------------- gather child states (sorted, xseq k-major) -----------------
__global__ void gather_k(const float* __restrict__ h_tensor,
                         const float* __restrict__ c_tensor,
                         const int*   __restrict__ indice){
    long i = (long)blockIdx.x*blockDim.x + threadIdx.x;
    if (i >= (long)NT*KC*(DM/4)) return;
    long nk = i / (DM/4);
    int  d4 = (int)(i % (DM/4));
    int sn = (int)(nk >> 4); int k = (int)(nk & 15);
    int orig = s_ord[sn];
    int id = indice[orig*KC+k]; if (id < 0) id = 0;
    float4 h = ((const float4*)h_tensor)[(long)id*(DM/4)+d4];
    ((float4*)s_cseq)[((long)sn*KC+k)*(DM/4)+d4] = ((const float4*)c_tensor)[(long)id*(DM/4)+d4];
    long xo = ((long)k*NT + sn)*DM + d4*4;
    ((__half2*)s_xseq16)[xo>>1]     = __floats2half2_rn(h.x, h.y);
    ((__half2*)s_xseq16)[(xo>>1)+1] = __floats2half2_rn(h.z, h.w);
}

// ---------------- initial states ----------------------------------------------
__global__ void meta_k(const float* __restrict__ h0, const float* __restrict__ c0){
    long idx = (long)blockIdx.x*blockDim.x + threadIdx.x;
    long stride = (long)gridDim.x*blockDim.x;
    const int jmap[5]={0,0,1,2,3};
    for (long i=idx; i<(long)NCMB*NT*DM; i+=stride){
        int cmb = (int)(i/((long)NT*DM)); int d = (int)(i%DM);
        s_h16[i] = __float2half(h0[jmap[cmb]*DM+d]);
        s_c[i]   = c0[jmap[cmb]*DM+d];
    }
}

__global__ void xlast_k(){
    long i = (long)blockIdx.x*blockDim.x + threadIdx.x;   // uint4 index (8 fp16)
    if (i >= (long)NT*(DM/8)) return;
    int sn = (int)(i/(DM/8)); int j = (int)(i%(DM/8));
    int last = s_len[sn]-1;
    ((uint4*)s_xlast16)[i] = ((const uint4*)s_xseq16)[((long)last*NT+sn)*(DM/8)+j];
}

__global__ void hb_k(const float* __restrict__ h0, const float* __restrict__ Whh,
                     const float* __restrict__ bih, const float* __restrict__ bhh){
    int idx = blockIdx.x*blockDim.x + threadIdx.x;
    if (idx >= 3*GD) return;
    int jb = idx/GD, o = idx%GD;
    int jd2 = 2*(jb+1)+1;
    const float* w = Whh + (long)jd2*GD*DM + (long)o*DM;
    const float* h = h0 + (jb+1)*DM;
    float acc=0.f;
    #pragma unroll 8
    for (int d=0; d<DM; d++) acc += h[d]*w[d];
    s_hb[idx] = acc + bih[jd2*GD+o] + bhh[jd2*GD+o];
}

// ---------------- fp16 mma.sync batched GEMM -----------------------------
// C = A @ B^T (+bias fp32)(+Cadd fp16); C fp32 (CF) or fp16 (CH).
// exitKind 1: rows are k-major slices of 4096; skip tile if within-slice row
//             >= cnt[k] (or cnt[15-k] for z==xorZ). exitKind 2: skip if
//             brow >= cnt[stepS] (z==1 uses cnt[15-stepS]).
#define STR2 20                       // u32 per smem row (16 data + 4 pad)
#define AB_U32 (128*STR2)
#define ABUF(b) ((b)*AB_U32)
#define BBUF(b) (3*AB_U32 + (b)*AB_U32)

__global__ void __launch_bounds__(256,2) gemm_h(
    const __half* __restrict__ A, long aBatch,
    const __half* __restrict__ B, long bBatch,
    const float* __restrict__ bias, long biasBatch,
    const __half* __restrict__ CaddH, long caddBatch, int caddRow,
    float* __restrict__ CF, __half* __restrict__ CH, long cBatch, int cRow,
    int M, int N, int K, int xorZ, int xorVal,
    const int* __restrict__ exCnt, int exitKind, int stepS)
{
    int z = blockIdx.z;
    long brow = (long)blockIdx.y * 128;
    if (exitKind == 1){
        int k = (int)(brow >> 12);
        int w = (int)(brow & 4095);
        int lim = (z==xorZ) ? exCnt[15-k] : exCnt[k];
        if (w >= lim) return;
    } else if (exitKind == 2){
        int lim = (z==1) ? exCnt[15-stepS] : exCnt[stepS];
        if (brow >= lim) return;
    }

    extern __shared__ uint32_t sm[];
    uint32_t sbase;
    asm("{ .reg .u64 t; cvta.to.shared.u64 t, %1; cvt.u32.u64 %0, t; }"
        : "=r"(sbase) : "l"(sm));
    int tid = threadIdx.x;
    int wid = tid >> 5;
    int lane = tid & 31;
    int g = lane >> 2, t = lane & 3;
    int wr = wid >> 2, wc = wid & 3;

    const __half* Ab = A + (long)z*aBatch;
    const __half* Bb = B + (long)z*bBatch;
    int rxor = (z==xorZ) ? xorVal : 0;
    long bcol = (long)blockIdx.x * 128;

    int lrow4 = tid >> 2;         // 0..63
    int lq    = tid & 3;          // 16B quarter of a 64B row

    #define PREFETCH(ch, buf) do {                                                \
        long kb = (long)(ch)*32;                                                  \
        _Pragma("unroll")                                                         \
        for (int l=0;l<2;l++){                                                    \
            int r = lrow4 + l*64;                                                 \
            long gr = (brow + r) ^ rxor;                                          \
            uint32_t da = sbase + (ABUF(buf) + r*STR2)*4 + lq*16;                 \
            asm volatile("cp.async.cg.shared.global [%0],[%1],16;"                \
                         :: "r"(da), "l"(Ab + gr*K + kb + lq*8));                 \
            uint32_t db = sbase + (BBUF(buf) + r*STR2)*4 + lq*16;                 \
            asm volatile("cp.async.cg.shared.global [%0],[%1],16;"                \
                         :: "r"(db), "l"(Bb + (bcol + r)*K + kb + lq*8));         \
        }                                                                         \
        asm volatile("cp.async.commit_group;");                                   \
    } while(0)

    float4 acc[4][4];
    #pragma unroll
    for (int i=0;i<4;i++)
        #pragma unroll
        for (int j=0;j<4;j++) acc[i][j] = make_float4(0.f,0.f,0.f,0.f);

    int nCh = K >> 5;
    PREFETCH(0, 0);
    if (nCh > 1) PREFETCH(1, 1);

    for (int i = 0; i < nCh; i++){
        if (i + 1 < nCh) asm volatile("cp.async.wait_group 1;" ::: "memory");
        else             asm volatile("cp.async.wait_group 0;" ::: "memory");
        __syncthreads();
        int cb = i % 3;
        const uint32_t* sA = &sm[ABUF(cb)];
        const uint32_t* sB = &sm[BBUF(cb)];
        #pragma unroll
        for (int ks = 0; ks < 2; ks++){
            int k0 = ks*8;
            uint32_t af[4][4], bf[4][2];
            #pragma unroll
            for (int mt=0; mt<4; mt++){
                int ar = wr*64 + mt*16 + g;
                af[mt][0] = sA[ar*STR2 + k0 + t];
                af[mt][1] = sA[(ar+8)*STR2 + k0 + t];
                af[mt][2] = sA[ar*STR2 + k0 + t + 4];
                af[mt][3] = sA[(ar+8)*STR2 + k0 + t + 4];
            }
            #pragma unroll
            for (int nt=0; nt<4; nt++){
                int bn = wc*32 + nt*8 + g;
                bf[nt][0] = sB[bn*STR2 + k0 + t];
                bf[nt][1] = sB[bn*STR2 + k0 + t + 4];
            }
            #pragma unroll
            for (int mt=0; mt<4; mt++)
                #pragma unroll
                for (int nt=0; nt<4; nt++)
                    mma_f16(acc[mt][nt], af[mt][0],af[mt][1],af[mt][2],af[mt][3],
                            bf[nt][0], bf[nt][1]);
        }
        if (i + 2 < nCh) PREFETCH(i + 2, (i + 2) % 3);
    }

    // ---- epilogue ----
    const float*  biasb = bias  ? bias  + (long)z*biasBatch : (const float*)0;
    const __half* caddb = CaddH ? CaddH + (long)z*caddBatch : (const __half*)0;
    #pragma unroll
    for (int mt=0; mt<4; mt++){
        long row0 = brow + wr*64 + mt*16 + g;
        #pragma unroll
        for (int nt=0; nt<4; nt++){
            long col = bcol + wc*32 + nt*8 + 2*t;
            float2 v0 = make_float2(acc[mt][nt].x, acc[mt][nt].y);
            float2 v1 = make_float2(acc[mt][nt].z, acc[mt][nt].w);
            if (biasb){
                v0.x += biasb[col];   v0.y += biasb[col+1];
                v1.x += biasb[col];   v1.y += biasb[col+1];
            }
            if (caddb){
                float2 a0 = __half22float2(*reinterpret_cast<const __half2*>(&caddb[row0*caddRow + col]));
                float2 a1 = __half22float2(*reinterpret_cast<const __half2*>(&caddb[(row0+8)*caddRow + col]));
                v0.x += a0.x; v0.y += a0.y;
                v1.x += a1.x; v1.y += a1.y;
            }
            if (CH){
                __half* Cb = CH + (long)z*cBatch;
                *reinterpret_cast<__half2*>(&Cb[row0*cRow + col])     = __floats2half2_rn(v0.x, v0.y);
                *reinterpret_cast<__half2*>(&Cb[(row0+8)*cRow + col]) = __floats2half2_rn(v1.x, v1.y);
            } else {
                float* Cb = CF + (long)z*cBatch;
                *reinterpret_cast<float2*>(&Cb[row0*cRow + col])     = v0;
                *reinterpret_cast<float2*>(&Cb[(row0+8)*cRow + col]) = v1;
            }
        }
    }
    #undef PREFETCH
}

// ---------------- gates + state update per recurrence step (half2) ----------
__global__ void gates_step(int s){
    long i = (long)blockIdx.x*blockDim.x + threadIdx.x;
    if (i >= (long)NCMB*NT*(DM/2)) return;
    int cmb = (int)(i/((long)NT*(DM/2)));
    long nd = i%((long)NT*(DM/2));
    int n = (int)(nd/(DM/2)), d2 = (int)(nd%(DM/2));
    int lim = (cmb==1) ? s_cntF[15-s] : s_cntF[s];
    if (n >= lim) return;                 // inactive tree: state frozen
    int d = d2*2;
    const __half2* g = (const __half2*)(s_g16 + (long)cmb*NT*GD + (long)n*GD);
    float2 gi = __half22float2(g[d2]);
    float2 gf = __half22float2(g[(DM>>1)+d2]);
    float2 gu = __half22float2(g[DM+d2]);
    float2 go = __half22float2(g[((3*DM)>>1)+d2]);
    long ist = ((long)cmb*NT + n)*DM + d;
    float2 cp = *reinterpret_cast<const float2*>(&s_c[ist]);
    float2 cn, hn;
    cn.x = sigf(gf.x)*cp.x + sigf(gi.x)*tanhf(gu.x);
    cn.y = sigf(gf.y)*cp.y + sigf(gi.y)*tanhf(gu.y);
    hn.x = sigf(go.x)*tanhf(cn.x);
    hn.y = sigf(go.y)*tanhf(cn.y);
    *reinterpret_cast<float2*>(&s_c[ist]) = cn;
    *reinterpret_cast<__half2*>(&s_h16[ist]) = __floats2half2_rn(hn.x, hn.y);
    if (cmb == 1){
        int kk = 15 - s;                  // active => kk < len
        *reinterpret_cast<__half2*>(&s_ycat016[((long)kk*NT+n)*(2*DM) + DM + d]) = __floats2half2_rn(hn.x, hn.y);
    } else if (cmb == 0){
        *reinterpret_cast<__half2*>(&s_ycat016[((long)s*NT+n)*(2*DM) + d]) = __floats2half2_rn(hn.x, hn.y);
    } else {
        if (s == s_len[n]-1)
            *reinterpret_cast<__half2*>(&s_ylcat16[((long)(cmb-2)*NT+n)*(2*DM) + d]) = __floats2half2_rn(hn.x, hn.y);
    }
}

__global__ void gates_last(const float* __restrict__ c0){
    long i = (long)blockIdx.x*blockDim.x + threadIdx.x;
    if (i >= 3L*NT*(DM/2)) return;
    int jb = (int)(i/((long)NT*(DM/2)));
    long nd = i%((long)NT*(DM/2));
    int n = (int)(nd/(DM/2)), d2 = (int)(nd%(DM/2));
    int d = d2*2;
    const __half2* g = (const __half2*)(s_gB16 + (long)jb*NT*GD + (long)n*GD);
    float2 gi = __half22float2(g[d2]);
    float2 gf = __half22float2(g[(DM>>1)+d2]);
    float2 gu = __half22float2(g[DM+d2]);
    float2 go = __half22float2(g[((3*DM)>>1)+d2]);
    float2 cp = *reinterpret_cast<const float2*>(&c0[(jb+1)*DM+d]);
    float2 hn;
    float cnx = sigf(gf.x)*cp.x + sigf(gi.x)*tanhf(gu.x);
    float cny = sigf(gf.y)*cp.y + sigf(gi.y)*tanhf(gu.y);
    hn.x = sigf(go.x)*tanhf(cnx);
    hn.y = sigf(go.y)*tanhf(cny);
    *reinterpret_cast<__half2*>(&s_ylcat16[((long)jb*NT+n)*(2*DM) + DM + d]) = __floats2half2_rn(hn.x, hn.y);
}

__global__ void final_k(float* __restrict__ out){
    int n = blockIdx.x, d = threadIdx.x;   // n = sorted slot
    int orig = s_ord[n];
    float wf = s_Wx[(long)n*GD + d];
    float wi = s_Wx[(long)n*GD + DM + d];
    float wu = s_Wx[(long)n*GD + 2*DM + d];
    float wo = s_Wx[(long)n*GD + 3*DM + d];
    int len = s_len[n];
    float bf = 0.f;
    for (int k=0;k<len;k++){
        float y  = __half2float(s_ys016[((long)k*NT+n)*DM + d]);
        float cc = s_cseq[((long)n*KC+k)*DM + d];
        bf += sigf(wf + y) * cc;
    }
    float bi = sigf (__half2float(s_ysl16[0L*NT*DM + (long)n*DM + d]) + wi);
    float bu = tanhf(__half2float(s_ysl16[1L*NT*DM + (long)n*DM + d]) + wu);
    float bo = sigf (__half2float(s_ysl16[2L*NT*DM + (long)n*DM + d]) + wo);
    float ncv = bi*bu + bf;
    float nhv = bo*tanhf(ncv);
    out[(long)orig*DM + d] = nhv;
    out[(long)NT*DM + (long)orig*DM + d] = ncv;
}

// =============================================================================
extern "C" void kernel_launch(void* const* d_in, const int* in_sizes, int n_in,
                              void* d_out, int out_size) {
    const float* x        = (const float*)d_in[0];
    const float* h_tensor = (const float*)d_in[1];
    const float* c_tensor = (const float*)d_in[2];
    const int*   indice   = (const int*)  d_in[3];
    const float* W_w      = (const float*)d_in[4];
    const float* W_b      = (const float*)d_in[5];
    const float* h0       = (const float*)d_in[6];
    const float* c0       = (const float*)d_in[7];
    const float* Wih      = (const float*)d_in[8];
    const float* Whh      = (const float*)d_in[9];
    const float* bih      = (const float*)d_in[10];
    const float* bhh      = (const float*)d_in[11];
    const float* fc       = (const float*)d_in[12];
    float* out = (float*)d_out;

    __half *p_x16,*p_xseq16,*p_xlast16,*p_Wih5h,*p_Whh5h,*p_WihBh,*p_Wwh,*p_fch,
           *p_h16,*p_ycat016,*p_ylcat16,*p_Gx16,*p_g16,*p_gB16,*p_ys016,*p_ysl16;
    float *p_b5,*p_hb,*p_Wx;
    int *p_cntF;
    cudaGetSymbolAddress((void**)&p_x16,     s_x16);
    cudaGetSymbolAddress((void**)&p_xseq16,  s_xseq16);
    cudaGetSymbolAddress((void**)&p_xlast16, s_xlast16);
    cudaGetSymbolAddress((void**)&p_Wih5h,   s_Wih5h);
    cudaGetSymbolAddress((void**)&p_Whh5h,   s_Whh5h);
    cudaGetSymbolAddress((void**)&p_WihBh,   s_WihBh);
    cudaGetSymbolAddress((void**)&p_Wwh,     s_Wwh);
    cudaGetSymbolAddress((void**)&p_fch,     s_fch);
    cudaGetSymbolAddress((void**)&p_h16,     s_h16);
    cudaGetSymbolAddress((void**)&p_ycat016, s_ycat016);
    cudaGetSymbolAddress((void**)&p_ylcat16, s_ylcat16);
    cudaGetSymbolAddress((void**)&p_Gx16,    s_Gx16);
    cudaGetSymbolAddress((void**)&p_g16,     s_g16);
    cudaGetSymbolAddress((void**)&p_gB16,    s_gB16);
    cudaGetSymbolAddress((void**)&p_ys016,   s_ys016);
    cudaGetSymbolAddress((void**)&p_ysl16,   s_ysl16);
    cudaGetSymbolAddress((void**)&p_b5,      s_b5);
    cudaGetSymbolAddress((void**)&p_hb,      s_hb);
    cudaGetSymbolAddress((void**)&p_Wx,      s_Wx);
    cudaGetSymbolAddress((void**)&p_cntF,    s_cntF);
    (void)in_sizes; (void)n_in; (void)out_size;

    const int SMEM_SZ = 6*AB_U32*4;       // 61440 bytes (3-stage A+B ring)
    cudaFuncSetAttribute(gemm_h, cudaFuncAttributeMaxDynamicSharedMemorySize, SMEM_SZ);

    // 1) sort by length, pack/convert weights, convert x, gather, init states
    sort_k<<<1,256>>>(indice);
    prep_weights<<<1024,256>>>(Wih,Whh,bih,bhh,W_w,fc);
    conv_x<<<(int)(((long)NT*(DM/4)+255)/256),256>>>(x);
    gather_k<<<(int)(((long)NT*KC*(DM/4))/256),256>>>(h_tensor,c_tensor,indice);
    meta_k<<<512,256>>>(h0,c0);

    // 2) Wx = x @ W_w^T + W_b   (sorted rows) -> fp32
    gemm_h<<<dim3(GD/128, NT/128, 1),256,SMEM_SZ>>>(
        p_x16,0, p_Wwh,0, W_b,0, (const __half*)0,0,0,
        p_Wx,(__half*)0,0,GD, NT,GD,DM, -1,0, (const int*)0,0,0);

    // 3) Gx = xseq @ Wih5^T + b5 -> fp16 (k-major rows, skip k>=len)
    gemm_h<<<dim3(GD/128, (NT*KC)/128, NCMB),256,SMEM_SZ>>>(
        p_xseq16,0, p_Wih5h,(long)GD*DM, p_b5,(long)GD, (const __half*)0,0,0,
        (float*)0,p_Gx16,(long)NT*KC*GD,GD, NT*KC,GD,DM, 1,(15<<12), p_cntF,1,0);

    // 4) one-step backward prep
    hb_k<<<12,256>>>(h0,Whh,bih,bhh);
    xlast_k<<<(int)(((long)NT*(DM/8)+255)/256),256>>>();

    // 5) the 16 recurrence steps (5 combos batched; prefix-active rows only)
    long gatesN = (long)NCMB*NT*(DM/2);
    for (int s = 0; s < KC; s++){
        gemm_h<<<dim3(GD/128, NT/128, NCMB),256,SMEM_SZ>>>(
            p_h16,(long)NT*DM, p_Whh5h,(long)GD*DM, (const float*)0,0,
            p_Gx16 + (long)s*NT*GD, (long)NT*KC*GD, GD,
            (float*)0,p_g16,(long)NT*GD,GD, NT,GD,DM, -1,0, p_cntF,2,s);
        gates_step<<<(int)((gatesN+255)/256),256>>>(s);
    }

    // 6) backward one-step for j=1..3 -> fp16
    gemm_h<<<dim3(GD/128, NT/128, 3),256,SMEM_SZ>>>(
        p_xlast16,0, p_WihBh,(long)GD*DM, p_hb,(long)GD, (const __half*)0,0,0,
        (float*)0,p_gB16,(long)NT*GD,GD, NT,GD,DM, -1,0, (const int*)0,0,0);
    gates_last<<<(int)((3L*NT*(DM/2)+255)/256),256>>>(c0);

    // 7) fc projections -> fp16 (ycat0 rows k-major; skip k>=len)
    gemm_h<<<dim3(DM/128, (NT*KC)/128, 1),256,SMEM_SZ>>>(
        p_ycat016,0, p_fch,0, (const float*)0,0, (const __half*)0,0,0,
        (float*)0,p_ys016,0,DM, NT*KC,DM,2*DM, -1,0, p_cntF,1,0);
    gemm_h<<<dim3(DM/128, NT/128, 3),256,SMEM_SZ>>>(
        p_ylcat16,(long)NT*2*DM, p_fch + (long)DM*2*DM,(long)DM*2*DM,
        (const float*)0,0, (const __half*)0,0,0,
        (float*)0,p_ysl16,(long)NT*DM,DM, NT,DM,2*DM, -1,0, (const int*)0,0,0);

    // 8) final combine -> (new_h, new_c), un-permuted
    final_k<<<NT,DM>>>(out);
}

// round 9
// speedup vs baseline: 3.8428x; 1.5655x over previous
#include <cuda_runtime.h>
#include <cuda_fp16.h>
#include <math.h>
#include <stdint.h>

#define NT   4096      // trees
#define KC   16        // children
#define DM   256       // DOUT
#define GD   1024      // 4*DOUT
#define NCMB 5         // recurrent combos: (j0,f),(j0,b),(j1,f),(j2,f),(j3,f)
#define NCTA 296       // persistent grid: 2 CTAs x 148 SMs

// ---------------- scratch (device globals; no allocations allowed) ----------
__device__ __align__(16) __half s_x16   [(long)NT*DM];
__device__ __align__(16) __half s_xseq16[(long)NT*KC*DM];   // k-major: [k*NT+n][DM]
__device__ __align__(16) __half s_xlast16[(long)NT*DM];
__device__ __align__(16) __half s_Wih5h [(long)NCMB*GD*DM]; // gate-interleaved
__device__ __align__(16) __half s_Whh5h [(long)NCMB*GD*DM]; // gate-interleaved
__device__ __align__(16) __half s_WihBh [3L*GD*DM];         // original order
__device__ __align__(16) __half s_Wwh   [(long)GD*DM];
__device__ __align__(16) __half s_fch   [4L*DM*2*DM];
__device__ __align__(16) __half s_h16   [2L*NCMB*NT*DM];    // double-buffered
__device__ __align__(16) __half s_ycat016[(long)NT*KC*2*DM]; // k-major rows
__device__ __align__(16) __half s_ylcat16[3L*NT*2*DM];
__device__ __align__(16) __half s_Gx16  [(long)NCMB*NT*KC*GD]; // k-major, interleaved cols
__device__ __align__(16) __half s_gB16  [3L*NT*GD];
__device__ __align__(16) __half s_ys016 [(long)NT*KC*DM];
__device__ __align__(16) __half s_ysl16 [3L*NT*DM];
__device__ float s_cseq [(long)NT*KC*DM];
__device__ int   s_len  [NT];        // sorted (descending)
__device__ int   s_ord  [NT];
__device__ int   s_lenOrig[NT];
__device__ int   s_cntF [17];        // cntF[s] = #trees with len > s
__device__ float s_b5   [NCMB*GD];   // gate-interleaved
__device__ float s_hb   [3*GD];
__device__ float s_c    [(long)NCMB*NT*DM];
__device__ float s_Wx   [(long)NT*GD];
__device__ int      g_barCnt;
__device__ unsigned g_barGen;

__device__ __forceinline__ float sigf(float x){ return 1.f/(1.f+expf(-x)); }

__device__ __forceinline__ void mma_f16(float4& c,
        uint32_t a0, uint32_t a1, uint32_t a2, uint32_t a3,
        uint32_t b0, uint32_t b1){
    asm volatile(
        "mma.sync.aligned.m16n8k16.row.col.f32.f16.f16.f32 "
        "{%0,%1,%2,%3}, {%4,%5,%6,%7}, {%8,%9}, {%0,%1,%2,%3};"
        : "+f"(c.x), "+f"(c.y), "+f"(c.z), "+f"(c.w)
        : "r"(a0), "r"(a1), "r"(a2), "r"(a3), "r"(b0), "r"(b1));
}

__device__ __forceinline__ void grid_barrier(){
    __syncthreads();
    if (threadIdx.x == 0){
        unsigned gen = atomicAdd(&g_barGen, 0u);
        __threadfence();
        if (atomicAdd(&g_barCnt, 1) == NCTA-1){
            g_barCnt = 0;
            __threadfence();
            atomicAdd(&g_barGen, 1u);
        } else {
            while (atomicAdd(&g_barGen, 0u) == gen) __nanosleep(64);
        }
        __threadfence();
    }
    __syncthreads();
}

// ---------------- sort trees by length (descending, counting sort) ----------
__global__ void sort_k(const int* __restrict__ indice){
    __shared__ int hist[17];
    __shared__ int binCur[17];
    int tid = threadIdx.x;
    if (tid < 17) hist[tid]=0;
    __syncthreads();
    for (int n=tid; n<NT; n+=blockDim.x){
        int l=0;
        #pragma unroll
        for (int k=0;k<KC;k++) if (indice[n*KC+k]!=-1) l++;
        s_lenOrig[n]=l;
        atomicAdd(&hist[l],1);
    }
    __syncthreads();
    if (tid==0){
        int run=0;
        for (int l=16;l>=1;l--){ binCur[l]=run; run+=hist[l]; }
        int c=0;
        s_cntF[16]=0;
        for (int s=15;s>=0;s--){ c += hist[s+1]; s_cntF[s]=c; }
        g_barCnt = 0;
    }
    __syncthreads();
    for (int n=tid; n<NT; n+=blockDim.x){
        int l=s_lenOrig[n];
        int pos=atomicAdd(&binCur[l],1);
        s_ord[pos]=n;
        s_len[pos]=l;
    }
}

// ---------------- prep: pack + convert weights (gate-interleaved) -----------
// packed row rp -> gate q=(rp>>5)&3, unit d=((rp>>7)<<5)|(rp&31); src r=q*256+d
__global__ void prep_weights(const float* __restrict__ Wih, const float* __restrict__ Whh,
                             const float* __restrict__ bih, const float* __restrict__ bhh,
                             const float* __restrict__ W_w, const float* __restrict__ fc){
    const int map5[5]={0,1,2,4,6};
    const int mapB[3]={3,5,7};
    long idx = (long)blockIdx.x*blockDim.x + threadIdx.x;
    long stride = (long)gridDim.x*blockDim.x;
    for (long i=idx; i<(long)NCMB*GD*DM; i+=stride){
        int cmb = (int)(i/((long)GD*DM)); long rem = i%((long)GD*DM);
        int rp = (int)(rem/DM); int kcol = (int)(rem%DM);
        int q = (rp>>5)&3; int du = ((rp>>7)<<5)|(rp&31);
        long src = (long)map5[cmb]*GD*DM + (long)(q*256+du)*DM + kcol;
        s_Wih5h[i]=__float2half(Wih[src]);
        s_Whh5h[i]=__float2half(Whh[src]);
    }
    for (long i=idx; i<3L*GD*DM; i+=stride){
        int jb = (int)(i/((long)GD*DM)); long r = i%((long)GD*DM);
        s_WihBh[i]=__float2half(Wih[(long)mapB[jb]*GD*DM + r]);
    }
    for (long i=idx; i<(long)GD*DM; i+=stride)
        s_Wwh[i]=__float2half(W_w[i]);
    for (long i=idx; i<4L*DM*2*DM; i+=stride)
        s_fch[i]=__float2half(fc[i]);
    for (long i=idx; i<(long)NCMB*GD; i+=stride){
        int cmb=(int)(i/GD); int rp=(int)(i%GD);
        int q=(rp>>5)&3; int du=((rp>>7)<<5)|(rp&31);
        int r = q*256+du;
        s_b5[i]=bih[map5[cmb]*GD+r]+bhh[map5[cmb]*GD+r];
    }
}

// ---------------- convert x to fp16 (sorted rows) ----------------------------
__global__ void conv_x(const float* __restrict__ x){
    long i = (long)blockIdx.x*blockDim.x + threadIdx.x;
    if (i >= (long)NT*(DM/4)) return;
    int sn = (int)(i/(DM/4)); int d4 = (int)(i%(DM/4));
    int orig = s_ord[sn];
    float4 v = ((const float4*)x)[(long)orig*(DM/4)+d4];
    ((__half2*)s_x16)[((long)sn*DM + d4*4)>>1]     = __floats2half2_rn(v.x, v.y);
    ((__half2*)s_x16)[(((long)sn*DM + d4*4)>>1)+1] = __floats2half2_rn(v.z, v.w);
}

// ---------------- gather child states (sorted, xseq k-major) -----------------
__global__ void gather_k(const float* __restrict__ h_tensor,
                         const float* __restrict__ c_tensor,
                         const int*   __restrict__ indice){
    long i = (long)blockIdx.x*blockDim.x + threadIdx.x;
    if (i >= (long)NT*KC*(DM/4)) return;
    long nk = i / (DM/4);
    int  d4 = (int)(i % (DM/4));
    int sn = (int)(nk >> 4); int k = (int)(nk & 15);
    int orig = s_ord[sn];
    int id = indice[orig*KC+k]; if (id < 0) id = 0;
    float4 h = ((const float4*)h_tensor)[(long)id*(DM/4)+d4];
    ((float4*)s_cseq)[((long)sn*KC+k)*(DM/4)+d4] = ((const float4*)c_tensor)[(long)id*(DM/4)+d4];
    long xo = ((long)k*NT + sn)*DM + d4*4;
    ((__half2*)s_xseq16)[xo>>1]     = __floats2half2_rn(h.x, h.y);
    ((__half2*)s_xseq16)[(xo>>1)+1] = __floats2half2_rn(h.z, h.w);
}

// ---------------- initial states (both h buffers) -----------------------------
__global__ void meta_k(const float* __restrict__ h0, const float* __restrict__ c0){
    long idx = (long)blockIdx.x*blockDim.x + threadIdx.x;
    long stride = (long)gridDim.x*blockDim.x;
    const int jmap[5]={0,0,1,2,3};
    for (long i=idx; i<2L*NCMB*NT*DM; i+=stride){
        int cmb = (int)((i/((long)NT*DM))%NCMB); int d = (int)(i%DM);
        s_h16[i] = __float2half(h0[jmap[cmb]*DM+d]);
    }
    for (long i=idx; i<(long)NCMB*NT*DM; i+=stride){
        int cmb = (int)(i/((long)NT*DM)); int d = (int)(i%DM);
        s_c[i] = c0[jmap[cmb]*DM+d];
    }
}

__global__ void xlast_k(){
    long i = (long)blockIdx.x*blockDim.x + threadIdx.x;
    if (i >= (long)NT*(DM/8)) return;
    int sn = (int)(i/(DM/8)); int j = (int)(i%(DM/8));
    int last = s_len[sn]-1;
    ((uint4*)s_xlast16)[i] = ((const uint4*)s_xseq16)[((long)last*NT+sn)*(DM/8)+j];
}

__global__ void hb_k(const float* __restrict__ h0, const float* __restrict__ Whh,
                     const float* __restrict__ bih, const float* __restrict__ bhh){
    int idx = blockIdx.x*blockDim.x + threadIdx.x;
    if (idx >= 3*GD) return;
    int jb = idx/GD, o = idx%GD;
    int jd2 = 2*(jb+1)+1;
    const float* w = Whh + (long)jd2*GD*DM + (long)o*DM;
    const float* h = h0 + (jb+1)*DM;
    float acc=0.f;
    #pragma unroll 8
    for (int d=0; d<DM; d++) acc += h[d]*w[d];
    s_hb[idx] = acc + bih[jd2*GD+o] + bhh[jd2*GD+o];
}

// ---------------- shared GEMM plumbing ---------------------------------------
#define STR2 20                       // u32 per smem row (16 data + 4 pad)
#define AB_U32 (128*STR2)
#define ABUF(b) ((b)*AB_U32)
#define BBUF(b) (3*AB_U32 + (b)*AB_U32)
#define SMEM_SZ (6*AB_U32*4)          // 61440 bytes

#define PRE16(Ab, Bb, Astride, Bstride, brow_, bcol_, rxor_, ch, buf) do {        \
    long kb = (long)(ch)*32;                                                      \
    _Pragma("unroll")                                                             \
    for (int l=0;l<2;l++){                                                        \
        int r = lrow4 + l*64;                                                     \
        long gr = ((brow_) + r) ^ (rxor_);                                        \
        uint32_t da = sbase + (ABUF(buf) + r*STR2)*4 + lq*16;                     \
        asm volatile("cp.async.cg.shared.global [%0],[%1],16;"                    \
                     :: "r"(da), "l"((Ab) + gr*(Astride) + kb + lq*8));           \
        uint32_t db = sbase + (BBUF(buf) + r*STR2)*4 + lq*16;                     \
        asm volatile("cp.async.cg.shared.global [%0],[%1],16;"                    \
                     :: "r"(db), "l"((Bb) + ((bcol_) + r)*(Bstride) + kb + lq*8)); \
    }                                                                             \
    asm volatile("cp.async.commit_group;");                                       \
} while(0)

#define MAINLOOP_CHUNK(cb)  do {                                                  \
    const uint32_t* sA = &sm[ABUF(cb)];                                           \
    const uint32_t* sB = &sm[BBUF(cb)];                                           \
    _Pragma("unroll")                                                             \
    for (int ks = 0; ks < 2; ks++){                                               \
        int k0 = ks*8;                                                            \
        uint32_t af[4][4], bf[4][2];                                              \
        _Pragma("unroll")                                                         \
        for (int mt=0; mt<4; mt++){                                               \
            int ar = wrw*64 + mt*16 + gq;                                         \
            af[mt][0] = sA[ar*STR2 + k0 + tq];                                    \
            af[mt][1] = sA[(ar+8)*STR2 + k0 + tq];                                \
            af[mt][2] = sA[ar*STR2 + k0 + tq + 4];                                \
            af[mt][3] = sA[(ar+8)*STR2 + k0 + tq + 4];                            \
        }                                                                         \
        _Pragma("unroll")                                                         \
        for (int nt=0; nt<4; nt++){                                               \
            int bn = wcw*32 + nt*8 + gq;                                          \
            bf[nt][0] = sB[bn*STR2 + k0 + tq];                                    \
            bf[nt][1] = sB[bn*STR2 + k0 + tq + 4];                                \
        }                                                                         \
        _Pragma("unroll")                                                         \
        for (int mt=0; mt<4; mt++)                                                \
            _Pragma("unroll")                                                     \
            for (int nt=0; nt<4; nt++)                                            \
                mma_f16(acc[mt][nt], af[mt][0],af[mt][1],af[mt][2],af[mt][3],     \
                        bf[nt][0], bf[nt][1]);                                    \
    }                                                                             \
} while(0)

// ---------------- generic fp16 GEMM (non-recurrent launches) -----------------
__global__ void __launch_bounds__(256,2) gemm_h(
    const __half* __restrict__ A, long aBatch,
    const __half* __restrict__ B, long bBatch,
    const float* __restrict__ bias, long biasBatch,
    float* __restrict__ CF, __half* __restrict__ CH, long cBatch, int cRow,
    int M, int N, int K, int xorZ, int xorVal,
    const int* __restrict__ exCnt, int exitKind)
{
    int z = blockIdx.z;
    long brow = (long)blockIdx.y * 128;
    if (exitKind == 1){
        int k = (int)(brow >> 12);
        int w = (int)(brow & 4095);
        int lim = (z==xorZ) ? exCnt[15-k] : exCnt[k];
        if (w >= lim) return;
    }
    extern __shared__ uint32_t sm[];
    uint32_t sbase;
    asm("{ .reg .u64 t; cvta.to.shared.u64 t, %1; cvt.u32.u64 %0, t; }"
        : "=r"(sbase) : "l"(sm));
    int tid = threadIdx.x;
    int wid = tid >> 5, lane = tid & 31;
    int gq = lane >> 2, tq = lane & 3;
    int wrw = wid >> 2, wcw = wid & 3;
    int lrow4 = tid >> 2, lq = tid & 3;

    const __half* Ab = A + (long)z*aBatch;
    const __half* Bb = B + (long)z*bBatch;
    long rxor = (z==xorZ) ? xorVal : 0;
    long bcol = (long)blockIdx.x * 128;

    float4 acc[4][4];
    #pragma unroll
    for (int i=0;i<4;i++)
        #pragma unroll
        for (int j=0;j<4;j++) acc[i][j] = make_float4(0.f,0.f,0.f,0.f);

    int nCh = K >> 5;
    PRE16(Ab, Bb, K, K, brow, bcol, rxor, 0, 0);
    if (nCh > 1) PRE16(Ab, Bb, K, K, brow, bcol, rxor, 1, 1);
    for (int i = 0; i < nCh; i++){
        if (i + 1 < nCh) asm volatile("cp.async.wait_group 1;" ::: "memory");
        else             asm volatile("cp.async.wait_group 0;" ::: "memory");
        __syncthreads();
        MAINLOOP_CHUNK(i % 3);
        if (i + 2 < nCh){
            PRE16(Ab, Bb, K, K, brow, bcol, rxor, i + 2, (i + 2) % 3);
        }
        __syncthreads();
    }

    const float* biasb = bias ? bias + (long)z*biasBatch : (const float*)0;
    #pragma unroll
    for (int mt=0; mt<4; mt++){
        long row0 = brow + wrw*64 + mt*16 + gq;
        #pragma unroll
        for (int nt=0; nt<4; nt++){
            long col = bcol + wcw*32 + nt*8 + 2*tq;
            float2 v0 = make_float2(acc[mt][nt].x, acc[mt][nt].y);
            float2 v1 = make_float2(acc[mt][nt].z, acc[mt][nt].w);
            if (biasb){
                v0.x += biasb[col];   v0.y += biasb[col+1];
                v1.x += biasb[col];   v1.y += biasb[col+1];
            }
            if (CH){
                __half* Cb = CH + (long)z*cBatch;
                *reinterpret_cast<__half2*>(&Cb[row0*cRow + col])     = __floats2half2_rn(v0.x, v0.y);
                *reinterpret_cast<__half2*>(&Cb[(row0+8)*cRow + col]) = __floats2half2_rn(v1.x, v1.y);
            } else {
                float* Cb = CF + (long)z*cBatch;
                *reinterpret_cast<float2*>(&Cb[row0*cRow + col])     = v0;
                *reinterpret_cast<float2*>(&Cb[(row0+8)*cRow + col]) = v1;
            }
        }
    }
}

// ---------------- persistent recurrence kernel (16 steps, fused gates) -------
__global__ void __launch_bounds__(256,2) rec_k(){
    extern __shared__ uint32_t sm[];
    __half* gs = (__half*)sm;          // 128 x 132 fp16 staging (33792 B)
    uint32_t sbase;
    asm("{ .reg .u64 t; cvta.to.shared.u64 t, %1; cvt.u32.u64 %0, t; }"
        : "=r"(sbase) : "l"(sm));
    int tid = threadIdx.x;
    int wid = tid >> 5, lane = tid & 31;
    int gq = lane >> 2, tq = lane & 3;
    int wrw = wid >> 2, wcw = wid & 3;
    int lrow4 = tid >> 2, lq = tid & 3;

    for (int s = 0; s < KC; s++){
        int rdb = s & 1, wrb = rdb ^ 1;
        int lim[5], base[6];
        base[0] = 0;
        #pragma unroll
        for (int c=0;c<5;c++){
            lim[c] = (c==1) ? s_cntF[15-s] : s_cntF[s];
            base[c+1] = base[c] + (((lim[c]+127)>>7) << 3);
        }
        int T = base[5];
        for (int tile = blockIdx.x; tile < T; tile += NCTA){
            int c = 0;
            #pragma unroll
            for (int cc=0;cc<4;cc++) if (tile >= base[cc+1]) c = cc+1;
            int idx = tile - base[c];
            int rowTile = idx >> 3, colTile = idx & 7;
            long brow = (long)rowTile << 7;
            long bcol = (long)colTile << 7;
            const __half* Ab = s_h16 + ((long)rdb*NCMB + c)*NT*DM;
            const __half* Bb = s_Whh5h + (long)c*GD*DM;
            const __half* caddb = s_Gx16 + ((long)c*KC + s)*NT*GD;

            float4 acc[4][4];
            #pragma unroll
            for (int i=0;i<4;i++)
                #pragma unroll
                for (int j=0;j<4;j++) acc[i][j] = make_float4(0.f,0.f,0.f,0.f);

            PRE16(Ab, Bb, DM, DM, brow, bcol, 0L, 0, 0);
            PRE16(Ab, Bb, DM, DM, brow, bcol, 0L, 1, 1);
            #pragma unroll
            for (int i = 0; i < 8; i++){
                if (i < 7) asm volatile("cp.async.wait_group 1;" ::: "memory");
                else       asm volatile("cp.async.wait_group 0;" ::: "memory");
                __syncthreads();
                MAINLOOP_CHUNK(i % 3);
                if (i + 2 < 8){
                    PRE16(Ab, Bb, DM, DM, brow, bcol, 0L, i + 2, (i + 2) % 3);
                }
                __syncthreads();
            }

            // stage gate preactivations (acc + Gx) into smem fp16
            #pragma unroll
            for (int mt=0; mt<4; mt++){
                int lr0 = wrw*64 + mt*16 + gq;
                long n0 = brow + lr0;
                #pragma unroll
                for (int nt=0; nt<4; nt++){
                    int lcol = wcw*32 + nt*8 + 2*tq;
                    long col = bcol + lcol;
                    float2 a0 = __half22float2(*reinterpret_cast<const __half2*>(&caddb[n0*GD + col]));
                    float2 a1 = __half22float2(*reinterpret_cast<const __half2*>(&caddb[(n0+8)*GD + col]));
                    *reinterpret_cast<__half2*>(&gs[lr0*132 + lcol]) =
                        __floats2half2_rn(acc[mt][nt].x + a0.x, acc[mt][nt].y + a0.y);
                    *reinterpret_cast<__half2*>(&gs[(lr0+8)*132 + lcol]) =
                        __floats2half2_rn(acc[mt][nt].z + a1.x, acc[mt][nt].w + a1.y);
                }
            }
            __syncthreads();

            // fused LSTM gates: 128 rows x 32 units, half2 over units
            #pragma unroll
            for (int it=0; it<8; it++){
                int idx2 = tid + it*256;
                int row = idx2 >> 4, up = idx2 & 15;
                int u = up*2;
                int n = (int)brow + row;
                if (n >= lim[c]) continue;
                int d = (colTile<<5) + u;
                float2 gi = __half22float2(*reinterpret_cast<const __half2*>(&gs[row*132 + u]));
                float2 gf = __half22float2(*reinterpret_cast<const __half2*>(&gs[row*132 + 32 + u]));
                float2 gu = __half22float2(*reinterpret_cast<const __half2*>(&gs[row*132 + 64 + u]));
                float2 go = __half22float2(*reinterpret_cast<const __half2*>(&gs[row*132 + 96 + u]));
                long ist = ((long)c*NT + n)*DM + d;
                float2 cp = *reinterpret_cast<const float2*>(&s_c[ist]);
                float2 cn, hn;
                cn.x = sigf(gf.x)*cp.x + sigf(gi.x)*tanhf(gu.x);
                cn.y = sigf(gf.y)*cp.y + sigf(gi.y)*tanhf(gu.y);
                hn.x = sigf(go.x)*tanhf(cn.x);
                hn.y = sigf(go.y)*tanhf(cn.y);
                *reinterpret_cast<float2*>(&s_c[ist]) = cn;
                __half2 hn2 = __floats2half2_rn(hn.x, hn.y);
                *reinterpret_cast<__half2*>(&s_h16[((long)wrb*NCMB + c)*NT*DM + (long)n*DM + d]) = hn2;
                if (c == 0)
                    *reinterpret_cast<__half2*>(&s_ycat016[((long)s*NT+n)*(2*DM) + d]) = hn2;
                else if (c == 1)
                    *reinterpret_cast<__half2*>(&s_ycat016[((long)(15-s)*NT+n)*(2*DM) + DM + d]) = hn2;
                else if (s == s_len[n]-1)
                    *reinterpret_cast<__half2*>(&s_ylcat16[((long)(c-2)*NT+n)*(2*DM) + d]) = hn2;
            }
            __syncthreads();   // protect gs before next tile's prefetch
        }
        grid_barrier();
    }
}

// ---------------- one-step backward gates (j=1..3, original layout) ----------
__global__ void gates_last(const float* __restrict__ c0){
    long i = (long)blockIdx.x*blockDim.x + threadIdx.x;
    if (i >= 3L*NT*(DM/2)) return;
    int jb = (int)(i/((long)NT*(DM/2)));
    long nd = i%((long)NT*(DM/2));
    int n = (int)(nd/(DM/2)), d2 = (int)(nd%(DM/2));
    int d = d2*2;
    const __half2* g = (const __half2*)(s_gB16 + (long)jb*NT*GD + (long)n*GD);
    float2 gi = __half22float2(g[d2]);
    float2 gf = __half22float2(g[(DM>>1)+d2]);
    float2 gu = __half22float2(g[DM+d2]);
    float2 go = __half22float2(g[((3*DM)>>1)+d2]);
    float2 cp = *reinterpret_cast<const float2*>(&c0[(jb+1)*DM+d]);
    float2 hn;
    float cnx = sigf(gf.x)*cp.x + sigf(gi.x)*tanhf(gu.x);
    float cny = sigf(gf.y)*cp.y + sigf(gi.y)*tanhf(gu.y);
    hn.x = sigf(go.x)*tanhf(cnx);
    hn.y = sigf(go.y)*tanhf(cny);
    *reinterpret_cast<__half2*>(&s_ylcat16[((long)jb*NT+n)*(2*DM) + DM + d]) = __floats2half2_rn(hn.x, hn.y);
}

__global__ void final_k(float* __restrict__ out){
    int n = blockIdx.x, d = threadIdx.x;   // n = sorted slot
    int orig = s_ord[n];
    float wf = s_Wx[(long)n*GD + d];
    float wi = s_Wx[(long)n*GD + DM + d];
    float wu = s_Wx[(long)n*GD + 2*DM + d];
    float wo = s_Wx[(long)n*GD + 3*DM + d];
    int len = s_len[n];
    float bf = 0.f;
    for (int k=0;k<len;k++){
        float y  = __half2float(s_ys016[((long)k*NT+n)*DM + d]);
        float cc = s_cseq[((long)n*KC+k)*DM + d];
        bf += sigf(wf + y) * cc;
    }
    float bi = sigf (__half2float(s_ysl16[0L*NT*DM + (long)n*DM + d]) + wi);
    float bu = tanhf(__half2float(s_ysl16[1L*NT*DM + (long)n*DM + d]) + wu);
    float bo = sigf (__half2float(s_ysl16[2L*NT*DM + (long)n*DM + d]) + wo);
    float ncv = bi*bu + bf;
    float nhv = bo*tanhf(ncv);
    out[(long)orig*DM + d] = nhv;
    out[(long)NT*DM + (long)orig*DM + d] = ncv;
}

// =============================================================================
extern "C" void kernel_launch(void* const* d_in, const int* in_sizes, int n_in,
                              void* d_out, int out_size) {
    const float* x        = (const float*)d_in[0];
    const float* h_tensor = (const float*)d_in[1];
    const float* c_tensor = (const float*)d_in[2];
    const int*   indice   = (const int*)  d_in[3];
    const float* W_w      = (const float*)d_in[4];
    const float* W_b      = (const float*)d_in[5];
    const float* h0       = (const float*)d_in[6];
    const float* c0       = (const float*)d_in[7];
    const float* Wih      = (const float*)d_in[8];
    const float* Whh      = (const float*)d_in[9];
    const float* bih      = (const float*)d_in[10];
    const float* bhh      = (const float*)d_in[11];
    const float* fc       = (const float*)d_in[12];
    float* out = (float*)d_out;

    __half *p_x16,*p_xseq16,*p_xlast16,*p_Wih5h,*p_WihBh,*p_Wwh,*p_fch,
           *p_ycat016,*p_ylcat16,*p_Gx16,*p_gB16,*p_ys016,*p_ysl16;
    float *p_b5,*p_hb,*p_Wx;
    int *p_cntF;
    cudaGetSymbolAddress((void**)&p_x16,     s_x16);
    cudaGetSymbolAddress((void**)&p_xseq16,  s_xseq16);
    cudaGetSymbolAddress((void**)&p_xlast16, s_xlast16);
    cudaGetSymbolAddress((void**)&p_Wih5h,   s_Wih5h);
    cudaGetSymbolAddress((void**)&p_WihBh,   s_WihBh);
    cudaGetSymbolAddress((void**)&p_Wwh,     s_Wwh);
    cudaGetSymbolAddress((void**)&p_fch,     s_fch);
    cudaGetSymbolAddress((void**)&p_ycat016, s_ycat016);
    cudaGetSymbolAddress((void**)&p_ylcat16, s_ylcat16);
    cudaGetSymbolAddress((void**)&p_Gx16,    s_Gx16);
    cudaGetSymbolAddress((void**)&p_gB16,    s_gB16);
    cudaGetSymbolAddress((void**)&p_ys016,   s_ys016);
    cudaGetSymbolAddress((void**)&p_ysl16,   s_ysl16);
    cudaGetSymbolAddress((void**)&p_b5,      s_b5);
    cudaGetSymbolAddress((void**)&p_hb,      s_hb);
    cudaGetSymbolAddress((void**)&p_Wx,      s_Wx);
    cudaGetSymbolAddress((void**)&p_cntF,    s_cntF);
    (void)in_sizes; (void)n_in; (void)out_size;

    cudaFuncSetAttribute(gemm_h, cudaFuncAttributeMaxDynamicSharedMemorySize, SMEM_SZ);
    cudaFuncSetAttribute(rec_k,  cudaFuncAttributeMaxDynamicSharedMemorySize, SMEM_SZ);

    // 1) sort, pack/convert weights (interleaved), convert x, gather, init
    sort_k<<<1,256>>>(indice);
    prep_weights<<<1024,256>>>(Wih,Whh,bih,bhh,W_w,fc);
    conv_x<<<(int)(((long)NT*(DM/4)+255)/256),256>>>(x);
    gather_k<<<(int)(((long)NT*KC*(DM/4))/256),256>>>(h_tensor,c_tensor,indice);
    meta_k<<<1024,256>>>(h0,c0);

    // 2) Wx = x @ W_w^T + W_b   (sorted rows, original cols) -> fp32
    gemm_h<<<dim3(GD/128, NT/128, 1),256,SMEM_SZ>>>(
        p_x16,0, p_Wwh,0, W_b,0,
        p_Wx,(__half*)0,0,GD, NT,GD,DM, -1,0, (const int*)0,0);

    // 3) Gx = xseq @ Wih5^T + b5 -> fp16 (k-major rows, interleaved cols,
    //    time-reversed k for combo 1, skip k>=len)
    gemm_h<<<dim3(GD/128, (NT*KC)/128, NCMB),256,SMEM_SZ>>>(
        p_xseq16,0, p_Wih5h,(long)GD*DM, p_b5,(long)GD,
        (float*)0,p_Gx16,(long)NT*KC*GD,GD, NT*KC,GD,DM, 1,(15<<12), p_cntF,1);

    // 4) one-step backward prep
    hb_k<<<12,256>>>(h0,Whh,bih,bhh);
    xlast_k<<<(int)(((long)NT*(DM/8)+255)/256),256>>>();

    // 5) the 16-step recurrence: ONE persistent kernel, gates fused
    rec_k<<<NCTA,256,SMEM_SZ>>>();

    // 6) backward one-step for j=1..3 -> fp16 (original layout)
    gemm_h<<<dim3(GD/128, NT/128, 3),256,SMEM_SZ>>>(
        p_xlast16,0, p_WihBh,(long)GD*DM, p_hb,(long)GD,
        (float*)0,p_gB16,(long)NT*GD,GD, NT,GD,DM, -1,0, (const int*)0,0);
    gates_last<<<(int)((3L*NT*(DM/2)+255)/256),256>>>(c0);

    // 7) fc projections -> fp16 (ycat0 k-major; skip k>=len)
    gemm_h<<<dim3(DM/128, (NT*KC)/128, 1),256,SMEM_SZ>>>(
        p_ycat016,0, p_fch,0, (const float*)0,0,
        (float*)0,p_ys016,0,DM, NT*KC,DM,2*DM, -1,0, p_cntF,1);
    gemm_h<<<dim3(DM/128, NT/128, 3),256,SMEM_SZ>>>(
        p_ylcat16,(long)NT*2*DM, p_fch + (long)DM*2*DM,(long)DM*2*DM,
        (const float*)0,0,
        (float*)0,p_ysl16,(long)NT*DM,DM, NT,DM,2*DM, -1,0, (const int*)0,0);

    // 8) final combine -> (new_h, new_c), un-permuted
    final_k<<<NT,DM>>>(out);
}

// round 10
// speedup vs baseline: 4.0225x; 1.0468x over previous
#include <cuda_runtime.h>
#include <cuda_fp16.h>
#include <math.h>
#include <stdint.h>

#define NT   4096      // trees
#define KC   16        // children
#define DM   256       // DOUT
#define GD   1024      // 4*DOUT
#define NCMB 5         // recurrent combos: (j0,f),(j0,b),(j1,f),(j2,f),(j3,f)
#define NCTA 296       // persistent grid: 2 CTAs x 148 SMs

// ---------------- scratch (device globals; no allocations allowed) ----------
__device__ __align__(16) __half s_x16   [(long)NT*DM];
__device__ __align__(16) __half s_xseq16[(long)NT*KC*DM];   // k-major: [k*NT+n][DM]
__device__ __align__(16) __half s_xlast16[(long)NT*DM];
__device__ __align__(16) __half s_Wih5h [(long)NCMB*GD*DM]; // gate-interleaved
__device__ __align__(16) __half s_Whh5h [(long)NCMB*GD*DM]; // gate-interleaved
__device__ __align__(16) __half s_WihBh [3L*GD*DM];         // original order
__device__ __align__(16) __half s_Wwh   [(long)GD*DM];
__device__ __align__(16) __half s_fch   [4L*DM*2*DM];
__device__ __align__(16) __half s_h16   [2L*NCMB*NT*DM];    // double-buffered
__device__ __align__(16) __half s_ycat016[(long)NT*KC*2*DM]; // k-major rows
__device__ __align__(16) __half s_ylcat16[3L*NT*2*DM];
__device__ __align__(16) __half s_Gx16  [(long)NCMB*NT*KC*GD]; // k-major, interleaved cols
__device__ __align__(16) __half s_gB16  [3L*NT*GD];
__device__ __align__(16) __half s_ys016 [(long)NT*KC*DM];
__device__ __align__(16) __half s_ysl16 [3L*NT*DM];
__device__ float s_cseq [(long)NT*KC*DM];
__device__ int   s_len  [NT];        // sorted (descending)
__device__ int   s_ord  [NT];
__device__ int   s_lenOrig[NT];
__device__ int   s_cntF [17];        // cntF[s] = #trees with len > s
__device__ float s_b5   [NCMB*GD];   // gate-interleaved
__device__ float s_hb   [3*GD];
__device__ float s_c    [(long)NCMB*NT*DM];
__device__ float s_Wx   [(long)NT*GD];
__device__ int      g_barCnt;
__device__ unsigned g_barGen;

__device__ __forceinline__ float sigf(float x){ return 1.f/(1.f+expf(-x)); }

__device__ __forceinline__ void mma_f16(float4& c,
        uint32_t a0, uint32_t a1, uint32_t a2, uint32_t a3,
        uint32_t b0, uint32_t b1){
    asm volatile(
        "mma.sync.aligned.m16n8k16.row.col.f32.f16.f16.f32 "
        "{%0,%1,%2,%3}, {%4,%5,%6,%7}, {%8,%9}, {%0,%1,%2,%3};"
        : "+f"(c.x), "+f"(c.y), "+f"(c.z), "+f"(c.w)
        : "r"(a0), "r"(a1), "r"(a2), "r"(a3), "r"(b0), "r"(b1));
}

__device__ __forceinline__ void ldsm_x4(uint32_t& r0, uint32_t& r1,
                                        uint32_t& r2, uint32_t& r3, uint32_t addr){
    asm volatile("ldmatrix.sync.aligned.m8n8.x4.shared.b16 {%0,%1,%2,%3}, [%4];"
                 : "=r"(r0),"=r"(r1),"=r"(r2),"=r"(r3) : "r"(addr));
}
__device__ __forceinline__ void ldsm_x2(uint32_t& r0, uint32_t& r1, uint32_t addr){
    asm volatile("ldmatrix.sync.aligned.m8n8.x2.shared.b16 {%0,%1}, [%2];"
                 : "=r"(r0),"=r"(r1) : "r"(addr));
}

__device__ __forceinline__ void grid_barrier(){
    __syncthreads();
    if (threadIdx.x == 0){
        unsigned gen = atomicAdd(&g_barGen, 0u);
        __threadfence();
        if (atomicAdd(&g_barCnt, 1) == NCTA-1){
            g_barCnt = 0;
            __threadfence();
            atomicAdd(&g_barGen, 1u);
        } else {
            while (atomicAdd(&g_barGen, 0u) == gen) __nanosleep(64);
        }
        __threadfence();
    }
    __syncthreads();
}

// ---------------- sort trees by length (descending, counting sort) ----------
__global__ void sort_k(const int* __restrict__ indice){
    __shared__ int hist[17];
    __shared__ int binCur[17];
    int tid = threadIdx.x;
    if (tid < 17) hist[tid]=0;
    __syncthreads();
    for (int n=tid; n<NT; n+=blockDim.x){
        int l=0;
        #pragma unroll
        for (int k=0;k<KC;k++) if (indice[n*KC+k]!=-1) l++;
        s_lenOrig[n]=l;
        atomicAdd(&hist[l],1);
    }
    __syncthreads();
    if (tid==0){
        int run=0;
        for (int l=16;l>=1;l--){ binCur[l]=run; run+=hist[l]; }
        int c=0;
        s_cntF[16]=0;
        for (int s=15;s>=0;s--){ c += hist[s+1]; s_cntF[s]=c; }
        g_barCnt = 0;
    }
    __syncthreads();
    for (int n=tid; n<NT; n+=blockDim.x){
        int l=s_lenOrig[n];
        int pos=atomicAdd(&binCur[l],1);
        s_ord[pos]=n;
        s_len[pos]=l;
    }
}

// ---------------- prep: pack + convert weights (gate-interleaved) -----------
__global__ void prep_weights(const float* __restrict__ Wih, const float* __restrict__ Whh,
                             const float* __restrict__ bih, const float* __restrict__ bhh,
                             const float* __restrict__ W_w, const float* __restrict__ fc){
    const int map5[5]={0,1,2,4,6};
    const int mapB[3]={3,5,7};
    long idx = (long)blockIdx.x*blockDim.x + threadIdx.x;
    long stride = (long)gridDim.x*blockDim.x;
    for (long i=idx; i<(long)NCMB*GD*DM; i+=stride){
        int cmb = (int)(i/((long)GD*DM)); long rem = i%((long)GD*DM);
        int rp = (int)(rem/DM); int kcol = (int)(rem%DM);
        int q = (rp>>5)&3; int du = ((rp>>7)<<5)|(rp&31);
        long src = (long)map5[cmb]*GD*DM + (long)(q*256+du)*DM + kcol;
        s_Wih5h[i]=__float2half(Wih[src]);
        s_Whh5h[i]=__float2half(Whh[src]);
    }
    for (long i=idx; i<3L*GD*DM; i+=stride){
        int jb = (int)(i/((long)GD*DM)); long r = i%((long)GD*DM);
        s_WihBh[i]=__float2half(Wih[(long)mapB[jb]*GD*DM + r]);
    }
    for (long i=idx; i<(long)GD*DM; i+=stride)
        s_Wwh[i]=__float2half(W_w[i]);
    for (long i=idx; i<4L*DM*2*DM; i+=stride)
        s_fch[i]=__float2half(fc[i]);
    for (long i=idx; i<(long)NCMB*GD; i+=stride){
        int cmb=(int)(i/GD); int rp=(int)(i%GD);
        int q=(rp>>5)&3; int du=((rp>>7)<<5)|(rp&31);
        int r = q*256+du;
        s_b5[i]=bih[map5[cmb]*GD+r]+bhh[map5[cmb]*GD+r];
    }
}

// ---------------- convert x to fp16 (sorted rows) ----------------------------
__global__ void conv_x(const float* __restrict__ x){
    long i = (long)blockIdx.x*blockDim.x + threadIdx.x;
    if (i >= (long)NT*(DM/4)) return;
    int sn = (int)(i/(DM/4)); int d4 = (int)(i%(DM/4));
    int orig = s_ord[sn];
    float4 v = ((const float4*)x)[(long)orig*(DM/4)+d4];
    ((__half2*)s_x16)[((long)sn*DM + d4*4)>>1]     = __floats2half2_rn(v.x, v.y);
    ((__half2*)s_x16)[(((long)sn*DM + d4*4)>>1)+1] = __floats2half2_rn(v.z, v.w);
}

// ---------------- gather child states (sorted, xseq k-major) -----------------
__global__ void gather_k(const float* __restrict__ h_tensor,
                         const float* __restrict__ c_tensor,
                         const int*   __restrict__ indice){
    long i = (long)blockIdx.x*blockDim.x + threadIdx.x;
    if (i >= (long)NT*KC*(DM/4)) return;
    long nk = i / (DM/4);
    int  d4 = (int)(i % (DM/4));
    int sn = (int)(nk >> 4); int k = (int)(nk & 15);
    int orig = s_ord[sn];
    int id = indice[orig*KC+k]; if (id < 0) id = 0;
    float4 h = ((const float4*)h_tensor)[(long)id*(DM/4)+d4];
    ((float4*)s_cseq)[((long)sn*KC+k)*(DM/4)+d4] = ((const float4*)c_tensor)[(long)id*(DM/4)+d4];
    long xo = ((long)k*NT + sn)*DM + d4*4;
    ((__half2*)s_xseq16)[xo>>1]     = __floats2half2_rn(h.x, h.y);
    ((__half2*)s_xseq16)[(xo>>1)+1] = __floats2half2_rn(h.z, h.w);
}

// ---------------- initial states (both h buffers) -----------------------------
__global__ void meta_k(const float* __restrict__ h0, const float* __restrict__ c0){
    long idx = (long)blockIdx.x*blockDim.x + threadIdx.x;
    long stride = (long)gridDim.x*blockDim.x;
    const int jmap[5]={0,0,1,2,3};
    for (long i=idx; i<2L*NCMB*NT*DM; i+=stride){
        int cmb = (int)((i/((long)NT*DM))%NCMB); int d = (int)(i%DM);
        s_h16[i] = __float2half(h0[jmap[cmb]*DM+d]);
    }
    for (long i=idx; i<(long)NCMB*NT*DM; i+=stride){
        int cmb = (int)(i/((long)NT*DM)); int d = (int)(i%DM);
        s_c[i] = c0[jmap[cmb]*DM+d];
    }
}

__global__ void xlast_k(){
    long i = (long)blockIdx.x*blockDim.x + threadIdx.x;
    if (i >= (long)NT*(DM/8)) return;
    int sn = (int)(i/(DM/8)); int j = (int)(i%(DM/8));
    int last = s_len[sn]-1;
    ((uint4*)s_xlast16)[i] = ((const uint4*)s_xseq16)[((long)last*NT+sn)*(DM/8)+j];
}

__global__ void hb_k(const float* __restrict__ h0, const float* __restrict__ Whh,
                     const float* __restrict__ bih, const float* __restrict__ bhh){
    int idx = blockIdx.x*blockDim.x + threadIdx.x;
    if (idx >= 3*GD) return;
    int jb = idx/GD, o = idx%GD;
    int jd2 = 2*(jb+1)+1;
    const float* w = Whh + (long)jd2*GD*DM + (long)o*DM;
    const float* h = h0 + (jb+1)*DM;
    float acc=0.f;
    #pragma unroll 8
    for (int d=0; d<DM; d++) acc += h[d]*w[d];
    s_hb[idx] = acc + bih[jd2*GD+o] + bhh[jd2*GD+o];
}

// ---------------- shared GEMM plumbing ---------------------------------------
#define STR2 20                       // u32 per smem row (16 data + 4 pad)
#define AB_U32 (128*STR2)
#define ABUF(b) ((b)*AB_U32)
#define BBUF(b) (3*AB_U32 + (b)*AB_U32)
#define SMEM_SZ (6*AB_U32*4)          // 61440 bytes

#define LDSM_OFFSETS()                                                            \
    int aoff[4], boff[4];                                                         \
    {                                                                             \
        int rA = lane & 15;                                                       \
        int cA = (lane >> 4) << 2;                                                \
        _Pragma("unroll")                                                         \
        for (int mt=0; mt<4; mt++)                                                \
            aoff[mt] = ((wrw*64 + mt*16 + rA)*STR2 + cA)*4;                       \
        int rB = lane & 7;                                                        \
        int cB = ((lane >> 3) & 1) << 2;                                          \
        _Pragma("unroll")                                                         \
        for (int nt=0; nt<4; nt++)                                                \
            boff[nt] = ((wcw*32 + nt*8 + rB)*STR2 + cB)*4;                        \
    }

#define PRE16(Ab, Bb, Astride, Bstride, brow_, bcol_, rxor_, ch, buf) do {        \
    long kb = (long)(ch)*32;                                                      \
    _Pragma("unroll")                                                             \
    for (int l=0;l<2;l++){                                                        \
        int r = lrow4 + l*64;                                                     \
        long gr = ((brow_) + r) ^ (rxor_);                                        \
        uint32_t da = sbase + (ABUF(buf) + r*STR2)*4 + lq*16;                     \
        asm volatile("cp.async.cg.shared.global [%0],[%1],16;"                    \
                     :: "r"(da), "l"((Ab) + gr*(Astride) + kb + lq*8));           \
        uint32_t db = sbase + (BBUF(buf) + r*STR2)*4 + lq*16;                     \
        asm volatile("cp.async.cg.shared.global [%0],[%1],16;"                    \
                     :: "r"(db), "l"((Bb) + ((bcol_) + r)*(Bstride) + kb + lq*8)); \
    }                                                                             \
    asm volatile("cp.async.commit_group;");                                       \
} while(0)

#define MAINLOOP_CHUNK(cb)  do {                                                  \
    uint32_t baA = sbase + (ABUF(cb))*4;                                          \
    uint32_t baB = sbase + (BBUF(cb))*4;                                          \
    _Pragma("unroll")                                                             \
    for (int ks = 0; ks < 2; ks++){                                               \
        uint32_t af[4][4], bf[4][2];                                              \
        _Pragma("unroll")                                                         \
        for (int mt=0; mt<4; mt++)                                                \
            ldsm_x4(af[mt][0],af[mt][1],af[mt][2],af[mt][3],                      \
                    baA + ks*32 + aoff[mt]);                                      \
        _Pragma("unroll")                                                         \
        for (int nt=0; nt<4; nt++)                                                \
            ldsm_x2(bf[nt][0],bf[nt][1], baB + ks*32 + boff[nt]);                 \
        _Pragma("unroll")                                                         \
        for (int mt=0; mt<4; mt++)                                                \
            _Pragma("unroll")                                                     \
            for (int nt=0; nt<4; nt++)                                            \
                mma_f16(acc[mt][nt], af[mt][0],af[mt][1],af[mt][2],af[mt][3],     \
                        bf[nt][0], bf[nt][1]);                                    \
    }                                                                             \
} while(0)

// ---------------- generic fp16 GEMM (non-recurrent launches) -----------------
__global__ void __launch_bounds__(256,2) gemm_h(
    const __half* __restrict__ A, long aBatch,
    const __half* __restrict__ B, long bBatch,
    const float* __restrict__ bias, long biasBatch,
    float* __restrict__ CF, __half* __restrict__ CH, long cBatch, int cRow,
    int M, int N, int K, int xorZ, int xorVal,
    const int* __restrict__ exCnt, int exitKind)
{
    int z = blockIdx.z;
    long brow = (long)blockIdx.y * 128;
    if (exitKind == 1){
        int k = (int)(brow >> 12);
        int w = (int)(brow & 4095);
        int lim = (z==xorZ) ? exCnt[15-k] : exCnt[k];
        if (w >= lim) return;
    }
    extern __shared__ uint32_t sm[];
    uint32_t sbase;
    asm("{ .reg .u64 t; cvta.to.shared.u64 t, %1; cvt.u32.u64 %0, t; }"
        : "=r"(sbase) : "l"(sm));
    int tid = threadIdx.x;
    int wid = tid >> 5, lane = tid & 31;
    int gq = lane >> 2, tq = lane & 3;
    int wrw = wid >> 2, wcw = wid & 3;
    int lrow4 = tid >> 2, lq = tid & 3;
    LDSM_OFFSETS();

    const __half* Ab = A + (long)z*aBatch;
    const __half* Bb = B + (long)z*bBatch;
    long rxor = (z==xorZ) ? xorVal : 0;
    long bcol = (long)blockIdx.x * 128;

    float4 acc[4][4];
    #pragma unroll
    for (int i=0;i<4;i++)
        #pragma unroll
        for (int j=0;j<4;j++) acc[i][j] = make_float4(0.f,0.f,0.f,0.f);

    int nCh = K >> 5;
    PRE16(Ab, Bb, K, K, brow, bcol, rxor, 0, 0);
    if (nCh > 1) PRE16(Ab, Bb, K, K, brow, bcol, rxor, 1, 1);
    for (int i = 0; i < nCh; i++){
        if (i + 1 < nCh) asm volatile("cp.async.wait_group 1;" ::: "memory");
        else             asm volatile("cp.async.wait_group 0;" ::: "memory");
        __syncthreads();
        MAINLOOP_CHUNK(i % 3);
        if (i + 2 < nCh){
            PRE16(Ab, Bb, K, K, brow, bcol, rxor, i + 2, (i + 2) % 3);
        }
    }

    const float* biasb = bias ? bias + (long)z*biasBatch : (const float*)0;
    #pragma unroll
    for (int mt=0; mt<4; mt++){
        long row0 = brow + wrw*64 + mt*16 + gq;
        #pragma unroll
        for (int nt=0; nt<4; nt++){
            long col = bcol + wcw*32 + nt*8 + 2*tq;
            float2 v0 = make_float2(acc[mt][nt].x, acc[mt][nt].y);
            float2 v1 = make_float2(acc[mt][nt].z, acc[mt][nt].w);
            if (biasb){
                v0.x += biasb[col];   v0.y += biasb[col+1];
                v1.x += biasb[col];   v1.y += biasb[col+1];
            }
            if (CH){
                __half* Cb = CH + (long)z*cBatch;
                *reinterpret_cast<__half2*>(&Cb[row0*cRow + col])     = __floats2half2_rn(v0.x, v0.y);
                *reinterpret_cast<__half2*>(&Cb[(row0+8)*cRow + col]) = __floats2half2_rn(v1.x, v1.y);
            } else {
                float* Cb = CF + (long)z*cBatch;
                *reinterpret_cast<float2*>(&Cb[row0*cRow + col])     = v0;
                *reinterpret_cast<float2*>(&Cb[(row0+8)*cRow + col]) = v1;
            }
        }
    }
}

// ---------------- persistent recurrence kernel (16 steps, fused gates) -------
__global__ void __launch_bounds__(256,2) rec_k(){
    extern __shared__ uint32_t sm[];
    __half* gs = (__half*)sm;          // 128 x 132 fp16 staging (33792 B)
    uint32_t sbase;
    asm("{ .reg .u64 t; cvta.to.shared.u64 t, %1; cvt.u32.u64 %0, t; }"
        : "=r"(sbase) : "l"(sm));
    int tid = threadIdx.x;
    int wid = tid >> 5, lane = tid & 31;
    int gq = lane >> 2, tq = lane & 3;
    int wrw = wid >> 2, wcw = wid & 3;
    int lrow4 = tid >> 2, lq = tid & 3;
    LDSM_OFFSETS();

    for (int s = 0; s < KC; s++){
        int rdb = s & 1, wrb = rdb ^ 1;
        int lim[5], base[6];
        base[0] = 0;
        #pragma unroll
        for (int c=0;c<5;c++){
            lim[c] = (c==1) ? s_cntF[15-s] : s_cntF[s];
            base[c+1] = base[c] + (((lim[c]+127)>>7) << 3);
        }
        int T = base[5];
        for (int tile = blockIdx.x; tile < T; tile += NCTA){
            int c = 0;
            #pragma unroll
            for (int cc=0;cc<4;cc++) if (tile >= base[cc+1]) c = cc+1;
            int idx = tile - base[c];
            int rowTile = idx >> 3, colTile = idx & 7;
            long brow = (long)rowTile << 7;
            long bcol = (long)colTile << 7;
            const __half* Ab = s_h16 + ((long)rdb*NCMB + c)*NT*DM;
            const __half* Bb = s_Whh5h + (long)c*GD*DM;
            const __half* caddb = s_Gx16 + ((long)c*KC + s)*NT*GD;

            float4 acc[4][4];
            #pragma unroll
            for (int i=0;i<4;i++)
                #pragma unroll
                for (int j=0;j<4;j++) acc[i][j] = make_float4(0.f,0.f,0.f,0.f);

            PRE16(Ab, Bb, DM, DM, brow, bcol, 0L, 0, 0);
            PRE16(Ab, Bb, DM, DM, brow, bcol, 0L, 1, 1);
            #pragma unroll
            for (int i = 0; i < 8; i++){
                if (i < 7) asm volatile("cp.async.wait_group 1;" ::: "memory");
                else       asm volatile("cp.async.wait_group 0;" ::: "memory");
                __syncthreads();
                MAINLOOP_CHUNK(i % 3);
                if (i + 2 < 8){
                    PRE16(Ab, Bb, DM, DM, brow, bcol, 0L, i + 2, (i + 2) % 3);
                }
            }
            __syncthreads();   // all warps done with ring smem before gs staging

            // stage gate preactivations (acc + Gx) into smem fp16
            #pragma unroll
            for (int mt=0; mt<4; mt++){
                int lr0 = wrw*64 + mt*16 + gq;
                long n0 = brow + lr0;
                #pragma unroll
                for (int nt=0; nt<4; nt++){
                    int lcol = wcw*32 + nt*8 + 2*tq;
                    long col = bcol + lcol;
                    float2 a0 = __half22float2(*reinterpret_cast<const __half2*>(&caddb[n0*GD + col]));
                    float2 a1 = __half22float2(*reinterpret_cast<const __half2*>(&caddb[(n0+8)*GD + col]));
                    *reinterpret_cast<__half2*>(&gs[lr0*132 + lcol]) =
                        __floats2half2_rn(acc[mt][nt].x + a0.x, acc[mt][nt].y + a0.y);
                    *reinterpret_cast<__half2*>(&gs[(lr0+8)*132 + lcol]) =
                        __floats2half2_rn(acc[mt][nt].z + a1.x, acc[mt][nt].w + a1.y);
                }
            }
            __syncthreads();

            // fused LSTM gates: 128 rows x 32 units, half2 over units
            #pragma unroll
            for (int it=0; it<8; it++){
                int idx2 = tid + it*256;
                int row = idx2 >> 4, up = idx2 & 15;
                int u = up*2;
                int n = (int)brow + row;
                if (n >= lim[c]) continue;
                int d = (colTile<<5) + u;
                float2 gi = __half22float2(*reinterpret_cast<const __half2*>(&gs[row*132 + u]));
                float2 gf = __half22float2(*reinterpret_cast<const __half2*>(&gs[row*132 + 32 + u]));
                float2 gu = __half22float2(*reinterpret_cast<const __half2*>(&gs[row*132 + 64 + u]));
                float2 go = __half22float2(*reinterpret_cast<const __half2*>(&gs[row*132 + 96 + u]));
                long ist = ((long)c*NT + n)*DM + d;
                float2 cp = *reinterpret_cast<const float2*>(&s_c[ist]);
                float2 cn, hn;
                cn.x = sigf(gf.x)*cp.x + sigf(gi.x)*tanhf(gu.x);
                cn.y = sigf(gf.y)*cp.y + sigf(gi.y)*tanhf(gu.y);
                hn.x = sigf(go.x)*tanhf(cn.x);
                hn.y = sigf(go.y)*tanhf(cn.y);
                *reinterpret_cast<float2*>(&s_c[ist]) = cn;
                __half2 hn2 = __floats2half2_rn(hn.x, hn.y);
                *reinterpret_cast<__half2*>(&s_h16[((long)wrb*NCMB + c)*NT*DM + (long)n*DM + d]) = hn2;
                if (c == 0)
                    *reinterpret_cast<__half2*>(&s_ycat016[((long)s*NT+n)*(2*DM) + d]) = hn2;
                else if (c == 1)
                    *reinterpret_cast<__half2*>(&s_ycat016[((long)(15-s)*NT+n)*(2*DM) + DM + d]) = hn2;
                else if (s == s_len[n]-1)
                    *reinterpret_cast<__half2*>(&s_ylcat16[((long)(c-2)*NT+n)*(2*DM) + d]) = hn2;
            }
            __syncthreads();   // protect gs before next tile's prefetch
        }
        grid_barrier();
    }
}

// ---------------- one-step backward gates (j=1..3, original layout) ----------
__global__ void gates_last(const float* __restrict__ c0){
    long i = (long)blockIdx.x*blockDim.x + threadIdx.x;
    if (i >= 3L*NT*(DM/2)) return;
    int jb = (int)(i/((long)NT*(DM/2)));
    long nd = i%((long)NT*(DM/2));
    int n = (int)(nd/(DM/2)), d2 = (int)(nd%(DM/2));
    int d = d2*2;
    const __half2* g = (const __half2*)(s_gB16 + (long)jb*NT*GD + (long)n*GD);
    float2 gi = __half22float2(g[d2]);
    float2 gf = __half22float2(g[(DM>>1)+d2]);
    float2 gu = __half22float2(g[DM+d2]);
    float2 go = __half22float2(g[((3*DM)>>1)+d2]);
    float2 cp = *reinterpret_cast<const float2*>(&c0[(jb+1)*DM+d]);
    float2 hn;
    float cnx = sigf(gf.x)*cp.x + sigf(gi.x)*tanhf(gu.x);
    float cny = sigf(gf.y)*cp.y + sigf(gi.y)*tanhf(gu.y);
    hn.x = sigf(go.x)*tanhf(cnx);
    hn.y = sigf(go.y)*tanhf(cny);
    *reinterpret_cast<__half2*>(&s_ylcat16[((long)jb*NT+n)*(2*DM) + DM + d]) = __floats2half2_rn(hn.x, hn.y);
}

__global__ void final_k(float* __restrict__ out){
    int n = blockIdx.x, d = threadIdx.x;   // n = sorted slot
    int orig = s_ord[n];
    float wf = s_Wx[(long)n*GD + d];
    float wi = s_Wx[(long)n*GD + DM + d];
    float wu = s_Wx[(long)n*GD + 2*DM + d];
    float wo = s_Wx[(long)n*GD + 3*DM + d];
    int len = s_len[n];
    float bf = 0.f;
    for (int k=0;k<len;k++){
        float y  = __half2float(s_ys016[((long)k*NT+n)*DM + d]);
        float cc = s_cseq[((long)n*KC+k)*DM + d];
        bf += sigf(wf + y) * cc;
    }
    float bi = sigf (__half2float(s_ysl16[0L*NT*DM + (long)n*DM + d]) + wi);
    float bu = tanhf(__half2float(s_ysl16[1L*NT*DM + (long)n*DM + d]) + wu);
    float bo = sigf (__half2float(s_ysl16[2L*NT*DM + (long)n*DM + d]) + wo);
    float ncv = bi*bu + bf;
    float nhv = bo*tanhf(ncv);
    out[(long)orig*DM + d] = nhv;
    out[(long)NT*DM + (long)orig*DM + d] = ncv;
}

// =============================================================================
extern "C" void kernel_launch(void* const* d_in, const int* in_sizes, int n_in,
                              void* d_out, int out_size) {
    const float* x        = (const float*)d_in[0];
    const float* h_tensor = (const float*)d_in[1];
    const float* c_tensor = (const float*)d_in[2];
    const int*   indice   = (const int*)  d_in[3];
    const float* W_w      = (const float*)d_in[4];
    const float* W_b      = (const float*)d_in[5];
    const float* h0       = (const float*)d_in[6];
    const float* c0       = (const float*)d_in[7];
    const float* Wih      = (const float*)d_in[8];
    const float* Whh      = (const float*)d_in[9];
    const float* bih      = (const float*)d_in[10];
    const float* bhh      = (const float*)d_in[11];
    const float* fc       = (const float*)d_in[12];
    float* out = (float*)d_out;

    __half *p_x16,*p_xseq16,*p_xlast16,*p_Wih5h,*p_WihBh,*p_Wwh,*p_fch,
           *p_ycat016,*p_ylcat16,*p_Gx16,*p_gB16,*p_ys016,*p_ysl16;
    float *p_b5,*p_hb,*p_Wx;
    int *p_cntF;
    cudaGetSymbolAddress((void**)&p_x16,     s_x16);
    cudaGetSymbolAddress((void**)&p_xseq16,  s_xseq16);
    cudaGetSymbolAddress((void**)&p_xlast16, s_xlast16);
    cudaGetSymbolAddress((void**)&p_Wih5h,   s_Wih5h);
    cudaGetSymbolAddress((void**)&p_WihBh,   s_WihBh);
    cudaGetSymbolAddress((void**)&p_Wwh,     s_Wwh);
    cudaGetSymbolAddress((void**)&p_fch,     s_fch);
    cudaGetSymbolAddress((void**)&p_ycat016, s_ycat016);
    cudaGetSymbolAddress((void**)&p_ylcat16, s_ylcat16);
    cudaGetSymbolAddress((void**)&p_Gx16,    s_Gx16);
    cudaGetSymbolAddress((void**)&p_gB16,    s_gB16);
    cudaGetSymbolAddress((void**)&p_ys016,   s_ys016);
    cudaGetSymbolAddress((void**)&p_ysl16,   s_ysl16);
    cudaGetSymbolAddress((void**)&p_b5,      s_b5);
    cudaGetSymbolAddress((void**)&p_hb,      s_hb);
    cudaGetSymbolAddress((void**)&p_Wx,      s_Wx);
    cudaGetSymbolAddress((void**)&p_cntF,    s_cntF);
    (void)in_sizes; (void)n_in; (void)out_size;

    cudaFuncSetAttribute(gemm_h, cudaFuncAttributeMaxDynamicSharedMemorySize, SMEM_SZ);
    cudaFuncSetAttribute(rec_k,  cudaFuncAttributeMaxDynamicSharedMemorySize, SMEM_SZ);

    // 1) sort, pack/convert weights (interleaved), convert x, gather, init
    sort_k<<<1,256>>>(indice);
    prep_weights<<<1024,256>>>(Wih,Whh,bih,bhh,W_w,fc);
    conv_x<<<(int)(((long)NT*(DM/4)+255)/256),256>>>(x);
    gather_k<<<(int)(((long)NT*KC*(DM/4))/256),256>>>(h_tensor,c_tensor,indice);
    meta_k<<<1024,256>>>(h0,c0);

    // 2) Wx = x @ W_w^T + W_b   (sorted rows, original cols) -> fp32
    gemm_h<<<dim3(GD/128, NT/128, 1),256,SMEM_SZ>>>(
        p_x16,0, p_Wwh,0, W_b,0,
        p_Wx,(__half*)0,0,GD, NT,GD,DM, -1,0, (const int*)0,0);

    // 3) Gx = xseq @ Wih5^T + b5 -> fp16 (k-major rows, interleaved cols,
    //    time-reversed k for combo 1, skip k>=len)
    gemm_h<<<dim3(GD/128, (NT*KC)/128, NCMB),256,SMEM_SZ>>>(
        p_xseq16,0, p_Wih5h,(long)GD*DM, p_b5,(long)GD,
        (float*)0,p_Gx16,(long)NT*KC*GD,GD, NT*KC,GD,DM, 1,(15<<12), p_cntF,1);

    // 4) one-step backward prep
    hb_k<<<12,256>>>(h0,Whh,bih,bhh);
    xlast_k<<<(int)(((long)NT*(DM/8)+255)/256),256>>>();

    // 5) the 16-step recurrence: ONE persistent kernel, gates fused
    rec_k<<<NCTA,256,SMEM_SZ>>>();

    // 6) backward one-step for j=1..3 -> fp16 (original layout)
    gemm_h<<<dim3(GD/128, NT/128, 3),256,SMEM_SZ>>>(
        p_xlast16,0, p_WihBh,(long)GD*DM, p_hb,(long)GD,
        (float*)0,p_gB16,(long)NT*GD,GD, NT,GD,DM, -1,0, (const int*)0,0);
    gates_last<<<(int)((3L*NT*(DM/2)+255)/256),256>>>(c0);

    // 7) fc projections -> fp16 (ycat0 k-major; skip k>=len)
    gemm_h<<<dim3(DM/128, (NT*KC)/128, 1),256,SMEM_SZ>>>(
        p_ycat016,0, p_fch,0, (const float*)0,0,
        (float*)0,p_ys016,0,DM, NT*KC,DM,2*DM, -1,0, p_cntF,1);
    gemm_h<<<dim3(DM/128, NT/128, 3),256,SMEM_SZ>>>(
        p_ylcat16,(long)NT*2*DM, p_fch + (long)DM*2*DM,(long)DM*2*DM,
        (const float*)0,0,
        (float*)0,p_ysl16,(long)NT*DM,DM, NT,DM,2*DM, -1,0, (const int*)0,0);

    // 8) final combine -> (new_h, new_c), un-permuted
    final_k<<<NT,DM>>>(out);
}

// round 11
// speedup vs baseline: 4.9695x; 1.2354x over previous
#include <cuda_runtime.h>
#include <cuda_fp16.h>
#include <math.h>
#include <stdint.h>

#define NT   4096      // trees
#define KC   16        // children
#define DM   256       // DOUT
#define GD   1024      // 4*DOUT
#define NCMB 5         // recurrent combos: (j0,f),(j0,b),(j1,f),(j2,f),(j3,f)
#define NCTA 296       // persistent grid: 2 CTAs x 148 SMs

// ---------------- scratch (device globals; no allocations allowed) ----------
__device__ __align__(16) __half s_x16   [(long)NT*DM];
__device__ __align__(16) __half s_xseq16[(long)NT*KC*DM];   // k-major: [k*NT+n][DM]
__device__ __align__(16) __half s_xlast16[(long)NT*DM];
__device__ __align__(16) __half s_Wih5h [(long)NCMB*GD*DM]; // gate-interleaved
__device__ __align__(16) __half s_Whh5h [(long)NCMB*GD*DM]; // gate-interleaved
__device__ __align__(16) __half s_WihBh [3L*GD*DM];         // original order
__device__ __align__(16) __half s_Wwh   [(long)GD*DM];
__device__ __align__(16) __half s_fch   [4L*DM*2*DM];
__device__ __align__(16) __half s_h16   [2L*NCMB*NT*DM];    // double-buffered
__device__ __align__(16) __half s_ycat016[(long)NT*KC*2*DM]; // k-major rows
__device__ __align__(16) __half s_ylcat16[3L*NT*2*DM];
__device__ __align__(16) __half s_gB16  [3L*NT*GD];
__device__ __align__(16) __half s_ys016 [(long)NT*KC*DM];
__device__ __align__(16) __half s_ysl16 [3L*NT*DM];
__device__ float s_cseq [(long)NT*KC*DM];
__device__ int   s_len  [NT];        // sorted (descending)
__device__ int   s_ord  [NT];
__device__ int   s_lenOrig[NT];
__device__ int   s_cntF [17];        // cntF[s] = #trees with len > s
__device__ float s_b5   [NCMB*GD];   // gate-interleaved
__device__ float s_hb   [3*GD];
__device__ float s_c    [(long)NCMB*NT*DM];
__device__ float s_Wx   [(long)NT*GD];
__device__ int      g_barCnt;
__device__ unsigned g_barGen;

__device__ __forceinline__ float sigf(float x){ return 1.f/(1.f+expf(-x)); }

__device__ __forceinline__ void mma_f16(float4& c,
        uint32_t a0, uint32_t a1, uint32_t a2, uint32_t a3,
        uint32_t b0, uint32_t b1){
    asm volatile(
        "mma.sync.aligned.m16n8k16.row.col.f32.f16.f16.f32 "
        "{%0,%1,%2,%3}, {%4,%5,%6,%7}, {%8,%9}, {%0,%1,%2,%3};"
        : "+f"(c.x), "+f"(c.y), "+f"(c.z), "+f"(c.w)
        : "r"(a0), "r"(a1), "r"(a2), "r"(a3), "r"(b0), "r"(b1));
}

__device__ __forceinline__ void ldsm_x4(uint32_t& r0, uint32_t& r1,
                                        uint32_t& r2, uint32_t& r3, uint32_t addr){
    asm volatile("ldmatrix.sync.aligned.m8n8.x4.shared.b16 {%0,%1,%2,%3}, [%4];"
                 : "=r"(r0),"=r"(r1),"=r"(r2),"=r"(r3) : "r"(addr));
}
__device__ __forceinline__ void ldsm_x2(uint32_t& r0, uint32_t& r1, uint32_t addr){
    asm volatile("ldmatrix.sync.aligned.m8n8.x2.shared.b16 {%0,%1}, [%2];"
                 : "=r"(r0),"=r"(r1) : "r"(addr));
}

__device__ __forceinline__ void grid_barrier(){
    __syncthreads();
    if (threadIdx.x == 0){
        unsigned gen = atomicAdd(&g_barGen, 0u);
        __threadfence();
        if (atomicAdd(&g_barCnt, 1) == NCTA-1){
            g_barCnt = 0;
            __threadfence();
            atomicAdd(&g_barGen, 1u);
        } else {
            while (atomicAdd(&g_barGen, 0u) == gen) __nanosleep(64);
        }
        __threadfence();
    }
    __syncthreads();
}

// ---------------- sort trees by length (descending, counting sort) ----------
__global__ void sort_k(const int* __restrict__ indice){
    __shared__ int hist[17];
    __shared__ int binCur[17];
    int tid = threadIdx.x;
    if (tid < 17) hist[tid]=0;
    __syncthreads();
    for (int n=tid; n<NT; n+=blockDim.x){
        int l=0;
        #pragma unroll
        for (int k=0;k<KC;k++) if (indice[n*KC+k]!=-1) l++;
        s_lenOrig[n]=l;
        atomicAdd(&hist[l],1);
    }
    __syncthreads();
    if (tid==0){
        int run=0;
        for (int l=16;l>=1;l--){ binCur[l]=run; run+=hist[l]; }
        int c=0;
        s_cntF[16]=0;
        for (int s=15;s>=0;s--){ c += hist[s+1]; s_cntF[s]=c; }
        g_barCnt = 0;
    }
    __syncthreads();
    for (int n=tid; n<NT; n+=blockDim.x){
        int l=s_lenOrig[n];
        int pos=atomicAdd(&binCur[l],1);
        s_ord[pos]=n;
        s_len[pos]=l;
    }
}

// ---------------- prep: pack + convert weights (gate-interleaved) -----------
__global__ void prep_weights(const float* __restrict__ Wih, const float* __restrict__ Whh,
                             const float* __restrict__ bih, const float* __restrict__ bhh,
                             const float* __restrict__ W_w, const float* __restrict__ fc){
    const int map5[5]={0,1,2,4,6};
    const int mapB[3]={3,5,7};
    long idx = (long)blockIdx.x*blockDim.x + threadIdx.x;
    long stride = (long)gridDim.x*blockDim.x;
    for (long i=idx; i<(long)NCMB*GD*DM; i+=stride){
        int cmb = (int)(i/((long)GD*DM)); long rem = i%((long)GD*DM);
        int rp = (int)(rem/DM); int kcol = (int)(rem%DM);
        int q = (rp>>5)&3; int du = ((rp>>7)<<5)|(rp&31);
        long src = (long)map5[cmb]*GD*DM + (long)(q*256+du)*DM + kcol;
        s_Wih5h[i]=__float2half(Wih[src]);
        s_Whh5h[i]=__float2half(Whh[src]);
    }
    for (long i=idx; i<3L*GD*DM; i+=stride){
        int jb = (int)(i/((long)GD*DM)); long r = i%((long)GD*DM);
        s_WihBh[i]=__float2half(Wih[(long)mapB[jb]*GD*DM + r]);
    }
    for (long i=idx; i<(long)GD*DM; i+=stride)
        s_Wwh[i]=__float2half(W_w[i]);
    for (long i=idx; i<4L*DM*2*DM; i+=stride)
        s_fch[i]=__float2half(fc[i]);
    for (long i=idx; i<(long)NCMB*GD; i+=stride){
        int cmb=(int)(i/GD); int rp=(int)(i%GD);
        int q=(rp>>5)&3; int du=((rp>>7)<<5)|(rp&31);
        int r = q*256+du;
        s_b5[i]=bih[map5[cmb]*GD+r]+bhh[map5[cmb]*GD+r];
    }
}

// ---------------- init: x->fp16 (sorted) + h/c initial states ----------------
__global__ void init_k(const float* __restrict__ x,
                       const float* __restrict__ h0, const float* __restrict__ c0){
    long idx = (long)blockIdx.x*blockDim.x + threadIdx.x;
    long stride = (long)gridDim.x*blockDim.x;
    const int jmap[5]={0,0,1,2,3};
    for (long i=idx; i<(long)NT*(DM/4); i+=stride){
        int sn = (int)(i/(DM/4)); int d4 = (int)(i%(DM/4));
        int orig = s_ord[sn];
        float4 v = ((const float4*)x)[(long)orig*(DM/4)+d4];
        ((__half2*)s_x16)[((long)sn*DM + d4*4)>>1]     = __floats2half2_rn(v.x, v.y);
        ((__half2*)s_x16)[(((long)sn*DM + d4*4)>>1)+1] = __floats2half2_rn(v.z, v.w);
    }
    for (long i=idx; i<2L*NCMB*NT*DM; i+=stride){
        int cmb = (int)((i/((long)NT*DM))%NCMB); int d = (int)(i%DM);
        s_h16[i] = __float2half(h0[jmap[cmb]*DM+d]);
    }
    for (long i=idx; i<(long)NCMB*NT*DM; i+=stride){
        int cmb = (int)(i/((long)NT*DM)); int d = (int)(i%DM);
        s_c[i] = c0[jmap[cmb]*DM+d];
    }
}

// ---------------- gather child states (sorted, xseq k-major, + xlast) --------
__global__ void gather_k(const float* __restrict__ h_tensor,
                         const float* __restrict__ c_tensor,
                         const int*   __restrict__ indice){
    long i = (long)blockIdx.x*blockDim.x + threadIdx.x;
    if (i >= (long)NT*KC*(DM/4)) return;
    long nk = i / (DM/4);
    int  d4 = (int)(i % (DM/4));
    int sn = (int)(nk >> 4); int k = (int)(nk & 15);
    int orig = s_ord[sn];
    int id = indice[orig*KC+k]; if (id < 0) id = 0;
    float4 h = ((const float4*)h_tensor)[(long)id*(DM/4)+d4];
    ((float4*)s_cseq)[((long)sn*KC+k)*(DM/4)+d4] = ((const float4*)c_tensor)[(long)id*(DM/4)+d4];
    __half2 h01 = __floats2half2_rn(h.x, h.y);
    __half2 h23 = __floats2half2_rn(h.z, h.w);
    long xo = ((long)k*NT + sn)*DM + d4*4;
    ((__half2*)s_xseq16)[xo>>1]     = h01;
    ((__half2*)s_xseq16)[(xo>>1)+1] = h23;
    if (k == s_len[sn]-1){
        long lo = (long)sn*DM + d4*4;
        ((__half2*)s_xlast16)[lo>>1]     = h01;
        ((__half2*)s_xlast16)[(lo>>1)+1] = h23;
    }
}

__global__ void hb_k(const float* __restrict__ h0, const float* __restrict__ Whh,
                     const float* __restrict__ bih, const float* __restrict__ bhh){
    int idx = blockIdx.x*blockDim.x + threadIdx.x;
    if (idx >= 3*GD) return;
    int jb = idx/GD, o = idx%GD;
    int jd2 = 2*(jb+1)+1;
    const float* w = Whh + (long)jd2*GD*DM + (long)o*DM;
    const float* h = h0 + (jb+1)*DM;
    float acc=0.f;
    #pragma unroll 8
    for (int d=0; d<DM; d++) acc += h[d]*w[d];
    s_hb[idx] = acc + bih[jd2*GD+o] + bhh[jd2*GD+o];
}

// ---------------- shared GEMM plumbing ---------------------------------------
#define STR2 20                       // u32 per smem row (16 data + 4 pad)
#define AB_U32 (128*STR2)
#define ABUF(b) ((b)*AB_U32)
#define BBUF(b) (3*AB_U32 + (b)*AB_U32)
#define SMEM_SZ (6*AB_U32*4)          // 61440 bytes

#define LDSM_OFFSETS()                                                            \
    int aoff[4], boff[4];                                                         \
    {                                                                             \
        int rA = lane & 15;                                                       \
        int cA = (lane >> 4) << 2;                                                \
        _Pragma("unroll")                                                         \
        for (int mt=0; mt<4; mt++)                                                \
            aoff[mt] = ((wrw*64 + mt*16 + rA)*STR2 + cA)*4;                       \
        int rB = lane & 7;                                                        \
        int cB = ((lane >> 3) & 1) << 2;                                          \
        _Pragma("unroll")                                                         \
        for (int nt=0; nt<4; nt++)                                                \
            boff[nt] = ((wcw*32 + nt*8 + rB)*STR2 + cB)*4;                        \
    }

#define PRE16(Ab, Bb, Astride, Bstride, brow_, bcol_, rxor_, kb_, buf) do {       \
    long kb = (kb_);                                                              \
    _Pragma("unroll")                                                             \
    for (int l=0;l<2;l++){                                                        \
        int r = lrow4 + l*64;                                                     \
        long gr = ((brow_) + r) ^ (rxor_);                                        \
        uint32_t da = sbase + (ABUF(buf) + r*STR2)*4 + lq*16;                     \
        asm volatile("cp.async.cg.shared.global [%0],[%1],16;"                    \
                     :: "r"(da), "l"((Ab) + gr*(Astride) + kb + lq*8));           \
        uint32_t db = sbase + (BBUF(buf) + r*STR2)*4 + lq*16;                     \
        asm volatile("cp.async.cg.shared.global [%0],[%1],16;"                    \
                     :: "r"(db), "l"((Bb) + ((bcol_) + r)*(Bstride) + kb + lq*8)); \
    }                                                                             \
    asm volatile("cp.async.commit_group;");                                       \
} while(0)

#define MAINLOOP_CHUNK(cb)  do {                                                  \
    uint32_t baA = sbase + (ABUF(cb))*4;                                          \
    uint32_t baB = sbase + (BBUF(cb))*4;                                          \
    _Pragma("unroll")                                                             \
    for (int ks = 0; ks < 2; ks++){                                               \
        uint32_t af[4][4], bf[4][2];                                              \
        _Pragma("unroll")                                                         \
        for (int mt=0; mt<4; mt++)                                                \
            ldsm_x4(af[mt][0],af[mt][1],af[mt][2],af[mt][3],                      \
                    baA + ks*32 + aoff[mt]);                                      \
        _Pragma("unroll")                                                         \
        for (int nt=0; nt<4; nt++)                                                \
            ldsm_x2(bf[nt][0],bf[nt][1], baB + ks*32 + boff[nt]);                 \
        _Pragma("unroll")                                                         \
        for (int mt=0; mt<4; mt++)                                                \
            _Pragma("unroll")                                                     \
            for (int nt=0; nt<4; nt++)                                            \
                mma_f16(acc[mt][nt], af[mt][0],af[mt][1],af[mt][2],af[mt][3],     \
                        bf[nt][0], bf[nt][1]);                                    \
    }                                                                             \
} while(0)

// ---------------- generic fp16 GEMM (non-recurrent launches) -----------------
__global__ void __launch_bounds__(256,2) gemm_h(
    const __half* __restrict__ A, long aBatch,
    const __half* __restrict__ B, long bBatch,
    const float* __restrict__ bias, long biasBatch,
    float* __restrict__ CF, __half* __restrict__ CH, long cBatch, int cRow,
    int M, int N, int K, int xorZ, int xorVal,
    const int* __restrict__ exCnt, int exitKind)
{
    int z = blockIdx.z;
    long brow = (long)blockIdx.y * 128;
    if (exitKind == 1){
        int k = (int)(brow >> 12);
        int w = (int)(brow & 4095);
        int lim = (z==xorZ) ? exCnt[15-k] : exCnt[k];
        if (w >= lim) return;
    }
    extern __shared__ uint32_t sm[];
    uint32_t sbase;
    asm("{ .reg .u64 t; cvta.to.shared.u64 t, %1; cvt.u32.u64 %0, t; }"
        : "=r"(sbase) : "l"(sm));
    int tid = threadIdx.x;
    int wid = tid >> 5, lane = tid & 31;
    int gq = lane >> 2, tq = lane & 3;
    int wrw = wid >> 2, wcw = wid & 3;
    int lrow4 = tid >> 2, lq = tid & 3;
    LDSM_OFFSETS();

    const __half* Ab = A + (long)z*aBatch;
    const __half* Bb = B + (long)z*bBatch;
    long rxor = (z==xorZ) ? xorVal : 0;
    long bcol = (long)blockIdx.x * 128;

    float4 acc[4][4];
    #pragma unroll
    for (int i=0;i<4;i++)
        #pragma unroll
        for (int j=0;j<4;j++) acc[i][j] = make_float4(0.f,0.f,0.f,0.f);

    int nCh = K >> 5;
    PRE16(Ab, Bb, K, K, brow, bcol, rxor, 0L, 0);
    if (nCh > 1) PRE16(Ab, Bb, K, K, brow, bcol, rxor, 32L, 1);
    for (int i = 0; i < nCh; i++){
        if (i + 1 < nCh) asm volatile("cp.async.wait_group 1;" ::: "memory");
        else             asm volatile("cp.async.wait_group 0;" ::: "memory");
        __syncthreads();
        MAINLOOP_CHUNK(i % 3);
        if (i + 2 < nCh){
            PRE16(Ab, Bb, K, K, brow, bcol, rxor, (long)(i+2)*32, (i + 2) % 3);
        }
    }

    const float* biasb = bias ? bias + (long)z*biasBatch : (const float*)0;
    #pragma unroll
    for (int mt=0; mt<4; mt++){
        long row0 = brow + wrw*64 + mt*16 + gq;
        #pragma unroll
        for (int nt=0; nt<4; nt++){
            long col = bcol + wcw*32 + nt*8 + 2*tq;
            float2 v0 = make_float2(acc[mt][nt].x, acc[mt][nt].y);
            float2 v1 = make_float2(acc[mt][nt].z, acc[mt][nt].w);
            if (biasb){
                v0.x += biasb[col];   v0.y += biasb[col+1];
                v1.x += biasb[col];   v1.y += biasb[col+1];
            }
            if (CH){
                __half* Cb = CH + (long)z*cBatch;
                *reinterpret_cast<__half2*>(&Cb[row0*cRow + col])     = __floats2half2_rn(v0.x, v0.y);
                *reinterpret_cast<__half2*>(&Cb[(row0+8)*cRow + col]) = __floats2half2_rn(v1.x, v1.y);
            } else {
                float* Cb = CF + (long)z*cBatch;
                *reinterpret_cast<float2*>(&Cb[row0*cRow + col])     = v0;
                *reinterpret_cast<float2*>(&Cb[(row0+8)*cRow + col]) = v1;
            }
        }
    }
}

// -------- persistent recurrence kernel: K=512 fused (h@Whh + xseq@Wih) --------
__global__ void __launch_bounds__(256,2) rec_k(){
    extern __shared__ uint32_t sm[];
    __half* gs = (__half*)sm;          // 128 x 132 fp16 staging (33792 B)
    uint32_t sbase;
    asm("{ .reg .u64 t; cvta.to.shared.u64 t, %1; cvt.u32.u64 %0, t; }"
        : "=r"(sbase) : "l"(sm));
    int tid = threadIdx.x;
    int wid = tid >> 5, lane = tid & 31;
    int gq = lane >> 2, tq = lane & 3;
    int wrw = wid >> 2, wcw = wid & 3;
    int lrow4 = tid >> 2, lq = tid & 3;
    LDSM_OFFSETS();

    for (int s = 0; s < KC; s++){
        int rdb = s & 1, wrb = rdb ^ 1;
        int lim[5], base[6];
        base[0] = 0;
        #pragma unroll
        for (int c=0;c<5;c++){
            lim[c] = (c==1) ? s_cntF[15-s] : s_cntF[s];
            base[c+1] = base[c] + (((lim[c]+127)>>7) << 3);
        }
        int T = base[5];
        for (int tile = blockIdx.x; tile < T; tile += NCTA){
            int c = 0;
            #pragma unroll
            for (int cc=0;cc<4;cc++) if (tile >= base[cc+1]) c = cc+1;
            int idx = tile - base[c];
            int rowTile = idx >> 3, colTile = idx & 7;
            long brow = (long)rowTile << 7;
            long bcol = (long)colTile << 7;
            const __half* Ah = s_h16 + ((long)rdb*NCMB + c)*NT*DM;
            const __half* Bh = s_Whh5h + (long)c*GD*DM;
            int kx = (c==1) ? 15-s : s;
            const __half* Ax = s_xseq16 + (long)kx*NT*DM;
            const __half* Bx = s_Wih5h + (long)c*GD*DM;
            const float* biasb = s_b5 + c*GD;

            float4 acc[4][4];
            #pragma unroll
            for (int i=0;i<4;i++)
                #pragma unroll
                for (int j=0;j<4;j++) acc[i][j] = make_float4(0.f,0.f,0.f,0.f);

            // 16 K-chunks: 0-7 = h@Whh, 8-15 = xseq[kx]@Wih
            #define PRER(ch, buf) do {                                            \
                if ((ch) < 8) PRE16(Ah, Bh, DM, DM, brow, bcol, 0L,               \
                                    (long)(ch)*32, buf);                          \
                else          PRE16(Ax, Bx, DM, DM, brow, bcol, 0L,               \
                                    (long)((ch)-8)*32, buf);                      \
            } while(0)

            PRER(0, 0);
            PRER(1, 1);
            #pragma unroll
            for (int i = 0; i < 16; i++){
                if (i < 15) asm volatile("cp.async.wait_group 1;" ::: "memory");
                else        asm volatile("cp.async.wait_group 0;" ::: "memory");
                __syncthreads();
                MAINLOOP_CHUNK(i % 3);
                if (i + 2 < 16) PRER(i + 2, (i + 2) % 3);
            }
            #undef PRER
            __syncthreads();   // ring smem free before gs staging

            // stage gate preactivations (acc + bias) into smem fp16
            #pragma unroll
            for (int mt=0; mt<4; mt++){
                int lr0 = wrw*64 + mt*16 + gq;
                #pragma unroll
                for (int nt=0; nt<4; nt++){
                    int lcol = wcw*32 + nt*8 + 2*tq;
                    long col = bcol + lcol;
                    float b0 = biasb[col], b1 = biasb[col+1];
                    *reinterpret_cast<__half2*>(&gs[lr0*132 + lcol]) =
                        __floats2half2_rn(acc[mt][nt].x + b0, acc[mt][nt].y + b1);
                    *reinterpret_cast<__half2*>(&gs[(lr0+8)*132 + lcol]) =
                        __floats2half2_rn(acc[mt][nt].z + b0, acc[mt][nt].w + b1);
                }
            }
            __syncthreads();

            // fused LSTM gates: 128 rows x 32 units, half2 over units
            #pragma unroll
            for (int it=0; it<8; it++){
                int idx2 = tid + it*256;
                int row = idx2 >> 4, up = idx2 & 15;
                int u = up*2;
                int n = (int)brow + row;
                if (n >= lim[c]) continue;
                int d = (colTile<<5) + u;
                float2 gi = __half22float2(*reinterpret_cast<const __half2*>(&gs[row*132 + u]));
                float2 gf = __half22float2(*reinterpret_cast<const __half2*>(&gs[row*132 + 32 + u]));
                float2 gu = __half22float2(*reinterpret_cast<const __half2*>(&gs[row*132 + 64 + u]));
                float2 go = __half22float2(*reinterpret_cast<const __half2*>(&gs[row*132 + 96 + u]));
                long ist = ((long)c*NT + n)*DM + d;
                float2 cp = *reinterpret_cast<const float2*>(&s_c[ist]);
                float2 cn, hn;
                cn.x = sigf(gf.x)*cp.x + sigf(gi.x)*tanhf(gu.x);
                cn.y = sigf(gf.y)*cp.y + sigf(gi.y)*tanhf(gu.y);
                hn.x = sigf(go.x)*tanhf(cn.x);
                hn.y = sigf(go.y)*tanhf(cn.y);
                *reinterpret_cast<float2*>(&s_c[ist]) = cn;
                __half2 hn2 = __floats2half2_rn(hn.x, hn.y);
                *reinterpret_cast<__half2*>(&s_h16[((long)wrb*NCMB + c)*NT*DM + (long)n*DM + d]) = hn2;
                if (c == 0)
                    *reinterpret_cast<__half2*>(&s_ycat016[((long)s*NT+n)*(2*DM) + d]) = hn2;
                else if (c == 1)
                    *reinterpret_cast<__half2*>(&s_ycat016[((long)(15-s)*NT+n)*(2*DM) + DM + d]) = hn2;
                else if (s == s_len[n]-1)
                    *reinterpret_cast<__half2*>(&s_ylcat16[((long)(c-2)*NT+n)*(2*DM) + d]) = hn2;
            }
            __syncthreads();   // protect gs before next tile's prefetch
        }
        grid_barrier();
    }
}

// ---------------- one-step backward gates (j=1..3, original layout) ----------
__global__ void gates_last(const float* __restrict__ c0){
    long i = (long)blockIdx.x*blockDim.x + threadIdx.x;
    if (i >= 3L*NT*(DM/2)) return;
    int jb = (int)(i/((long)NT*(DM/2)));
    long nd = i%((long)NT*(DM/2));
    int n = (int)(nd/(DM/2)), d2 = (int)(nd%(DM/2));
    int d = d2*2;
    const __half2* g = (const __half2*)(s_gB16 + (long)jb*NT*GD + (long)n*GD);
    float2 gi = __half22float2(g[d2]);
    float2 gf = __half22float2(g[(DM>>1)+d2]);
    float2 gu = __half22float2(g[DM+d2]);
    float2 go = __half22float2(g[((3*DM)>>1)+d2]);
    float2 cp = *reinterpret_cast<const float2*>(&c0[(jb+1)*DM+d]);
    float2 hn;
    float cnx = sigf(gf.x)*cp.x + sigf(gi.x)*tanhf(gu.x);
    float cny = sigf(gf.y)*cp.y + sigf(gi.y)*tanhf(gu.y);
    hn.x = sigf(go.x)*tanhf(cnx);
    hn.y = sigf(go.y)*tanhf(cny);
    *reinterpret_cast<__half2*>(&s_ylcat16[((long)jb*NT+n)*(2*DM) + DM + d]) = __floats2half2_rn(hn.x, hn.y);
}

__global__ void final_k(float* __restrict__ out){
    int n = blockIdx.x, d = threadIdx.x;   // n = sorted slot
    int orig = s_ord[n];
    float wf = s_Wx[(long)n*GD + d];
    float wi = s_Wx[(long)n*GD + DM + d];
    float wu = s_Wx[(long)n*GD + 2*DM + d];
    float wo = s_Wx[(long)n*GD + 3*DM + d];
    int len = s_len[n];
    float bf = 0.f;
    for (int k=0;k<len;k++){
        float y  = __half2float(s_ys016[((long)k*NT+n)*DM + d]);
        float cc = s_cseq[((long)n*KC+k)*DM + d];
        bf += sigf(wf + y) * cc;
    }
    float bi = sigf (__half2float(s_ysl16[0L*NT*DM + (long)n*DM + d]) + wi);
    float bu = tanhf(__half2float(s_ysl16[1L*NT*DM + (long)n*DM + d]) + wu);
    float bo = sigf (__half2float(s_ysl16[2L*NT*DM + (long)n*DM + d]) + wo);
    float ncv = bi*bu + bf;
    float nhv = bo*tanhf(ncv);
    out[(long)orig*DM + d] = nhv;
    out[(long)NT*DM + (long)orig*DM + d] = ncv;
}

// =============================================================================
extern "C" void kernel_launch(void* const* d_in, const int* in_sizes, int n_in,
                              void* d_out, int out_size) {
    const float* x        = (const float*)d_in[0];
    const float* h_tensor = (const float*)d_in[1];
    const float* c_tensor = (const float*)d_in[2];
    const int*   indice   = (const int*)  d_in[3];
    const float* W_w      = (const float*)d_in[4];
    const float* W_b      = (const float*)d_in[5];
    const float* h0       = (const float*)d_in[6];
    const float* c0       = (const float*)d_in[7];
    const float* Wih      = (const float*)d_in[8];
    const float* Whh      = (const float*)d_in[9];
    const float* bih      = (const float*)d_in[10];
    const float* bhh      = (const float*)d_in[11];
    const float* fc       = (const float*)d_in[12];
    float* out = (float*)d_out;

    __half *p_x16,*p_xlast16,*p_WihBh,*p_Wwh,*p_fch,
           *p_ycat016,*p_ylcat16,*p_gB16,*p_ys016,*p_ysl16;
    float *p_hb,*p_Wx;
    int *p_cntF;
    cudaGetSymbolAddress((void**)&p_x16,     s_x16);
    cudaGetSymbolAddress((void**)&p_xlast16, s_xlast16);
    cudaGetSymbolAddress((void**)&p_WihBh,   s_WihBh);
    cudaGetSymbolAddress((void**)&p_Wwh,     s_Wwh);
    cudaGetSymbolAddress((void**)&p_fch,     s_fch);
    cudaGetSymbolAddress((void**)&p_ycat016, s_ycat016);
    cudaGetSymbolAddress((void**)&p_ylcat16, s_ylcat16);
    cudaGetSymbolAddress((void**)&p_gB16,    s_gB16);
    cudaGetSymbolAddress((void**)&p_ys016,   s_ys016);
    cudaGetSymbolAddress((void**)&p_ysl16,   s_ysl16);
    cudaGetSymbolAddress((void**)&p_hb,      s_hb);
    cudaGetSymbolAddress((void**)&p_Wx,      s_Wx);
    cudaGetSymbolAddress((void**)&p_cntF,    s_cntF);
    (void)in_sizes; (void)n_in; (void)out_size;

    cudaFuncSetAttribute(gemm_h, cudaFuncAttributeMaxDynamicSharedMemorySize, SMEM_SZ);
    cudaFuncSetAttribute(rec_k,  cudaFuncAttributeMaxDynamicSharedMemorySize, SMEM_SZ);

    // 1) sort, pack/convert weights (interleaved), init states, gather(+xlast)
    sort_k<<<1,256>>>(indice);
    prep_weights<<<1024,256>>>(Wih,Whh,bih,bhh,W_w,fc);
    init_k<<<2048,256>>>(x,h0,c0);
    gather_k<<<(int)(((long)NT*KC*(DM/4))/256),256>>>(h_tensor,c_tensor,indice);
    hb_k<<<12,256>>>(h0,Whh,bih,bhh);

    // 2) Wx = x @ W_w^T + W_b   (sorted rows, original cols) -> fp32
    gemm_h<<<dim3(GD/128, NT/128, 1),256,SMEM_SZ>>>(
        p_x16,0, p_Wwh,0, W_b,0,
        p_Wx,(__half*)0,0,GD, NT,GD,DM, -1,0, (const int*)0,0);

    // 3) the 16-step recurrence: ONE persistent kernel, x-part + gates fused
    rec_k<<<NCTA,256,SMEM_SZ>>>();

    // 4) backward one-step for j=1..3 -> fp16 (original layout)
    gemm_h<<<dim3(GD/128, NT/128, 3),256,SMEM_SZ>>>(
        p_xlast16,0, p_WihBh,(long)GD*DM, p_hb,(long)GD,
        (float*)0,p_gB16,(long)NT*GD,GD, NT,GD,DM, -1,0, (const int*)0,0);
    gates_last<<<(int)((3L*NT*(DM/2)+255)/256),256>>>(c0);

    // 5) fc projections -> fp16 (ycat0 k-major; skip k>=len)
    gemm_h<<<dim3(DM/128, (NT*KC)/128, 1),256,SMEM_SZ>>>(
        p_ycat016,0, p_fch,0, (const float*)0,0,
        (float*)0,p_ys016,0,DM, NT*KC,DM,2*DM, -1,0, p_cntF,1);
    gemm_h<<<dim3(DM/128, NT/128, 3),256,SMEM_SZ>>>(
        p_ylcat16,(long)NT*2*DM, p_fch + (long)DM*2*DM,(long)DM*2*DM,
        (const float*)0,0,
        (float*)0,p_ysl16,(long)NT*DM,DM, NT,DM,2*DM, -1,0, (const int*)0,0);

    // 6) final combine -> (new_h, new_c), un-permuted
    final_k<<<NT,DM>>>(out);
}

// round 12
// speedup vs baseline: 5.1629x; 1.0389x over previous
#include <cuda_runtime.h>
#include <cuda_fp16.h>
#include <math.h>
#include <stdint.h>

#define NT   4096      // trees
#define KC   16        // children
#define DM   256       // DOUT
#define GD   1024      // 4*DOUT
#define NCMB 5         // recurrent combos: (j0,f),(j0,b),(j1,f),(j2,f),(j3,f)
#define NCTA 296       // persistent grid: 2 CTAs x 148 SMs

// ---------------- scratch (device globals; no allocations allowed) ----------
__device__ __align__(16) __half s_x16   [(long)NT*DM];
__device__ __align__(16) __half s_xseq16[(long)NT*KC*DM];   // k-major: [k*NT+n][DM]
__device__ __align__(16) __half s_xlast16[(long)NT*DM];
__device__ __align__(16) __half s_Wih5h [(long)NCMB*GD*DM]; // gate-interleaved
__device__ __align__(16) __half s_Whh5h [(long)NCMB*GD*DM]; // gate-interleaved
__device__ __align__(16) __half s_WihBh [3L*GD*DM];         // original order
__device__ __align__(16) __half s_Wwh   [(long)GD*DM];
__device__ __align__(16) __half s_fch   [4L*DM*2*DM];
__device__ __align__(16) __half s_h16   [2L*NCMB*NT*DM];    // double-buffered
__device__ __align__(16) __half s_ycat016[(long)NT*KC*2*DM]; // k-major rows
__device__ __align__(16) __half s_ylcat16[3L*NT*2*DM];
__device__ __align__(16) __half s_gB16  [3L*NT*GD];
__device__ __align__(16) __half s_ys016 [(long)NT*KC*DM];
__device__ __align__(16) __half s_ysl16 [3L*NT*DM];
__device__ float s_cseq [(long)NT*KC*DM];
__device__ int   s_len  [NT];        // sorted (descending)
__device__ int   s_ord  [NT];
__device__ int   s_lenOrig[NT];
__device__ int   s_cntF [17];        // cntF[s] = #trees with len > s
__device__ float s_b5   [NCMB*GD];   // gate-interleaved
__device__ float s_hb   [3*GD];
__device__ float s_c    [(long)NCMB*NT*DM];
__device__ float s_Wx   [(long)NT*GD];
// dependency-queue state (reset each launch in sort_k)
__device__ int s_tileBase[16*NCMB+1];  // cumulative tiles per (s,c); [80] = total
__device__ int s_firstStepB[32];       // bwd combo: first active step per rowTile
__device__ int s_dep[NCMB*32];         // completed col-tiles per (combo,rowTile)
__device__ int g_qHead;

__device__ __forceinline__ float sigf(float x){ return 1.f/(1.f+expf(-x)); }

__device__ __forceinline__ void mma_f16(float4& c,
        uint32_t a0, uint32_t a1, uint32_t a2, uint32_t a3,
        uint32_t b0, uint32_t b1){
    asm volatile(
        "mma.sync.aligned.m16n8k16.row.col.f32.f16.f16.f32 "
        "{%0,%1,%2,%3}, {%4,%5,%6,%7}, {%8,%9}, {%0,%1,%2,%3};"
        : "+f"(c.x), "+f"(c.y), "+f"(c.z), "+f"(c.w)
        : "r"(a0), "r"(a1), "r"(a2), "r"(a3), "r"(b0), "r"(b1));
}

__device__ __forceinline__ void ldsm_x4(uint32_t& r0, uint32_t& r1,
                                        uint32_t& r2, uint32_t& r3, uint32_t addr){
    asm volatile("ldmatrix.sync.aligned.m8n8.x4.shared.b16 {%0,%1,%2,%3}, [%4];"
                 : "=r"(r0),"=r"(r1),"=r"(r2),"=r"(r3) : "r"(addr));
}
__device__ __forceinline__ void ldsm_x2(uint32_t& r0, uint32_t& r1, uint32_t addr){
    asm volatile("ldmatrix.sync.aligned.m8n8.x2.shared.b16 {%0,%1}, [%2];"
                 : "=r"(r0),"=r"(r1) : "r"(addr));
}

// ---------------- sort + queue-table build -----------------------------------
__global__ void sort_k(const int* __restrict__ indice){
    __shared__ int hist[17];
    __shared__ int binCur[17];
    int tid = threadIdx.x;
    if (tid < 17) hist[tid]=0;
    __syncthreads();
    for (int n=tid; n<NT; n+=blockDim.x){
        int l=0;
        #pragma unroll
        for (int k=0;k<KC;k++) if (indice[n*KC+k]!=-1) l++;
        s_lenOrig[n]=l;
        atomicAdd(&hist[l],1);
    }
    __syncthreads();
    if (tid==0){
        int run=0;
        for (int l=16;l>=1;l--){ binCur[l]=run; run+=hist[l]; }
        int c=0;
        s_cntF[16]=0;
        for (int s=15;s>=0;s--){ c += hist[s+1]; s_cntF[s]=c; }
        g_qHead = 0;
        // tile base table (ordered by step, then combo)
        int tb=0; s_tileBase[0]=0;
        for (int i=0;i<16*NCMB;i++){
            int s=i/NCMB, cc=i%NCMB;
            int lim = (cc==1)? s_cntF[15-s] : s_cntF[s];
            tb += ((lim+127)>>7)<<3;
            s_tileBase[i+1]=tb;
        }
        // bwd combo first active step per rowTile
        for (int r=0;r<32;r++){
            int fs=16;
            for (int s=0;s<16;s++) if (s_cntF[15-s] > 128*r){ fs=s; break; }
            s_firstStepB[r]=fs;
        }
    }
    if (tid < NCMB*32) s_dep[tid]=0;
    __syncthreads();
    for (int n=tid; n<NT; n+=blockDim.x){
        int l=s_lenOrig[n];
        int pos=atomicAdd(&binCur[l],1);
        s_ord[pos]=n;
        s_len[pos]=l;
    }
}

// ---------------- prep: pack + convert weights (gate-interleaved) -----------
__global__ void prep_weights(const float* __restrict__ Wih, const float* __restrict__ Whh,
                             const float* __restrict__ bih, const float* __restrict__ bhh,
                             const float* __restrict__ W_w, const float* __restrict__ fc){
    const int map5[5]={0,1,2,4,6};
    const int mapB[3]={3,5,7};
    long idx = (long)blockIdx.x*blockDim.x + threadIdx.x;
    long stride = (long)gridDim.x*blockDim.x;
    for (long i=idx; i<(long)NCMB*GD*DM; i+=stride){
        int cmb = (int)(i/((long)GD*DM)); long rem = i%((long)GD*DM);
        int rp = (int)(rem/DM); int kcol = (int)(rem%DM);
        int q = (rp>>5)&3; int du = ((rp>>7)<<5)|(rp&31);
        long src = (long)map5[cmb]*GD*DM + (long)(q*256+du)*DM + kcol;
        s_Wih5h[i]=__float2half(Wih[src]);
        s_Whh5h[i]=__float2half(Whh[src]);
    }
    for (long i=idx; i<3L*GD*DM; i+=stride){
        int jb = (int)(i/((long)GD*DM)); long r = i%((long)GD*DM);
        s_WihBh[i]=__float2half(Wih[(long)mapB[jb]*GD*DM + r]);
    }
    for (long i=idx; i<(long)GD*DM; i+=stride)
        s_Wwh[i]=__float2half(W_w[i]);
    for (long i=idx; i<4L*DM*2*DM; i+=stride)
        s_fch[i]=__float2half(fc[i]);
    for (long i=idx; i<(long)NCMB*GD; i+=stride){
        int cmb=(int)(i/GD); int rp=(int)(i%GD);
        int q=(rp>>5)&3; int du=((rp>>7)<<5)|(rp&31);
        int r = q*256+du;
        s_b5[i]=bih[map5[cmb]*GD+r]+bhh[map5[cmb]*GD+r];
    }
}

// ---------------- init: x->fp16 (sorted) + h/c initial states ----------------
__global__ void init_k(const float* __restrict__ x,
                       const float* __restrict__ h0, const float* __restrict__ c0){
    long idx = (long)blockIdx.x*blockDim.x + threadIdx.x;
    long stride = (long)gridDim.x*blockDim.x;
    const int jmap[5]={0,0,1,2,3};
    for (long i=idx; i<(long)NT*(DM/4); i+=stride){
        int sn = (int)(i/(DM/4)); int d4 = (int)(i%(DM/4));
        int orig = s_ord[sn];
        float4 v = ((const float4*)x)[(long)orig*(DM/4)+d4];
        ((__half2*)s_x16)[((long)sn*DM + d4*4)>>1]     = __floats2half2_rn(v.x, v.y);
        ((__half2*)s_x16)[(((long)sn*DM + d4*4)>>1)+1] = __floats2half2_rn(v.z, v.w);
    }
    for (long i=idx; i<2L*NCMB*NT*DM; i+=stride){
        int cmb = (int)((i/((long)NT*DM))%NCMB); int d = (int)(i%DM);
        s_h16[i] = __float2half(h0[jmap[cmb]*DM+d]);
    }
    for (long i=idx; i<(long)NCMB*NT*DM; i+=stride){
        int cmb = (int)(i/((long)NT*DM)); int d = (int)(i%DM);
        s_c[i] = c0[jmap[cmb]*DM+d];
    }
}

// ---------------- gather child states (sorted, xseq k-major, + xlast) --------
__global__ void gather_k(const float* __restrict__ h_tensor,
                         const float* __restrict__ c_tensor,
                         const int*   __restrict__ indice){
    long i = (long)blockIdx.x*blockDim.x + threadIdx.x;
    if (i >= (long)NT*KC*(DM/4)) return;
    long nk = i / (DM/4);
    int  d4 = (int)(i % (DM/4));
    int sn = (int)(nk >> 4); int k = (int)(nk & 15);
    int orig = s_ord[sn];
    int id = indice[orig*KC+k]; if (id < 0) id = 0;
    float4 h = ((const float4*)h_tensor)[(long)id*(DM/4)+d4];
    ((float4*)s_cseq)[((long)sn*KC+k)*(DM/4)+d4] = ((const float4*)c_tensor)[(long)id*(DM/4)+d4];
    __half2 h01 = __floats2half2_rn(h.x, h.y);
    __half2 h23 = __floats2half2_rn(h.z, h.w);
    long xo = ((long)k*NT + sn)*DM + d4*4;
    ((__half2*)s_xseq16)[xo>>1]     = h01;
    ((__half2*)s_xseq16)[(xo>>1)+1] = h23;
    if (k == s_len[sn]-1){
        long lo = (long)sn*DM + d4*4;
        ((__half2*)s_xlast16)[lo>>1]     = h01;
        ((__half2*)s_xlast16)[(lo>>1)+1] = h23;
    }
}

__global__ void hb_k(const float* __restrict__ h0, const float* __restrict__ Whh,
                     const float* __restrict__ bih, const float* __restrict__ bhh){
    int idx = blockIdx.x*blockDim.x + threadIdx.x;
    if (idx >= 3*GD) return;
    int jb = idx/GD, o = idx%GD;
    int jd2 = 2*(jb+1)+1;
    const float* w = Whh + (long)jd2*GD*DM + (long)o*DM;
    const float* h = h0 + (jb+1)*DM;
    float acc=0.f;
    #pragma unroll 8
    for (int d=0; d<DM; d++) acc += h[d]*w[d];
    s_hb[idx] = acc + bih[jd2*GD+o] + bhh[jd2*GD+o];
}

// ---------------- shared GEMM plumbing ---------------------------------------
#define STR2 20                       // u32 per smem row (16 data + 4 pad)
#define AB_U32 (128*STR2)
#define ABUF(b) ((b)*AB_U32)
#define BBUF(b) (3*AB_U32 + (b)*AB_U32)
#define SMEM_SZ (6*AB_U32*4)          // 61440 bytes

#define LDSM_OFFSETS()                                                            \
    int aoff[4], boff[4];                                                         \
    {                                                                             \
        int rA = lane & 15;                                                       \
        int cA = (lane >> 4) << 2;                                                \
        _Pragma("unroll")                                                         \
        for (int mt=0; mt<4; mt++)                                                \
            aoff[mt] = ((wrw*64 + mt*16 + rA)*STR2 + cA)*4;                       \
        int rB = lane & 7;                                                        \
        int cB = ((lane >> 3) & 1) << 2;                                          \
        _Pragma("unroll")                                                         \
        for (int nt=0; nt<4; nt++)                                                \
            boff[nt] = ((wcw*32 + nt*8 + rB)*STR2 + cB)*4;                        \
    }

#define PRE16(Ab, Bb, Astride, Bstride, brow_, bcol_, rxor_, kb_, buf) do {       \
    long kb = (kb_);                                                              \
    _Pragma("unroll")                                                             \
    for (int l=0;l<2;l++){                                                        \
        int r = lrow4 + l*64;                                                     \
        long gr = ((brow_) + r) ^ (rxor_);                                        \
        uint32_t da = sbase + (ABUF(buf) + r*STR2)*4 + lq*16;                     \
        asm volatile("cp.async.cg.shared.global [%0],[%1],16;"                    \
                     :: "r"(da), "l"((Ab) + gr*(Astride) + kb + lq*8));           \
        uint32_t db = sbase + (BBUF(buf) + r*STR2)*4 + lq*16;                     \
        asm volatile("cp.async.cg.shared.global [%0],[%1],16;"                    \
                     :: "r"(db), "l"((Bb) + ((bcol_) + r)*(Bstride) + kb + lq*8)); \
    }                                                                             \
    asm volatile("cp.async.commit_group;");                                       \
} while(0)

#define MAINLOOP_CHUNK(cb)  do {                                                  \
    uint32_t baA = sbase + (ABUF(cb))*4;                                          \
    uint32_t baB = sbase + (BBUF(cb))*4;                                          \
    _Pragma("unroll")                                                             \
    for (int ks = 0; ks < 2; ks++){                                               \
        uint32_t af[4][4], bf[4][2];                                              \
        _Pragma("unroll")                                                         \
        for (int mt=0; mt<4; mt++)                                                \
            ldsm_x4(af[mt][0],af[mt][1],af[mt][2],af[mt][3],                      \
                    baA + ks*32 + aoff[mt]);                                      \
        _Pragma("unroll")                                                         \
        for (int nt=0; nt<4; nt++)                                                \
            ldsm_x2(bf[nt][0],bf[nt][1], baB + ks*32 + boff[nt]);                 \
        _Pragma("unroll")                                                         \
        for (int mt=0; mt<4; mt++)                                                \
            _Pragma("unroll")                                                     \
            for (int nt=0; nt<4; nt++)                                            \
                mma_f16(acc[mt][nt], af[mt][0],af[mt][1],af[mt][2],af[mt][3],     \
                        bf[nt][0], bf[nt][1]);                                    \
    }                                                                             \
} while(0)

// ---------------- generic fp16 GEMM (non-recurrent launches) -----------------
__global__ void __launch_bounds__(256,2) gemm_h(
    const __half* __restrict__ A, long aBatch,
    const __half* __restrict__ B, long bBatch,
    const float* __restrict__ bias, long biasBatch,
    float* __restrict__ CF, __half* __restrict__ CH, long cBatch, int cRow,
    int M, int N, int K, int xorZ, int xorVal,
    const int* __restrict__ exCnt, int exitKind)
{
    int z = blockIdx.z;
    long brow = (long)blockIdx.y * 128;
    if (exitKind == 1){
        int k = (int)(brow >> 12);
        int w = (int)(brow & 4095);
        int lim = (z==xorZ) ? exCnt[15-k] : exCnt[k];
        if (w >= lim) return;
    }
    extern __shared__ uint32_t sm[];
    uint32_t sbase;
    asm("{ .reg .u64 t; cvta.to.shared.u64 t, %1; cvt.u32.u64 %0, t; }"
        : "=r"(sbase) : "l"(sm));
    int tid = threadIdx.x;
    int wid = tid >> 5, lane = tid & 31;
    int gq = lane >> 2, tq = lane & 3;
    int wrw = wid >> 2, wcw = wid & 3;
    int lrow4 = tid >> 2, lq = tid & 3;
    LDSM_OFFSETS();

    const __half* Ab = A + (long)z*aBatch;
    const __half* Bb = B + (long)z*bBatch;
    long rxor = (z==xorZ) ? xorVal : 0;
    long bcol = (long)blockIdx.x * 128;

    float4 acc[4][4];
    #pragma unroll
    for (int i=0;i<4;i++)
        #pragma unroll
        for (int j=0;j<4;j++) acc[i][j] = make_float4(0.f,0.f,0.f,0.f);

    int nCh = K >> 5;
    PRE16(Ab, Bb, K, K, brow, bcol, rxor, 0L, 0);
    if (nCh > 1) PRE16(Ab, Bb, K, K, brow, bcol, rxor, 32L, 1);
    for (int i = 0; i < nCh; i++){
        if (i + 1 < nCh) asm volatile("cp.async.wait_group 1;" ::: "memory");
        else             asm volatile("cp.async.wait_group 0;" ::: "memory");
        __syncthreads();
        MAINLOOP_CHUNK(i % 3);
        if (i + 2 < nCh){
            PRE16(Ab, Bb, K, K, brow, bcol, rxor, (long)(i+2)*32, (i + 2) % 3);
        }
    }

    const float* biasb = bias ? bias + (long)z*biasBatch : (const float*)0;
    #pragma unroll
    for (int mt=0; mt<4; mt++){
        long row0 = brow + wrw*64 + mt*16 + gq;
        #pragma unroll
        for (int nt=0; nt<4; nt++){
            long col = bcol + wcw*32 + nt*8 + 2*tq;
            float2 v0 = make_float2(acc[mt][nt].x, acc[mt][nt].y);
            float2 v1 = make_float2(acc[mt][nt].z, acc[mt][nt].w);
            if (biasb){
                v0.x += biasb[col];   v0.y += biasb[col+1];
                v1.x += biasb[col];   v1.y += biasb[col+1];
            }
            if (CH){
                __half* Cb = CH + (long)z*cBatch;
                *reinterpret_cast<__half2*>(&Cb[row0*cRow + col])     = __floats2half2_rn(v0.x, v0.y);
                *reinterpret_cast<__half2*>(&Cb[(row0+8)*cRow + col]) = __floats2half2_rn(v1.x, v1.y);
            } else {
                float* Cb = CF + (long)z*cBatch;
                *reinterpret_cast<float2*>(&Cb[row0*cRow + col])     = v0;
                *reinterpret_cast<float2*>(&Cb[(row0+8)*cRow + col]) = v1;
            }
        }
    }
}

// -------- persistent recurrence: work queue + per-(combo,rowTile) deps --------
__global__ void __launch_bounds__(256,2) rec_k(){
    extern __shared__ uint32_t sm[];
    __half* gs = (__half*)sm;          // 128 x 132 fp16 staging
    __shared__ int sh4[4];             // decoded (s,c,r,col)
    uint32_t sbase;
    asm("{ .reg .u64 t; cvta.to.shared.u64 t, %1; cvt.u32.u64 %0, t; }"
        : "=r"(sbase) : "l"(sm));
    int tid = threadIdx.x;
    int wid = tid >> 5, lane = tid & 31;
    int gq = lane >> 2, tq = lane & 3;
    int wrw = wid >> 2, wcw = wid & 3;
    int lrow4 = tid >> 2, lq = tid & 3;
    LDSM_OFFSETS();

    int total = s_tileBase[16*NCMB];

    while (true){
        if (tid == 0){
            int t = atomicAdd(&g_qHead, 1);
            int ss=-1, cc=0, rr=0, col=0;
            if (t < total){
                int i = 0;
                while (t >= s_tileBase[i+1]) i++;
                ss = i/NCMB; cc = i%NCMB;
                int off = t - s_tileBase[i];
                rr = off >> 3; col = off & 7;
                // dependency wait: all 8 col-tiles of (ss-1, cc, rr)
                int first = (cc==1) ? s_firstStepB[rr] : 0;
                int need = 8*(ss - first);
                if (need > 0){
                    while (atomicAdd(&s_dep[cc*32+rr], 0) < need) __nanosleep(64);
                }
                __threadfence();   // acquire: order dep-read before h reads
            }
            sh4[0]=ss; sh4[1]=cc; sh4[2]=rr; sh4[3]=col;
        }
        __syncthreads();
        int s = sh4[0];
        if (s < 0) break;
        int c = sh4[1], rowTile = sh4[2], colTile = sh4[3];
        __syncthreads();            // sh4 consumed before next overwrite

        int rdb = s & 1, wrb = rdb ^ 1;
        int lim = (c==1) ? s_cntF[15-s] : s_cntF[s];
        long brow = (long)rowTile << 7;
        long bcol = (long)colTile << 7;
        const __half* Ah = s_h16 + ((long)rdb*NCMB + c)*NT*DM;
        const __half* Bh = s_Whh5h + (long)c*GD*DM;
        int kx = (c==1) ? 15-s : s;
        const __half* Ax = s_xseq16 + (long)kx*NT*DM;
        const __half* Bx = s_Wih5h + (long)c*GD*DM;
        const float* biasb = s_b5 + c*GD;

        float4 acc[4][4];
        #pragma unroll
        for (int i=0;i<4;i++)
            #pragma unroll
            for (int j=0;j<4;j++) acc[i][j] = make_float4(0.f,0.f,0.f,0.f);

        // 16 K-chunks: 0-7 = h@Whh, 8-15 = xseq[kx]@Wih
        #define PRER(ch, buf) do {                                            \
            if ((ch) < 8) PRE16(Ah, Bh, DM, DM, brow, bcol, 0L,               \
                                (long)(ch)*32, buf);                          \
            else          PRE16(Ax, Bx, DM, DM, brow, bcol, 0L,               \
                                (long)((ch)-8)*32, buf);                      \
        } while(0)

        PRER(0, 0);
        PRER(1, 1);
        #pragma unroll
        for (int i = 0; i < 16; i++){
            if (i < 15) asm volatile("cp.async.wait_group 1;" ::: "memory");
            else        asm volatile("cp.async.wait_group 0;" ::: "memory");
            __syncthreads();
            MAINLOOP_CHUNK(i % 3);
            if (i + 2 < 16) PRER(i + 2, (i + 2) % 3);
        }
        #undef PRER
        __syncthreads();   // ring smem free before gs staging

        // stage gate preactivations (acc + bias) into smem fp16
        #pragma unroll
        for (int mt=0; mt<4; mt++){
            int lr0 = wrw*64 + mt*16 + gq;
            #pragma unroll
            for (int nt=0; nt<4; nt++){
                int lcol = wcw*32 + nt*8 + 2*tq;
                long col2 = bcol + lcol;
                float b0 = biasb[col2], b1 = biasb[col2+1];
                *reinterpret_cast<__half2*>(&gs[lr0*132 + lcol]) =
                    __floats2half2_rn(acc[mt][nt].x + b0, acc[mt][nt].y + b1);
                *reinterpret_cast<__half2*>(&gs[(lr0+8)*132 + lcol]) =
                    __floats2half2_rn(acc[mt][nt].z + b0, acc[mt][nt].w + b1);
            }
        }
        __syncthreads();

        // fused LSTM gates: 128 rows x 32 units, half2 over units
        #pragma unroll
        for (int it=0; it<8; it++){
            int idx2 = tid + it*256;
            int row = idx2 >> 4, up = idx2 & 15;
            int u = up*2;
            int n = (int)brow + row;
            if (n >= lim) continue;
            int d = (colTile<<5) + u;
            float2 gi = __half22float2(*reinterpret_cast<const __half2*>(&gs[row*132 + u]));
            float2 gf = __half22float2(*reinterpret_cast<const __half2*>(&gs[row*132 + 32 + u]));
            float2 gu = __half22float2(*reinterpret_cast<const __half2*>(&gs[row*132 + 64 + u]));
            float2 go = __half22float2(*reinterpret_cast<const __half2*>(&gs[row*132 + 96 + u]));
            long ist = ((long)c*NT + n)*DM + d;
            float2 cp = *reinterpret_cast<const float2*>(&s_c[ist]);
            float2 cn, hn;
            cn.x = sigf(gf.x)*cp.x + sigf(gi.x)*tanhf(gu.x);
            cn.y = sigf(gf.y)*cp.y + sigf(gi.y)*tanhf(gu.y);
            hn.x = sigf(go.x)*tanhf(cn.x);
            hn.y = sigf(go.y)*tanhf(cn.y);
            *reinterpret_cast<float2*>(&s_c[ist]) = cn;
            __half2 hn2 = __floats2half2_rn(hn.x, hn.y);
            *reinterpret_cast<__half2*>(&s_h16[((long)wrb*NCMB + c)*NT*DM + (long)n*DM + d]) = hn2;
            if (c == 0)
                *reinterpret_cast<__half2*>(&s_ycat016[((long)s*NT+n)*(2*DM) + d]) = hn2;
            else if (c == 1)
                *reinterpret_cast<__half2*>(&s_ycat016[((long)(15-s)*NT+n)*(2*DM) + DM + d]) = hn2;
            else if (s == s_len[n]-1)
                *reinterpret_cast<__half2*>(&s_ylcat16[((long)(c-2)*NT+n)*(2*DM) + d]) = hn2;
        }
        __threadfence();           // publish h/c writes (each thread fences own)
        __syncthreads();
        if (tid == 0) atomicAdd(&s_dep[c*32+rowTile], 1);
    }
}

// ---------------- one-step backward gates (j=1..3, original layout) ----------
__global__ void gates_last(const float* __restrict__ c0){
    long i = (long)blockIdx.x*blockDim.x + threadIdx.x;
    if (i >= 3L*NT*(DM/2)) return;
    int jb = (int)(i/((long)NT*(DM/2)));
    long nd = i%((long)NT*(DM/2));
    int n = (int)(nd/(DM/2)), d2 = (int)(nd%(DM/2));
    int d = d2*2;
    const __half2* g = (const __half2*)(s_gB16 + (long)jb*NT*GD + (long)n*GD);
    float2 gi = __half22float2(g[d2]);
    float2 gf = __half22float2(g[(DM>>1)+d2]);
    float2 gu = __half22float2(g[DM+d2]);
    float2 go = __half22float2(g[((3*DM)>>1)+d2]);
    float2 cp = *reinterpret_cast<const float2*>(&c0[(jb+1)*DM+d]);
    float2 hn;
    float cnx = sigf(gf.x)*cp.x + sigf(gi.x)*tanhf(gu.x);
    float cny = sigf(gf.y)*cp.y + sigf(gi.y)*tanhf(gu.y);
    hn.x = sigf(go.x)*tanhf(cnx);
    hn.y = sigf(go.y)*tanhf(cny);
    *reinterpret_cast<__half2*>(&s_ylcat16[((long)jb*NT+n)*(2*DM) + DM + d]) = __floats2half2_rn(hn.x, hn.y);
}

__global__ void final_k(float* __restrict__ out){
    int n = blockIdx.x, d = threadIdx.x;   // n = sorted slot
    int orig = s_ord[n];
    float wf = s_Wx[(long)n*GD + d];
    float wi = s_Wx[(long)n*GD + DM + d];
    float wu = s_Wx[(long)n*GD + 2*DM + d];
    float wo = s_Wx[(long)n*GD + 3*DM + d];
    int len = s_len[n];
    float bf = 0.f;
    for (int k=0;k<len;k++){
        float y  = __half2float(s_ys016[((long)k*NT+n)*DM + d]);
        float cc = s_cseq[((long)n*KC+k)*DM + d];
        bf += sigf(wf + y) * cc;
    }
    float bi = sigf (__half2float(s_ysl16[0L*NT*DM + (long)n*DM + d]) + wi);
    float bu = tanhf(__half2float(s_ysl16[1L*NT*DM + (long)n*DM + d]) + wu);
    float bo = sigf (__half2float(s_ysl16[2L*NT*DM + (long)n*DM + d]) + wo);
    float ncv = bi*bu + bf;
    float nhv = bo*tanhf(ncv);
    out[(long)orig*DM + d] = nhv;
    out[(long)NT*DM + (long)orig*DM + d] = ncv;
}

// =============================================================================
extern "C" void kernel_launch(void* const* d_in, const int* in_sizes, int n_in,
                              void* d_out, int out_size) {
    const float* x        = (const float*)d_in[0];
    const float* h_tensor = (const float*)d_in[1];
    const float* c_tensor = (const float*)d_in[2];
    const int*   indice   = (const int*)  d_in[3];
    const float* W_w      = (const float*)d_in[4];
    const float* W_b      = (const float*)d_in[5];
    const float* h0       = (const float*)d_in[6];
    const float* c0       = (const float*)d_in[7];
    const float* Wih      = (const float*)d_in[8];
    const float* Whh      = (const float*)d_in[9];
    const float* bih      = (const float*)d_in[10];
    const float* bhh      = (const float*)d_in[11];
    const float* fc       = (const float*)d_in[12];
    float* out = (float*)d_out;

    __half *p_x16,*p_xlast16,*p_WihBh,*p_Wwh,*p_fch,
           *p_ycat016,*p_ylcat16,*p_gB16,*p_ys016,*p_ysl16;
    float *p_hb,*p_Wx;
    int *p_cntF;
    cudaGetSymbolAddress((void**)&p_x16,     s_x16);
    cudaGetSymbolAddress((void**)&p_xlast16, s_xlast16);
    cudaGetSymbolAddress((void**)&p_WihBh,   s_WihBh);
    cudaGetSymbolAddress((void**)&p_Wwh,     s_Wwh);
    cudaGetSymbolAddress((void**)&p_fch,     s_fch);
    cudaGetSymbolAddress((void**)&p_ycat016, s_ycat016);
    cudaGetSymbolAddress((void**)&p_ylcat16, s_ylcat16);
    cudaGetSymbolAddress((void**)&p_gB16,    s_gB16);
    cudaGetSymbolAddress((void**)&p_ys016,   s_ys016);
    cudaGetSymbolAddress((void**)&p_ysl16,   s_ysl16);
    cudaGetSymbolAddress((void**)&p_hb,      s_hb);
    cudaGetSymbolAddress((void**)&p_Wx,      s_Wx);
    cudaGetSymbolAddress((void**)&p_cntF,    s_cntF);
    (void)in_sizes; (void)n_in; (void)out_size;

    cudaFuncSetAttribute(gemm_h, cudaFuncAttributeMaxDynamicSharedMemorySize, SMEM_SZ);
    cudaFuncSetAttribute(rec_k,  cudaFuncAttributeMaxDynamicSharedMemorySize, SMEM_SZ);

    // 1) sort + queue tables, pack/convert weights, init states, gather(+xlast)
    sort_k<<<1,256>>>(indice);
    prep_weights<<<1024,256>>>(Wih,Whh,bih,bhh,W_w,fc);
    init_k<<<2048,256>>>(x,h0,c0);
    gather_k<<<(int)(((long)NT*KC*(DM/4))/256),256>>>(h_tensor,c_tensor,indice);
    hb_k<<<12,256>>>(h0,Whh,bih,bhh);

    // 2) Wx = x @ W_w^T + W_b   (sorted rows, original cols) -> fp32
    gemm_h<<<dim3(GD/128, NT/128, 1),256,SMEM_SZ>>>(
        p_x16,0, p_Wwh,0, W_b,0,
        p_Wx,(__half*)0,0,GD, NT,GD,DM, -1,0, (const int*)0,0);

    // 3) the 16-step recurrence: work-queue persistent kernel
    rec_k<<<NCTA,256,SMEM_SZ>>>();

    // 4) backward one-step for j=1..3 -> fp16 (original layout)
    gemm_h<<<dim3(GD/128, NT/128, 3),256,SMEM_SZ>>>(
        p_xlast16,0, p_WihBh,(long)GD*DM, p_hb,(long)GD,
        (float*)0,p_gB16,(long)NT*GD,GD, NT,GD,DM, -1,0, (const int*)0,0);
    gates_last<<<(int)((3L*NT*(DM/2)+255)/256),256>>>(c0);

    // 5) fc projections -> fp16 (ycat0 k-major; skip k>=len)
    gemm_h<<<dim3(DM/128, (NT*KC)/128, 1),256,SMEM_SZ>>>(
        p_ycat016,0, p_fch,0, (const float*)0,0,
        (float*)0,p_ys016,0,DM, NT*KC,DM,2*DM, -1,0, p_cntF,1);
    gemm_h<<<dim3(DM/128, NT/128, 3),256,SMEM_SZ>>>(
        p_ylcat16,(long)NT*2*DM, p_fch + (long)DM*2*DM,(long)DM*2*DM,
        (const float*)0,0,
        (float*)0,p_ysl16,(long)NT*DM,DM, NT,DM,2*DM, -1,0, (const int*)0,0);

    // 6) final combine -> (new_h, new_c), un-permuted
    final_k<<<NT,DM>>>(out);
}